// round 1
// baseline (speedup 1.0000x reference)
#include <cuda_runtime.h>

#define LSEQ 2048
#define BATCH 2
#define NH 12
#define FEATD 16
#define HD 64
#define DM 768
#define QKD (NH * FEATD)   // 192
#define ROWS (BATCH * LSEQ) // 4096

// Scratch (no cudaMalloc allowed)
__device__ float g_Q[ROWS * QKD];
__device__ float g_K[ROWS * QKD];
__device__ float g_V[ROWS * DM];
__device__ float g_Y[ROWS * DM];

// ---------------------------------------------------------------------------
// C[M,N] = X[M,Kd] @ W[N,Kd]^T   (both row-major over Kd)
// 128x128 tile, BK=8, 256 threads, 8x8 per thread.
// ---------------------------------------------------------------------------
__global__ void __launch_bounds__(256) sgemm_xwt(
    const float* __restrict__ X, const float* __restrict__ W,
    float* __restrict__ C, int M, int N, int Kd)
{
    __shared__ float As[8][128];
    __shared__ float Bs[8][128];

    const int tid = threadIdx.x;
    const int m0 = blockIdx.y * 128;
    const int n0 = blockIdx.x * 128;
    const int tx = tid & 15;
    const int ty = tid >> 4;

    const int lrow = tid >> 1;          // 0..127
    const int lcol = (tid & 1) * 4;     // 0 or 4

    float acc[8][8];
#pragma unroll
    for (int i = 0; i < 8; i++)
#pragma unroll
        for (int j = 0; j < 8; j++) acc[i][j] = 0.f;

    for (int k0 = 0; k0 < Kd; k0 += 8) {
        float4 xa = make_float4(0.f, 0.f, 0.f, 0.f);
        float4 wb = make_float4(0.f, 0.f, 0.f, 0.f);
        if (m0 + lrow < M)
            xa = *(const float4*)&X[(size_t)(m0 + lrow) * Kd + k0 + lcol];
        if (n0 + lrow < N)
            wb = *(const float4*)&W[(size_t)(n0 + lrow) * Kd + k0 + lcol];

        __syncthreads();
        As[lcol + 0][lrow] = xa.x; As[lcol + 1][lrow] = xa.y;
        As[lcol + 2][lrow] = xa.z; As[lcol + 3][lrow] = xa.w;
        Bs[lcol + 0][lrow] = wb.x; Bs[lcol + 1][lrow] = wb.y;
        Bs[lcol + 2][lrow] = wb.z; Bs[lcol + 3][lrow] = wb.w;
        __syncthreads();

#pragma unroll
        for (int k = 0; k < 8; k++) {
            float a[8], b[8];
            *(float4*)&a[0] = *(const float4*)&As[k][ty * 8];
            *(float4*)&a[4] = *(const float4*)&As[k][ty * 8 + 4];
            *(float4*)&b[0] = *(const float4*)&Bs[k][tx * 8];
            *(float4*)&b[4] = *(const float4*)&Bs[k][tx * 8 + 4];
#pragma unroll
            for (int i = 0; i < 8; i++)
#pragma unroll
                for (int j = 0; j < 8; j++)
                    acc[i][j] += a[i] * b[j];
        }
    }

#pragma unroll
    for (int i = 0; i < 8; i++) {
        int m = m0 + ty * 8 + i;
        if (m >= M) continue;
#pragma unroll
        for (int j = 0; j < 8; j += 4) {
            int n = n0 + tx * 8 + j;
            if (n + 3 < N) {
                *(float4*)&C[(size_t)m * N + n] =
                    make_float4(acc[i][j], acc[i][j + 1], acc[i][j + 2], acc[i][j + 3]);
            } else {
#pragma unroll
                for (int jj = 0; jj < 4; jj++)
                    if (n + jj < N) C[(size_t)m * N + n + jj] = acc[i][j + jj];
            }
        }
    }
}

// ---------------------------------------------------------------------------
// Attention: per (b,h): s = q.k (16-dim), A = 1 + s/4 + s^2/32,
// weight 2 for m<=n else 1; Y = (Aw @ V) / rowsum(Aw).
// 1 query per thread, 128 queries per block, K/V tiles of 64 keys in smem.
// All lanes in a warp read the same key row -> pure broadcast (conflict-free).
// ---------------------------------------------------------------------------
__global__ void __launch_bounds__(128) attn_kernel(
    const float* __restrict__ Q, const float* __restrict__ K,
    const float* __restrict__ V, float* __restrict__ Y)
{
    const int tid = threadIdx.x;
    const int n = blockIdx.x * 128 + tid;   // query index
    const int h = blockIdx.y;
    const int b = blockIdx.z;

    __shared__ float Ks[64][16];
    __shared__ float Vs[64][64];

    const float* Qp = Q + (size_t)(b * LSEQ) * QKD + h * FEATD;
    const float* Kp = K + (size_t)(b * LSEQ) * QKD + h * FEATD;
    const float* Vp = V + (size_t)(b * LSEQ) * DM + h * HD;

    float q[16];
    {
        const float4* qv = (const float4*)&Qp[(size_t)n * QKD];
#pragma unroll
        for (int i = 0; i < 4; i++) {
            float4 t = qv[i];
            q[4 * i + 0] = t.x; q[4 * i + 1] = t.y;
            q[4 * i + 2] = t.z; q[4 * i + 3] = t.w;
        }
    }

    float acc[64];
#pragma unroll
    for (int e = 0; e < 64; e++) acc[e] = 0.f;
    float zacc = 0.f;

    for (int m0 = 0; m0 < LSEQ; m0 += 64) {
        __syncthreads();
        // Load K tile: 64 x 16 floats = 256 float4s
#pragma unroll
        for (int idx = tid; idx < 256; idx += 128) {
            int r = idx >> 2, c = (idx & 3) << 2;
            *(float4*)&Ks[r][c] = *(const float4*)&Kp[(size_t)(m0 + r) * QKD + c];
        }
        // Load V tile: 64 x 64 floats = 1024 float4s
#pragma unroll
        for (int idx = tid; idx < 1024; idx += 128) {
            int r = idx >> 4, c = (idx & 15) << 2;
            *(float4*)&Vs[r][c] = *(const float4*)&Vp[(size_t)(m0 + r) * DM + c];
        }
        __syncthreads();

        const int mlim = n - m0;   // keys with local idx <= mlim get weight 2
#pragma unroll 2
        for (int m = 0; m < 64; m++) {
            float4 ka = *(const float4*)&Ks[m][0];
            float4 kb = *(const float4*)&Ks[m][4];
            float4 kc = *(const float4*)&Ks[m][8];
            float4 kd = *(const float4*)&Ks[m][12];
            float s = q[0] * ka.x + q[1] * ka.y + q[2] * ka.z + q[3] * ka.w
                    + q[4] * kb.x + q[5] * kb.y + q[6] * kb.z + q[7] * kb.w
                    + q[8] * kc.x + q[9] * kc.y + q[10] * kc.z + q[11] * kc.w
                    + q[12] * kd.x + q[13] * kd.y + q[14] * kd.z + q[15] * kd.w;
            float a = 1.f + 0.25f * s + 0.03125f * s * s;
            if (m <= mlim) a += a;   // causal weight 2
            zacc += a;
            const float4* vr = (const float4*)&Vs[m][0];
#pragma unroll
            for (int e4 = 0; e4 < 16; e4++) {
                float4 v = vr[e4];
                acc[4 * e4 + 0] += a * v.x;
                acc[4 * e4 + 1] += a * v.y;
                acc[4 * e4 + 2] += a * v.z;
                acc[4 * e4 + 3] += a * v.w;
            }
        }
    }

    const float inv = 1.f / zacc;
    float* yp = Y + (size_t)(b * LSEQ + n) * DM + h * HD;
#pragma unroll
    for (int e4 = 0; e4 < 16; e4++) {
        *(float4*)&yp[4 * e4] = make_float4(acc[4 * e4 + 0] * inv,
                                            acc[4 * e4 + 1] * inv,
                                            acc[4 * e4 + 2] * inv,
                                            acc[4 * e4 + 3] * inv);
    }
}

// ---------------------------------------------------------------------------
extern "C" void kernel_launch(void* const* d_in, const int* in_sizes, int n_in,
                              void* d_out, int out_size)
{
    const float* hs = (const float*)d_in[0];
    const float* Wq = (const float*)d_in[1];
    const float* Wk = (const float*)d_in[2];
    const float* Wv = (const float*)d_in[3];
    const float* Wo = (const float*)d_in[4];
    float* out = (float*)d_out;

    float *Q, *K, *V, *Y;
    cudaGetSymbolAddress((void**)&Q, g_Q);
    cudaGetSymbolAddress((void**)&K, g_K);
    cudaGetSymbolAddress((void**)&V, g_V);
    cudaGetSymbolAddress((void**)&Y, g_Y);

    // Projections: y = x @ W^T
    {
        dim3 gq((QKD + 127) / 128, ROWS / 128);
        sgemm_xwt<<<gq, 256>>>(hs, Wq, Q, ROWS, QKD, DM);
        sgemm_xwt<<<gq, 256>>>(hs, Wk, K, ROWS, QKD, DM);
        dim3 gv(DM / 128, ROWS / 128);
        sgemm_xwt<<<gv, 256>>>(hs, Wv, V, ROWS, DM, DM);
    }

    // Attention
    {
        dim3 ga(LSEQ / 128, NH, BATCH);
        attn_kernel<<<ga, 128>>>(Q, K, V, Y);
    }

    // Output projection
    {
        dim3 go(DM / 128, ROWS / 128);
        sgemm_xwt<<<go, 256>>>(Y, Wo, out, ROWS, DM, DM);
    }
}

// round 2
// speedup vs baseline: 1.0654x; 1.0654x over previous
#include <cuda_runtime.h>

#define LSEQ 2048
#define BATCH 2
#define NH 12
#define FEATD 16
#define HD 64
#define DM 768
#define QKD (NH * FEATD)    // 192
#define ROWS (BATCH * LSEQ) // 4096

// Scratch (no cudaMalloc allowed)
__device__ float g_Q[ROWS * QKD];
__device__ float g_K[ROWS * QKD];
__device__ float g_V[ROWS * DM];
__device__ float g_Y[ROWS * DM];

typedef unsigned long long ull;

// ---- packed f32x2 helpers (SASS FFMA2 — ptxas never emits from C++) ----
__device__ __forceinline__ ull pack2(float x, float y) {
    ull r; asm("mov.b64 %0, {%1, %2};" : "=l"(r) : "f"(x), "f"(y)); return r;
}
__device__ __forceinline__ void unpack2(ull v, float& x, float& y) {
    asm("mov.b64 {%0, %1}, %2;" : "=f"(x), "=f"(y) : "l"(v));
}
__device__ __forceinline__ ull ffma2(ull a, ull b, ull c) {
    ull d; asm("fma.rn.f32x2 %0, %1, %2, %3;" : "=l"(d) : "l"(a), "l"(b), "l"(c)); return d;
}
__device__ __forceinline__ ull fadd2(ull a, ull b) {
    ull d; asm("add.rn.f32x2 %0, %1, %2;" : "=l"(d) : "l"(a), "l"(b)); return d;
}

// ---------------------------------------------------------------------------
// C[M,N] = X[M,Kd] @ W[N,Kd]^T   (both row-major over Kd)
// 128x128 tile, BK=8, 256 threads, 8x8 per thread, f32x2 inner product.
// ---------------------------------------------------------------------------
__global__ void __launch_bounds__(256) sgemm_xwt(
    const float* __restrict__ X, const float* __restrict__ W,
    float* __restrict__ C, int M, int N, int Kd)
{
    __shared__ float As[8][128];
    __shared__ float Bs[8][128];

    const int tid = threadIdx.x;
    const int m0 = blockIdx.y * 128;
    const int n0 = blockIdx.x * 128;
    const int tx = tid & 15;
    const int ty = tid >> 4;

    const int lrow = tid >> 1;          // 0..127
    const int lcol = (tid & 1) * 4;     // 0 or 4

    ull acc2[8][4];
    const ull Z = pack2(0.f, 0.f);
#pragma unroll
    for (int i = 0; i < 8; i++)
#pragma unroll
        for (int j = 0; j < 4; j++) acc2[i][j] = Z;

    for (int k0 = 0; k0 < Kd; k0 += 8) {
        float4 xa = make_float4(0.f, 0.f, 0.f, 0.f);
        float4 wb = make_float4(0.f, 0.f, 0.f, 0.f);
        if (m0 + lrow < M)
            xa = *(const float4*)&X[(size_t)(m0 + lrow) * Kd + k0 + lcol];
        if (n0 + lrow < N)
            wb = *(const float4*)&W[(size_t)(n0 + lrow) * Kd + k0 + lcol];

        __syncthreads();
        As[lcol + 0][lrow] = xa.x; As[lcol + 1][lrow] = xa.y;
        As[lcol + 2][lrow] = xa.z; As[lcol + 3][lrow] = xa.w;
        Bs[lcol + 0][lrow] = wb.x; Bs[lcol + 1][lrow] = wb.y;
        Bs[lcol + 2][lrow] = wb.z; Bs[lcol + 3][lrow] = wb.w;
        __syncthreads();

#pragma unroll
        for (int k = 0; k < 8; k++) {
            float a[8];
            *(float4*)&a[0] = *(const float4*)&As[k][ty * 8];
            *(float4*)&a[4] = *(const float4*)&As[k][ty * 8 + 4];
            ulonglong2 b01 = *(const ulonglong2*)&Bs[k][tx * 8];
            ulonglong2 b23 = *(const ulonglong2*)&Bs[k][tx * 8 + 4];
            ull b2[4] = { b01.x, b01.y, b23.x, b23.y };
#pragma unroll
            for (int i = 0; i < 8; i++) {
                ull aa = pack2(a[i], a[i]);
#pragma unroll
                for (int j = 0; j < 4; j++)
                    acc2[i][j] = ffma2(aa, b2[j], acc2[i][j]);
            }
        }
    }

#pragma unroll
    for (int i = 0; i < 8; i++) {
        int m = m0 + ty * 8 + i;
        if (m >= M) continue;
        float o[8];
#pragma unroll
        for (int j = 0; j < 4; j++) unpack2(acc2[i][j], o[2 * j], o[2 * j + 1]);
#pragma unroll
        for (int j = 0; j < 8; j += 4) {
            int n = n0 + tx * 8 + j;
            if (n + 3 < N) {
                *(float4*)&C[(size_t)m * N + n] =
                    make_float4(o[j], o[j + 1], o[j + 2], o[j + 3]);
            } else {
#pragma unroll
                for (int jj = 0; jj < 4; jj++)
                    if (n + jj < N) C[(size_t)m * N + n + jj] = o[j + jj];
            }
        }
    }
}

// ---------------------------------------------------------------------------
// Attention: per (b,h): s = q.k (16-dim), A = 1 + s/4 + s^2/32,
// weight 2 for m<=n else 1; Y = (Aw @ V) / rowsum(Aw).
// 1 query/thread, 128 queries/block, K/V tiles in smem, f32x2 math.
// ---------------------------------------------------------------------------
__global__ void __launch_bounds__(128, 4) attn_kernel(
    const float* __restrict__ Q, const float* __restrict__ K,
    const float* __restrict__ V, float* __restrict__ Y)
{
    const int tid = threadIdx.x;
    const int n = blockIdx.x * 128 + tid;   // query index
    const int h = blockIdx.y;
    const int b = blockIdx.z;

    __shared__ float Ks[64][16];
    __shared__ float Vs[64][64];

    const float* Qp = Q + (size_t)(b * LSEQ) * QKD + h * FEATD;
    const float* Kp = K + (size_t)(b * LSEQ) * QKD + h * FEATD;
    const float* Vp = V + (size_t)(b * LSEQ) * DM + h * HD;

    // q packed into 8 f32x2 lanes
    ull q2[8];
    {
        const float4* qv = (const float4*)&Qp[(size_t)n * QKD];
#pragma unroll
        for (int i = 0; i < 4; i++) {
            float4 t = qv[i];
            q2[2 * i + 0] = pack2(t.x, t.y);
            q2[2 * i + 1] = pack2(t.z, t.w);
        }
    }

    const ull Z = pack2(0.f, 0.f);
    ull acc2[32];
#pragma unroll
    for (int e = 0; e < 32; e++) acc2[e] = Z;
    float zacc = 0.f;

    for (int m0 = 0; m0 < LSEQ; m0 += 64) {
        __syncthreads();
        // Load K tile: 64 x 16 floats = 256 float4s
#pragma unroll
        for (int idx = tid; idx < 256; idx += 128) {
            int r = idx >> 2, c = (idx & 3) << 2;
            *(float4*)&Ks[r][c] = *(const float4*)&Kp[(size_t)(m0 + r) * QKD + c];
        }
        // Load V tile: 64 x 64 floats = 1024 float4s
#pragma unroll
        for (int idx = tid; idx < 1024; idx += 128) {
            int r = idx >> 4, c = (idx & 15) << 2;
            *(float4*)&Vs[r][c] = *(const float4*)&Vp[(size_t)(m0 + r) * DM + c];
        }
        __syncthreads();

        const int mlim = n - m0;   // keys with local idx <= mlim get weight 2
#pragma unroll 2
        for (int m = 0; m < 64; m++) {
            // 16-dim dot product: two independent f32x2 chains
            const ulonglong2* kr = (const ulonglong2*)&Ks[m][0];
            ulonglong2 ka = kr[0], kb = kr[1], kc = kr[2], kd = kr[3];
            ull sA = ffma2(q2[0], ka.x, Z);
            ull sB = ffma2(q2[1], ka.y, Z);
            sA = ffma2(q2[2], kb.x, sA);
            sB = ffma2(q2[3], kb.y, sB);
            sA = ffma2(q2[4], kc.x, sA);
            sB = ffma2(q2[5], kc.y, sB);
            sA = ffma2(q2[6], kd.x, sA);
            sB = ffma2(q2[7], kd.y, sB);
            ull sAB = fadd2(sA, sB);
            float sx, sy; unpack2(sAB, sx, sy);
            float s = sx + sy;

            float t = fmaf(s, 0.03125f, 0.25f);
            float a = fmaf(s, t, 1.0f);
            if (m <= mlim) a += a;    // causal weight 2
            zacc += a;
            ull aa = pack2(a, a);

            const ulonglong2* vr = (const ulonglong2*)&Vs[m][0];
#pragma unroll
            for (int e4 = 0; e4 < 16; e4++) {
                ulonglong2 v = vr[e4];
                acc2[2 * e4 + 0] = ffma2(aa, v.x, acc2[2 * e4 + 0]);
                acc2[2 * e4 + 1] = ffma2(aa, v.y, acc2[2 * e4 + 1]);
            }
        }
    }

    const float inv = 1.f / zacc;
    float* yp = Y + (size_t)(b * LSEQ + n) * DM + h * HD;
#pragma unroll
    for (int e4 = 0; e4 < 16; e4++) {
        float a0, a1, a2, a3;
        unpack2(acc2[2 * e4 + 0], a0, a1);
        unpack2(acc2[2 * e4 + 1], a2, a3);
        *(float4*)&yp[4 * e4] = make_float4(a0 * inv, a1 * inv, a2 * inv, a3 * inv);
    }
}

// ---------------------------------------------------------------------------
extern "C" void kernel_launch(void* const* d_in, const int* in_sizes, int n_in,
                              void* d_out, int out_size)
{
    const float* hs = (const float*)d_in[0];
    const float* Wq = (const float*)d_in[1];
    const float* Wk = (const float*)d_in[2];
    const float* Wv = (const float*)d_in[3];
    const float* Wo = (const float*)d_in[4];
    float* out = (float*)d_out;

    float *Q, *K, *V, *Y;
    cudaGetSymbolAddress((void**)&Q, g_Q);
    cudaGetSymbolAddress((void**)&K, g_K);
    cudaGetSymbolAddress((void**)&V, g_V);
    cudaGetSymbolAddress((void**)&Y, g_Y);

    // Projections: y = x @ W^T
    {
        dim3 gq((QKD + 127) / 128, ROWS / 128);
        sgemm_xwt<<<gq, 256>>>(hs, Wq, Q, ROWS, QKD, DM);
        sgemm_xwt<<<gq, 256>>>(hs, Wk, K, ROWS, QKD, DM);
        dim3 gv(DM / 128, ROWS / 128);
        sgemm_xwt<<<gv, 256>>>(hs, Wv, V, ROWS, DM, DM);
    }

    // Attention
    {
        dim3 ga(LSEQ / 128, NH, BATCH);
        attn_kernel<<<ga, 128>>>(Q, K, V, Y);
    }

    // Output projection
    {
        dim3 go(DM / 128, ROWS / 128);
        sgemm_xwt<<<go, 256>>>(Y, Wo, out, ROWS, DM, DM);
    }
}

// round 3
// speedup vs baseline: 1.1958x; 1.1224x over previous
#include <cuda_runtime.h>

#define LSEQ 2048
#define BATCH 2
#define NH 12
#define FEATD 16
#define HD 64
#define DM 768
#define QKD (NH * FEATD)    // 192
#define ROWS (BATCH * LSEQ) // 4096
#define KT 32               // key tile in attention

// Scratch (no cudaMalloc allowed)
__device__ float g_Q[ROWS * QKD];
__device__ float g_K[ROWS * QKD];
__device__ float g_V[ROWS * DM];
__device__ float g_Y[ROWS * DM];

typedef unsigned long long ull;

// ---- packed f32x2 helpers (SASS FFMA2 — ptxas never emits from C++) ----
__device__ __forceinline__ ull pack2(float x, float y) {
    ull r; asm("mov.b64 %0, {%1, %2};" : "=l"(r) : "f"(x), "f"(y)); return r;
}
__device__ __forceinline__ void unpack2(ull v, float& x, float& y) {
    asm("mov.b64 {%0, %1}, %2;" : "=f"(x), "=f"(y) : "l"(v));
}
__device__ __forceinline__ ull ffma2(ull a, ull b, ull c) {
    ull d; asm("fma.rn.f32x2 %0, %1, %2, %3;" : "=l"(d) : "l"(a), "l"(b), "l"(c)); return d;
}
__device__ __forceinline__ ull fadd2(ull a, ull b) {
    ull d; asm("add.rn.f32x2 %0, %1, %2;" : "=l"(d) : "l"(a), "l"(b)); return d;
}

// ---------------------------------------------------------------------------
// C[M,N] = X[M,Kd] @ W[N,Kd]^T. 128x128 tile, BK=16, 256 threads, 8x8/thread.
// ---------------------------------------------------------------------------
__global__ void __launch_bounds__(256, 2) sgemm_xwt(
    const float* __restrict__ X, const float* __restrict__ W,
    float* __restrict__ C, int M, int N, int Kd)
{
    __shared__ float As[16][132];
    __shared__ float Bs[16][132];

    const int tid = threadIdx.x;
    const int m0 = blockIdx.y * 128;
    const int n0 = blockIdx.x * 128;
    const int tx = tid & 15;
    const int ty = tid >> 4;

    const int lrow = tid >> 1;          // 0..127
    const int lc = (tid & 1) * 8;       // 0 or 8

    ull acc2[8][4];
    const ull Z = pack2(0.f, 0.f);
#pragma unroll
    for (int i = 0; i < 8; i++)
#pragma unroll
        for (int j = 0; j < 4; j++) acc2[i][j] = Z;

    for (int k0 = 0; k0 < Kd; k0 += 16) {
        float4 xa0 = make_float4(0.f, 0.f, 0.f, 0.f), xa1 = xa0;
        float4 wb0 = xa0, wb1 = xa0;
        if (m0 + lrow < M) {
            xa0 = *(const float4*)&X[(size_t)(m0 + lrow) * Kd + k0 + lc];
            xa1 = *(const float4*)&X[(size_t)(m0 + lrow) * Kd + k0 + lc + 4];
        }
        if (n0 + lrow < N) {
            wb0 = *(const float4*)&W[(size_t)(n0 + lrow) * Kd + k0 + lc];
            wb1 = *(const float4*)&W[(size_t)(n0 + lrow) * Kd + k0 + lc + 4];
        }

        __syncthreads();
        As[lc + 0][lrow] = xa0.x; As[lc + 1][lrow] = xa0.y;
        As[lc + 2][lrow] = xa0.z; As[lc + 3][lrow] = xa0.w;
        As[lc + 4][lrow] = xa1.x; As[lc + 5][lrow] = xa1.y;
        As[lc + 6][lrow] = xa1.z; As[lc + 7][lrow] = xa1.w;
        Bs[lc + 0][lrow] = wb0.x; Bs[lc + 1][lrow] = wb0.y;
        Bs[lc + 2][lrow] = wb0.z; Bs[lc + 3][lrow] = wb0.w;
        Bs[lc + 4][lrow] = wb1.x; Bs[lc + 5][lrow] = wb1.y;
        Bs[lc + 6][lrow] = wb1.z; Bs[lc + 7][lrow] = wb1.w;
        __syncthreads();

#pragma unroll
        for (int k = 0; k < 16; k++) {
            float a[8];
            *(float4*)&a[0] = *(const float4*)&As[k][ty * 8];
            *(float4*)&a[4] = *(const float4*)&As[k][ty * 8 + 4];
            ulonglong2 b01 = *(const ulonglong2*)&Bs[k][tx * 8];
            ulonglong2 b23 = *(const ulonglong2*)&Bs[k][tx * 8 + 4];
            ull b2[4] = { b01.x, b01.y, b23.x, b23.y };
#pragma unroll
            for (int i = 0; i < 8; i++) {
                ull aa = pack2(a[i], a[i]);
#pragma unroll
                for (int j = 0; j < 4; j++)
                    acc2[i][j] = ffma2(aa, b2[j], acc2[i][j]);
            }
        }
    }

#pragma unroll
    for (int i = 0; i < 8; i++) {
        int m = m0 + ty * 8 + i;
        if (m >= M) continue;
        float o[8];
#pragma unroll
        for (int j = 0; j < 4; j++) unpack2(acc2[i][j], o[2 * j], o[2 * j + 1]);
#pragma unroll
        for (int j = 0; j < 8; j += 4) {
            int n = n0 + tx * 8 + j;
            if (n + 3 < N) {
                *(float4*)&C[(size_t)m * N + n] =
                    make_float4(o[j], o[j + 1], o[j + 2], o[j + 3]);
            } else {
#pragma unroll
                for (int jj = 0; jj < 4; jj++)
                    if (n + jj < N) C[(size_t)m * N + n + jj] = o[j + jj];
            }
        }
    }
}

// ---------------------------------------------------------------------------
// Attention, GEMM-tiled:
// Per CTA: 128 queries of one (b,h). Key tiles of KT=32.
// P1: S = Q K^T (Kdim=16), A = (1 + s/4 + s^2/32) * (2 if m<=n else 1),
//     stored transposed AsT[k][q].
// P2: Y += A @ V (outer-product tiled, 8 rows x 4 cols per thread),
//     z rides along as sum_k of the A operand.
// ---------------------------------------------------------------------------
__global__ void __launch_bounds__(256, 3) attn_kernel(
    const float* __restrict__ Q, const float* __restrict__ K,
    const float* __restrict__ V, float* __restrict__ Y)
{
    __shared__ float QsT[16][132];   // [d][q]
    __shared__ float KsT[16][36];    // [d][k]
    __shared__ float Vs[KT][68];     // [k][e]
    __shared__ float AsT[KT][132];   // [k][q]

    const int tid = threadIdx.x;
    const int tx = tid & 15;        // 0..15
    const int ty = tid >> 4;        // 0..15
    const int r0 = ty * 8;          // query rows r0..r0+7 (local)
    const int c0 = tx * 2;          // P1 key cols (local)
    const int c2 = tx * 4;          // P2 value cols
    const int qb0 = blockIdx.x * 128;
    const int h = blockIdx.y;
    const int b = blockIdx.z;

    const float* Qp = Q + (size_t)(b * LSEQ + qb0) * QKD + h * FEATD;
    const float* Kp = K + (size_t)(b * LSEQ) * QKD + h * FEATD;
    const float* Vp = V + (size_t)(b * LSEQ) * DM + h * HD;

    // Load Q tile transposed: 128 rows x 16 dims
    {
        int r = tid >> 1;
        int c4 = (tid & 1) * 8;
        float4 t0 = *(const float4*)&Qp[(size_t)r * QKD + c4];
        float4 t1 = *(const float4*)&Qp[(size_t)r * QKD + c4 + 4];
        QsT[c4 + 0][r] = t0.x; QsT[c4 + 1][r] = t0.y;
        QsT[c4 + 2][r] = t0.z; QsT[c4 + 3][r] = t0.w;
        QsT[c4 + 4][r] = t1.x; QsT[c4 + 5][r] = t1.y;
        QsT[c4 + 6][r] = t1.z; QsT[c4 + 7][r] = t1.w;
    }

    const ull Z = pack2(0.f, 0.f);
    ull acc[4][4];                  // [rowpair][col] lanes = rows {2i2, 2i2+1}
    ull zacc[4];
#pragma unroll
    for (int i = 0; i < 4; i++) {
        zacc[i] = Z;
#pragma unroll
        for (int j = 0; j < 4; j++) acc[i][j] = Z;
    }

    for (int m0 = 0; m0 < LSEQ; m0 += KT) {
        __syncthreads();
        // Load K tile transposed: KT keys x 16 dims
        if (tid < 128) {
            int kk = tid >> 2;
            int c4 = (tid & 3) * 4;
            float4 t = *(const float4*)&Kp[(size_t)(m0 + kk) * QKD + c4];
            KsT[c4 + 0][kk] = t.x; KsT[c4 + 1][kk] = t.y;
            KsT[c4 + 2][kk] = t.z; KsT[c4 + 3][kk] = t.w;
        }
        // Load V tile: KT x 64
        {
            int r = tid >> 3;
            int c = (tid & 7) * 8;
            *(float4*)&Vs[r][c]     = *(const float4*)&Vp[(size_t)(m0 + r) * DM + c];
            *(float4*)&Vs[r][c + 4] = *(const float4*)&Vp[(size_t)(m0 + r) * DM + c + 4];
        }
        __syncthreads();

        // ---- P1: scores for 8 rows x 2 cols per thread ----
        ull s2[4][2];
#pragma unroll
        for (int i = 0; i < 4; i++) { s2[i][0] = Z; s2[i][1] = Z; }
#pragma unroll
        for (int d = 0; d < 16; d++) {
            ulonglong2 qa = *(const ulonglong2*)&QsT[d][r0];
            ulonglong2 qb = *(const ulonglong2*)&QsT[d][r0 + 4];
            float k0v = KsT[d][c0], k1v = KsT[d][c0 + 1];
            ull kk0 = pack2(k0v, k0v), kk1 = pack2(k1v, k1v);
            s2[0][0] = ffma2(qa.x, kk0, s2[0][0]); s2[0][1] = ffma2(qa.x, kk1, s2[0][1]);
            s2[1][0] = ffma2(qa.y, kk0, s2[1][0]); s2[1][1] = ffma2(qa.y, kk1, s2[1][1]);
            s2[2][0] = ffma2(qb.x, kk0, s2[2][0]); s2[2][1] = ffma2(qb.x, kk1, s2[2][1]);
            s2[3][0] = ffma2(qb.y, kk0, s2[3][0]); s2[3][1] = ffma2(qb.y, kk1, s2[3][1]);
        }
        // poly + causal weight + store transposed
#pragma unroll
        for (int i2 = 0; i2 < 4; i2++) {
            int n0r = qb0 + r0 + 2 * i2;   // global query idx of lane .lo
#pragma unroll
            for (int j = 0; j < 2; j++) {
                float sa, sb; unpack2(s2[i2][j], sa, sb);
                int m = m0 + c0 + j;
                float a0 = fmaf(sa, fmaf(sa, 0.03125f, 0.25f), 1.0f);
                float a1 = fmaf(sb, fmaf(sb, 0.03125f, 0.25f), 1.0f);
                if (m <= n0r)     a0 += a0;
                if (m <= n0r + 1) a1 += a1;
                *(ull*)&AsT[c0 + j][r0 + 2 * i2] = pack2(a0, a1);
            }
        }
        __syncthreads();

        // ---- P2: Y += A @ V, z += rowsum(A) ----
#pragma unroll 8
        for (int k = 0; k < KT; k++) {
            ulonglong2 a01 = *(const ulonglong2*)&AsT[k][r0];
            ulonglong2 a23 = *(const ulonglong2*)&AsT[k][r0 + 4];
            ull arp[4] = { a01.x, a01.y, a23.x, a23.y };
            float4 v = *(const float4*)&Vs[k][c2];
            ull v0 = pack2(v.x, v.x), v1 = pack2(v.y, v.y);
            ull v2 = pack2(v.z, v.z), v3 = pack2(v.w, v.w);
#pragma unroll
            for (int i2 = 0; i2 < 4; i2++) {
                acc[i2][0] = ffma2(arp[i2], v0, acc[i2][0]);
                acc[i2][1] = ffma2(arp[i2], v1, acc[i2][1]);
                acc[i2][2] = ffma2(arp[i2], v2, acc[i2][2]);
                acc[i2][3] = ffma2(arp[i2], v3, acc[i2][3]);
                zacc[i2]   = fadd2(arp[i2], zacc[i2]);
            }
        }
    }

    // Finalize: scale by 1/z and store
#pragma unroll
    for (int i2 = 0; i2 < 4; i2++) {
        float z0, z1; unpack2(zacc[i2], z0, z1);
        float inv0 = 1.f / z0, inv1 = 1.f / z1;
        float y0[4], y1[4];
#pragma unroll
        for (int j = 0; j < 4; j++) {
            float lo, hi; unpack2(acc[i2][j], lo, hi);
            y0[j] = lo * inv0;
            y1[j] = hi * inv1;
        }
        size_t row0 = (size_t)(b * LSEQ + qb0 + r0 + 2 * i2) * DM + h * HD + c2;
        *(float4*)&Y[row0]      = make_float4(y0[0], y0[1], y0[2], y0[3]);
        *(float4*)&Y[row0 + DM] = make_float4(y1[0], y1[1], y1[2], y1[3]);
    }
}

// ---------------------------------------------------------------------------
extern "C" void kernel_launch(void* const* d_in, const int* in_sizes, int n_in,
                              void* d_out, int out_size)
{
    const float* hs = (const float*)d_in[0];
    const float* Wq = (const float*)d_in[1];
    const float* Wk = (const float*)d_in[2];
    const float* Wv = (const float*)d_in[3];
    const float* Wo = (const float*)d_in[4];
    float* out = (float*)d_out;

    float *Q, *K, *V, *Y;
    cudaGetSymbolAddress((void**)&Q, g_Q);
    cudaGetSymbolAddress((void**)&K, g_K);
    cudaGetSymbolAddress((void**)&V, g_V);
    cudaGetSymbolAddress((void**)&Y, g_Y);

    // Projections: y = x @ W^T
    {
        dim3 gq((QKD + 127) / 128, ROWS / 128);
        sgemm_xwt<<<gq, 256>>>(hs, Wq, Q, ROWS, QKD, DM);
        sgemm_xwt<<<gq, 256>>>(hs, Wk, K, ROWS, QKD, DM);
        dim3 gv(DM / 128, ROWS / 128);
        sgemm_xwt<<<gv, 256>>>(hs, Wv, V, ROWS, DM, DM);
    }

    // Attention
    {
        dim3 ga(LSEQ / 128, NH, BATCH);
        attn_kernel<<<ga, 256>>>(Q, K, V, Y);
    }

    // Output projection
    {
        dim3 go(DM / 128, ROWS / 128);
        sgemm_xwt<<<go, 256>>>(Y, Wo, out, ROWS, DM, DM);
    }
}

// round 5
// speedup vs baseline: 1.8870x; 1.5781x over previous
#include <cuda_runtime.h>
#include <cuda_bf16.h>
#include <cstdint>

#define LSEQ 2048
#define BATCH 2
#define NH 12
#define FEATD 16
#define HD 64
#define DM 768
#define QKS 384             // combined Q|K projection width
#define ROWS (BATCH * LSEQ) // 4096
#define KT 32               // key tile in attention

// Scratch (no cudaMalloc allowed)
__device__ float g_QK[ROWS * QKS];
__device__ float g_V[ROWS * DM];
__device__ float g_Y[ROWS * DM];
__device__ __nv_bfloat16 g_Xh[ROWS * DM];
__device__ __nv_bfloat16 g_Xl[ROWS * DM];
__device__ __nv_bfloat16 g_Wh[DM * DM];
__device__ __nv_bfloat16 g_Wl[DM * DM];

typedef unsigned long long ull;

// ---- packed f32x2 helpers ----
__device__ __forceinline__ ull pack2(float x, float y) {
    ull r; asm("mov.b64 %0, {%1, %2};" : "=l"(r) : "f"(x), "f"(y)); return r;
}
__device__ __forceinline__ void unpack2(ull v, float& x, float& y) {
    asm("mov.b64 {%0, %1}, %2;" : "=f"(x), "=f"(y) : "l"(v));
}
__device__ __forceinline__ ull ffma2(ull a, ull b, ull c) {
    ull d; asm("fma.rn.f32x2 %0, %1, %2, %3;" : "=l"(d) : "l"(a), "l"(b), "l"(c)); return d;
}
__device__ __forceinline__ ull fadd2(ull a, ull b) {
    ull d; asm("add.rn.f32x2 %0, %1, %2;" : "=l"(d) : "l"(a), "l"(b)); return d;
}

// ---- HMMA helpers ----
__device__ __forceinline__ uint32_t smem_u32(const void* p) {
    uint32_t a;
    asm("{ .reg .u64 t; cvta.to.shared.u64 t, %1; cvt.u32.u64 %0, t; }" : "=r"(a) : "l"(p));
    return a;
}
__device__ __forceinline__ uint32_t sw128(uint32_t o) { return o ^ ((o >> 3) & 0x70); }
__device__ __forceinline__ void ldsm_x4(uint32_t* r, uint32_t addr) {
    asm volatile("ldmatrix.sync.aligned.m8n8.x4.shared.b16 {%0,%1,%2,%3}, [%4];"
                 : "=r"(r[0]), "=r"(r[1]), "=r"(r[2]), "=r"(r[3]) : "r"(addr));
}
__device__ __forceinline__ void mma_bf16(float* d, const uint32_t* a, uint32_t b0, uint32_t b1) {
    asm volatile(
        "mma.sync.aligned.m16n8k16.row.col.f32.bf16.bf16.f32 "
        "{%0,%1,%2,%3}, {%4,%5,%6,%7}, {%8,%9}, {%0,%1,%2,%3};"
        : "+f"(d[0]), "+f"(d[1]), "+f"(d[2]), "+f"(d[3])
        : "r"(a[0]), "r"(a[1]), "r"(a[2]), "r"(a[3]), "r"(b0), "r"(b1));
}
__device__ __forceinline__ void cp16(uint32_t dst, const void* src) {
    asm volatile("cp.async.cg.shared.global [%0], [%1], 16;" :: "r"(dst), "l"(src));
}
__device__ __forceinline__ void cp_commit() { asm volatile("cp.async.commit_group;" ::: "memory"); }
template <int N> __device__ __forceinline__ void cp_wait() {
    asm volatile("cp.async.wait_group %0;" :: "n"(N) : "memory");
}

// ---------------------------------------------------------------------------
// Split fp32 -> bf16 hi/lo
// ---------------------------------------------------------------------------
__global__ void __launch_bounds__(256) convert_split(
    const float* __restrict__ x, __nv_bfloat16* __restrict__ xh,
    __nv_bfloat16* __restrict__ xl)
{
    int i = (blockIdx.x * 256 + threadIdx.x) * 4;
    float4 v = *(const float4*)&x[i];
    __nv_bfloat16 h0 = __float2bfloat16(v.x);
    __nv_bfloat16 h1 = __float2bfloat16(v.y);
    __nv_bfloat16 h2 = __float2bfloat16(v.z);
    __nv_bfloat16 h3 = __float2bfloat16(v.w);
    __nv_bfloat16 l0 = __float2bfloat16(v.x - __bfloat162float(h0));
    __nv_bfloat16 l1 = __float2bfloat16(v.y - __bfloat162float(h1));
    __nv_bfloat16 l2 = __float2bfloat16(v.z - __bfloat162float(h2));
    __nv_bfloat16 l3 = __float2bfloat16(v.w - __bfloat162float(h3));
    ((__nv_bfloat162*)(xh + i))[0] = __nv_bfloat162(h0, h1);
    ((__nv_bfloat162*)(xh + i))[1] = __nv_bfloat162(h2, h3);
    ((__nv_bfloat162*)(xl + i))[0] = __nv_bfloat162(l0, l1);
    ((__nv_bfloat162*)(xl + i))[1] = __nv_bfloat162(l2, l3);
}

// ---------------------------------------------------------------------------
// HMMA split-bf16 3-pass GEMM: C[M,N] = X[M,768] @ W[N,768]^T  (fp32 out)
// 128x128 CTA tile, 8 warps 4x2 (warp tile 32x64), BK=64, cp.async double buf.
// M, N multiples of 128; Kd = 768.
// ---------------------------------------------------------------------------
#define STG 65536                     // bytes per stage (Ah,Al,Bh,Bl x 16KB)
#define OFF_AH 0
#define OFF_AL 16384
#define OFF_BH 32768
#define OFF_BL 49152

__global__ void __launch_bounds__(256, 1) mma_gemm(
    const __nv_bfloat16* __restrict__ Xh, const __nv_bfloat16* __restrict__ Xl,
    const __nv_bfloat16* __restrict__ Wh, const __nv_bfloat16* __restrict__ Wl,
    float* __restrict__ C, int N)
{
    extern __shared__ char smem[];
    const uint32_t sb = smem_u32(smem);
    const int tid = threadIdx.x;
    const int wid = tid >> 5;
    const int lane = tid & 31;
    const int warpRow = wid >> 1;     // 0..3 -> m offset *32
    const int warpCol = wid & 1;      // 0..1 -> n offset *64
    const int m0 = blockIdx.y * 128;
    const int n0 = blockIdx.x * 128;

    // per-thread cp.async source/dest mapping (4 rows of 16B per matrix)
    int ur[4], uc[4]; uint32_t usw[4];
#pragma unroll
    for (int t = 0; t < 4; t++) {
        int u = tid + t * 256;        // 0..1023
        ur[t] = u >> 3;               // row 0..127
        uc[t] = (u & 7) * 16;         // byte col 0..112
        usw[t] = sw128((uint32_t)(ur[t] * 128 + uc[t]));
    }

    // ldmatrix per-lane addressing
    const int lrow8 = ((lane >> 3) & 1) * 8 + (lane & 7);
    const int klane = ((lane >> 4) & 1) * 16;   // byte offset within k16 step
    const int a_row = warpRow * 32 + lrow8;
    const int b_row = warpCol * 64 + lrow8;

    float acc[2][8][4];
#pragma unroll
    for (int mt = 0; mt < 2; mt++)
#pragma unroll
        for (int nt = 0; nt < 8; nt++)
#pragma unroll
            for (int j = 0; j < 4; j++) acc[mt][nt][j] = 0.f;

    const int NCH = DM / 64;          // 12 chunks

    // prologue: load chunk 0
    {
        uint32_t s0 = sb;
#pragma unroll
        for (int t = 0; t < 4; t++) {
            size_t xo = (size_t)(m0 + ur[t]) * DM + (uc[t] >> 1);
            size_t wo = (size_t)(n0 + ur[t]) * DM + (uc[t] >> 1);
            cp16(s0 + OFF_AH + usw[t], Xh + xo);
            cp16(s0 + OFF_AL + usw[t], Xl + xo);
            cp16(s0 + OFF_BH + usw[t], Wh + wo);
            cp16(s0 + OFF_BL + usw[t], Wl + wo);
        }
        cp_commit();
    }

    for (int c = 0; c < NCH; c++) {
        if (c + 1 < NCH) {
            uint32_t s1 = sb + ((c + 1) & 1) * STG;
            int k0 = (c + 1) * 64;
#pragma unroll
            for (int t = 0; t < 4; t++) {
                size_t xo = (size_t)(m0 + ur[t]) * DM + k0 + (uc[t] >> 1);
                size_t wo = (size_t)(n0 + ur[t]) * DM + k0 + (uc[t] >> 1);
                cp16(s1 + OFF_AH + usw[t], Xh + xo);
                cp16(s1 + OFF_AL + usw[t], Xl + xo);
                cp16(s1 + OFF_BH + usw[t], Wh + wo);
                cp16(s1 + OFF_BL + usw[t], Wl + wo);
            }
            cp_commit();
            cp_wait<1>();
        } else {
            cp_wait<0>();
        }
        __syncthreads();

        const uint32_t sc = sb + (c & 1) * STG;
#pragma unroll
        for (int kt = 0; kt < 4; kt++) {
            const uint32_t kb = kt * 32 + klane;
            uint32_t ah[2][4], al[2][4], bh[4][4], bl[4][4];
#pragma unroll
            for (int mt = 0; mt < 2; mt++) {
                uint32_t off = sw128((uint32_t)((a_row + mt * 16) * 128 + kb));
                ldsm_x4(ah[mt], sc + OFF_AH + off);
                ldsm_x4(al[mt], sc + OFF_AL + off);
            }
#pragma unroll
            for (int nt2 = 0; nt2 < 4; nt2++) {
                uint32_t off = sw128((uint32_t)((b_row + nt2 * 16) * 128 + kb));
                ldsm_x4(bh[nt2], sc + OFF_BH + off);
                ldsm_x4(bl[nt2], sc + OFF_BL + off);
            }
#pragma unroll
            for (int mt = 0; mt < 2; mt++)
#pragma unroll
                for (int nt = 0; nt < 8; nt++) {
                    int p = nt >> 1, j = nt & 1;
                    mma_bf16(acc[mt][nt], ah[mt], bh[p][j], bh[p][2 + j]);
                    mma_bf16(acc[mt][nt], ah[mt], bl[p][j], bl[p][2 + j]);
                    mma_bf16(acc[mt][nt], al[mt], bh[p][j], bh[p][2 + j]);
                }
        }
        __syncthreads();
    }

    // epilogue
    const int g = lane >> 2;
    const int tc = (lane & 3) * 2;
#pragma unroll
    for (int mt = 0; mt < 2; mt++) {
        int row = m0 + warpRow * 32 + mt * 16 + g;
#pragma unroll
        for (int nt = 0; nt < 8; nt++) {
            int col = n0 + warpCol * 64 + nt * 8 + tc;
            *(float2*)&C[(size_t)row * N + col] =
                make_float2(acc[mt][nt][0], acc[mt][nt][1]);
            *(float2*)&C[(size_t)(row + 8) * N + col] =
                make_float2(acc[mt][nt][2], acc[mt][nt][3]);
        }
    }
}

// ---------------------------------------------------------------------------
// Attention (R2/R3 structure), Q/K from combined buffer (stride QKS=384).
// ---------------------------------------------------------------------------
__global__ void __launch_bounds__(256, 3) attn_kernel(
    const float* __restrict__ QK, const float* __restrict__ V, float* __restrict__ Y)
{
    __shared__ float QsT[16][132];
    __shared__ float KsT[16][36];
    __shared__ float Vs[KT][68];
    __shared__ float AsT[KT][132];

    const int tid = threadIdx.x;
    const int tx = tid & 15;
    const int ty = tid >> 4;
    const int r0 = ty * 8;
    const int c0 = tx * 2;
    const int c2 = tx * 4;
    const int qb0 = blockIdx.x * 128;
    const int h = blockIdx.y;
    const int b = blockIdx.z;

    const float* Qp = QK + (size_t)(b * LSEQ + qb0) * QKS + h * FEATD;
    const float* Kp = QK + (size_t)(b * LSEQ) * QKS + 192 + h * FEATD;
    const float* Vp = V + (size_t)(b * LSEQ) * DM + h * HD;

    {
        int r = tid >> 1;
        int c4 = (tid & 1) * 8;
        float4 t0 = *(const float4*)&Qp[(size_t)r * QKS + c4];
        float4 t1 = *(const float4*)&Qp[(size_t)r * QKS + c4 + 4];
        QsT[c4 + 0][r] = t0.x; QsT[c4 + 1][r] = t0.y;
        QsT[c4 + 2][r] = t0.z; QsT[c4 + 3][r] = t0.w;
        QsT[c4 + 4][r] = t1.x; QsT[c4 + 5][r] = t1.y;
        QsT[c4 + 6][r] = t1.z; QsT[c4 + 7][r] = t1.w;
    }

    const ull Z = pack2(0.f, 0.f);
    ull acc[4][4];
    ull zacc[4];
#pragma unroll
    for (int i = 0; i < 4; i++) {
        zacc[i] = Z;
#pragma unroll
        for (int j = 0; j < 4; j++) acc[i][j] = Z;
    }

    for (int m0 = 0; m0 < LSEQ; m0 += KT) {
        __syncthreads();
        if (tid < 128) {
            int kk = tid >> 2;
            int c4 = (tid & 3) * 4;
            float4 t = *(const float4*)&Kp[(size_t)(m0 + kk) * QKS + c4];
            KsT[c4 + 0][kk] = t.x; KsT[c4 + 1][kk] = t.y;
            KsT[c4 + 2][kk] = t.z; KsT[c4 + 3][kk] = t.w;
        }
        {
            int r = tid >> 3;
            int c = (tid & 7) * 8;
            *(float4*)&Vs[r][c]     = *(const float4*)&Vp[(size_t)(m0 + r) * DM + c];
            *(float4*)&Vs[r][c + 4] = *(const float4*)&Vp[(size_t)(m0 + r) * DM + c + 4];
        }
        __syncthreads();

        ull s2[4][2];
#pragma unroll
        for (int i = 0; i < 4; i++) { s2[i][0] = Z; s2[i][1] = Z; }
#pragma unroll
        for (int d = 0; d < 16; d++) {
            ulonglong2 qa = *(const ulonglong2*)&QsT[d][r0];
            ulonglong2 qb = *(const ulonglong2*)&QsT[d][r0 + 4];
            float k0v = KsT[d][c0], k1v = KsT[d][c0 + 1];
            ull kk0 = pack2(k0v, k0v), kk1 = pack2(k1v, k1v);
            s2[0][0] = ffma2(qa.x, kk0, s2[0][0]); s2[0][1] = ffma2(qa.x, kk1, s2[0][1]);
            s2[1][0] = ffma2(qa.y, kk0, s2[1][0]); s2[1][1] = ffma2(qa.y, kk1, s2[1][1]);
            s2[2][0] = ffma2(qb.x, kk0, s2[2][0]); s2[2][1] = ffma2(qb.x, kk1, s2[2][1]);
            s2[3][0] = ffma2(qb.y, kk0, s2[3][0]); s2[3][1] = ffma2(qb.y, kk1, s2[3][1]);
        }
#pragma unroll
        for (int i2 = 0; i2 < 4; i2++) {
            int n0r = qb0 + r0 + 2 * i2;
#pragma unroll
            for (int j = 0; j < 2; j++) {
                float sa, sb; unpack2(s2[i2][j], sa, sb);
                int m = m0 + c0 + j;
                float a0 = fmaf(sa, fmaf(sa, 0.03125f, 0.25f), 1.0f);
                float a1 = fmaf(sb, fmaf(sb, 0.03125f, 0.25f), 1.0f);
                if (m <= n0r)     a0 += a0;
                if (m <= n0r + 1) a1 += a1;
                *(ull*)&AsT[c0 + j][r0 + 2 * i2] = pack2(a0, a1);
            }
        }
        __syncthreads();

#pragma unroll 8
        for (int k = 0; k < KT; k++) {
            ulonglong2 a01 = *(const ulonglong2*)&AsT[k][r0];
            ulonglong2 a23 = *(const ulonglong2*)&AsT[k][r0 + 4];
            ull arp[4] = { a01.x, a01.y, a23.x, a23.y };
            float4 v = *(const float4*)&Vs[k][c2];
            ull v0 = pack2(v.x, v.x), v1 = pack2(v.y, v.y);
            ull v2 = pack2(v.z, v.z), v3 = pack2(v.w, v.w);
#pragma unroll
            for (int i2 = 0; i2 < 4; i2++) {
                acc[i2][0] = ffma2(arp[i2], v0, acc[i2][0]);
                acc[i2][1] = ffma2(arp[i2], v1, acc[i2][1]);
                acc[i2][2] = ffma2(arp[i2], v2, acc[i2][2]);
                acc[i2][3] = ffma2(arp[i2], v3, acc[i2][3]);
                zacc[i2]   = fadd2(arp[i2], zacc[i2]);
            }
        }
    }

#pragma unroll
    for (int i2 = 0; i2 < 4; i2++) {
        float z0, z1; unpack2(zacc[i2], z0, z1);
        float inv0 = 1.f / z0, inv1 = 1.f / z1;
        float y0[4], y1[4];
#pragma unroll
        for (int j = 0; j < 4; j++) {
            float lo, hi; unpack2(acc[i2][j], lo, hi);
            y0[j] = lo * inv0;
            y1[j] = hi * inv1;
        }
        size_t row0 = (size_t)(b * LSEQ + qb0 + r0 + 2 * i2) * DM + h * HD + c2;
        *(float4*)&Y[row0]      = make_float4(y0[0], y0[1], y0[2], y0[3]);
        *(float4*)&Y[row0 + DM] = make_float4(y1[0], y1[1], y1[2], y1[3]);
    }
}

// ---------------------------------------------------------------------------
extern "C" void kernel_launch(void* const* d_in, const int* in_sizes, int n_in,
                              void* d_out, int out_size)
{
    const float* hs = (const float*)d_in[0];
    const float* Wq = (const float*)d_in[1];
    const float* Wk = (const float*)d_in[2];
    const float* Wv = (const float*)d_in[3];
    const float* Wo = (const float*)d_in[4];
    float* out = (float*)d_out;

    float *QK, *V, *Y;
    __nv_bfloat16 *Xh, *Xl, *Wh, *Wl;
    cudaGetSymbolAddress((void**)&QK, g_QK);
    cudaGetSymbolAddress((void**)&V, g_V);
    cudaGetSymbolAddress((void**)&Y, g_Y);
    cudaGetSymbolAddress((void**)&Xh, g_Xh);
    cudaGetSymbolAddress((void**)&Xl, g_Xl);
    cudaGetSymbolAddress((void**)&Wh, g_Wh);
    cudaGetSymbolAddress((void**)&Wl, g_Wl);

    static bool attr_set = false;
    if (!attr_set) {
        cudaFuncSetAttribute(mma_gemm, cudaFuncAttributeMaxDynamicSharedMemorySize, 2 * STG);
        attr_set = true;
    }

    // Split hidden states
    convert_split<<<(ROWS * DM) / 1024, 256>>>(hs, Xh, Xl);

    // Combined Q|K projection (N = 384)
    convert_split<<<(192 * DM) / 1024, 256>>>(Wq, Wh, Wl);
    convert_split<<<(192 * DM) / 1024, 256>>>(Wk, Wh + 192 * DM, Wl + 192 * DM);
    {
        dim3 g(QKS / 128, ROWS / 128);
        mma_gemm<<<g, 256, 2 * STG>>>(Xh, Xl, Wh, Wl, QK, QKS);
    }
    // V projection (N = 768)
    convert_split<<<(DM * DM) / 1024, 256>>>(Wv, Wh, Wl);
    {
        dim3 g(DM / 128, ROWS / 128);
        mma_gemm<<<g, 256, 2 * STG>>>(Xh, Xl, Wh, Wl, V, DM);
    }

    // Attention
    {
        dim3 ga(LSEQ / 128, NH, BATCH);
        attn_kernel<<<ga, 256>>>(QK, V, Y);
    }

    // Output projection
    convert_split<<<(ROWS * DM) / 1024, 256>>>(Y, Xh, Xl);
    convert_split<<<(DM * DM) / 1024, 256>>>(Wo, Wh, Wl);
    {
        dim3 g(DM / 128, ROWS / 128);
        mma_gemm<<<g, 256, 2 * STG>>>(Xh, Xl, Wh, Wl, out, DM);
    }
}

// round 7
// speedup vs baseline: 3.6456x; 1.9319x over previous
#include <cuda_runtime.h>
#include <cuda_bf16.h>
#include <cstdint>

#define LSEQ 2048
#define BATCH 2
#define NH 12
#define FEATD 16
#define HD 64
#define DM 768
#define QKS 384             // combined Q|K projection width
#define ROWS (BATCH * LSEQ) // 4096
#define AKT 64              // attention key tile

// Scratch (no cudaMalloc allowed)
__device__ __nv_bfloat16 g_Xh[ROWS * DM];   // X split; later reused as Y split
__device__ __nv_bfloat16 g_Xl[ROWS * DM];
__device__ __nv_bfloat16 g_Wh[DM * DM];
__device__ __nv_bfloat16 g_Wl[DM * DM];
__device__ __nv_bfloat16 g_QKh[ROWS * QKS];
__device__ __nv_bfloat16 g_QKl[ROWS * QKS];
__device__ __nv_bfloat16 g_Vh[ROWS * DM];
__device__ __nv_bfloat16 g_Vl[ROWS * DM];

// ---- helpers ----
__device__ __forceinline__ uint32_t smem_u32(const void* p) {
    uint32_t a;
    asm("{ .reg .u64 t; cvta.to.shared.u64 t, %1; cvt.u32.u64 %0, t; }" : "=r"(a) : "l"(p));
    return a;
}
__device__ __forceinline__ uint32_t sw128(uint32_t o) { return o ^ ((o >> 3) & 0x70); }
__device__ __forceinline__ void ldsm_x4(uint32_t* r, uint32_t addr) {
    asm volatile("ldmatrix.sync.aligned.m8n8.x4.shared.b16 {%0,%1,%2,%3}, [%4];"
                 : "=r"(r[0]), "=r"(r[1]), "=r"(r[2]), "=r"(r[3]) : "r"(addr));
}
__device__ __forceinline__ void ldsm_x4t(uint32_t* r, uint32_t addr) {
    asm volatile("ldmatrix.sync.aligned.m8n8.x4.trans.shared.b16 {%0,%1,%2,%3}, [%4];"
                 : "=r"(r[0]), "=r"(r[1]), "=r"(r[2]), "=r"(r[3]) : "r"(addr));
}
__device__ __forceinline__ void mma_bf16(float* d, const uint32_t* a, uint32_t b0, uint32_t b1) {
    asm volatile(
        "mma.sync.aligned.m16n8k16.row.col.f32.bf16.bf16.f32 "
        "{%0,%1,%2,%3}, {%4,%5,%6,%7}, {%8,%9}, {%0,%1,%2,%3};"
        : "+f"(d[0]), "+f"(d[1]), "+f"(d[2]), "+f"(d[3])
        : "r"(a[0]), "r"(a[1]), "r"(a[2]), "r"(a[3]), "r"(b0), "r"(b1));
}
__device__ __forceinline__ void cp16(uint32_t dst, const void* src) {
    asm volatile("cp.async.cg.shared.global [%0], [%1], 16;" :: "r"(dst), "l"(src));
}
__device__ __forceinline__ void cp_commit() { asm volatile("cp.async.commit_group;" ::: "memory"); }
template <int N> __device__ __forceinline__ void cp_wait() {
    asm volatile("cp.async.wait_group %0;" :: "n"(N) : "memory");
}
// pack two f32 -> bf16x2 (lo = first arg)
__device__ __forceinline__ uint32_t cvt2(float lo, float hi) {
    uint32_t r; asm("cvt.rn.bf16x2.f32 %0, %1, %2;" : "=r"(r) : "f"(hi), "f"(lo)); return r;
}
__device__ __forceinline__ float poly(float s) {
    return fmaf(s, fmaf(s, 0.03125f, 0.25f), 1.0f);
}
// split one float into bf16 hi + residual (as floats)
__device__ __forceinline__ void split1(float v, float& hi, float& lo) {
    hi = __bfloat162float(__float2bfloat16(v));
    lo = v - hi;
}

// ---------------------------------------------------------------------------
// Split fp32 -> bf16 hi/lo
// ---------------------------------------------------------------------------
__global__ void __launch_bounds__(256) convert_split(
    const float* __restrict__ x, __nv_bfloat16* __restrict__ xh,
    __nv_bfloat16* __restrict__ xl)
{
    int i = (blockIdx.x * 256 + threadIdx.x) * 4;
    float4 v = *(const float4*)&x[i];
    __nv_bfloat16 h0 = __float2bfloat16(v.x);
    __nv_bfloat16 h1 = __float2bfloat16(v.y);
    __nv_bfloat16 h2 = __float2bfloat16(v.z);
    __nv_bfloat16 h3 = __float2bfloat16(v.w);
    __nv_bfloat16 l0 = __float2bfloat16(v.x - __bfloat162float(h0));
    __nv_bfloat16 l1 = __float2bfloat16(v.y - __bfloat162float(h1));
    __nv_bfloat16 l2 = __float2bfloat16(v.z - __bfloat162float(h2));
    __nv_bfloat16 l3 = __float2bfloat16(v.w - __bfloat162float(h3));
    ((__nv_bfloat162*)(xh + i))[0] = __nv_bfloat162(h0, h1);
    ((__nv_bfloat162*)(xh + i))[1] = __nv_bfloat162(h2, h3);
    ((__nv_bfloat162*)(xl + i))[0] = __nv_bfloat162(l0, l1);
    ((__nv_bfloat162*)(xl + i))[1] = __nv_bfloat162(l2, l3);
}

// ---------------------------------------------------------------------------
// HMMA split-bf16 3-pass GEMM: C[M,N] = X[M,768] @ W[N,768]^T
// MODE 0: fp32 output C. MODE 1: split bf16 outputs Ch/Cl.
// ---------------------------------------------------------------------------
#define STG 65536
#define OFF_AH 0
#define OFF_AL 16384
#define OFF_BH 32768
#define OFF_BL 49152

template <int MODE>
__global__ void __launch_bounds__(256, 1) mma_gemm(
    const __nv_bfloat16* __restrict__ Xh, const __nv_bfloat16* __restrict__ Xl,
    const __nv_bfloat16* __restrict__ Wh, const __nv_bfloat16* __restrict__ Wl,
    float* __restrict__ C, __nv_bfloat16* __restrict__ Ch,
    __nv_bfloat16* __restrict__ Cl, int N)
{
    extern __shared__ char smem[];
    const uint32_t sb = smem_u32(smem);
    const int tid = threadIdx.x;
    const int wid = tid >> 5;
    const int lane = tid & 31;
    const int warpRow = wid >> 1;
    const int warpCol = wid & 1;
    const int m0 = blockIdx.y * 128;
    const int n0 = blockIdx.x * 128;

    int ur[4], uc[4]; uint32_t usw[4];
#pragma unroll
    for (int t = 0; t < 4; t++) {
        int u = tid + t * 256;
        ur[t] = u >> 3;
        uc[t] = (u & 7) * 16;
        usw[t] = sw128((uint32_t)(ur[t] * 128 + uc[t]));
    }

    const int lrow8 = ((lane >> 3) & 1) * 8 + (lane & 7);
    const int klane = ((lane >> 4) & 1) * 16;
    const int a_row = warpRow * 32 + lrow8;
    const int b_row = warpCol * 64 + lrow8;

    float acc[2][8][4];
#pragma unroll
    for (int mt = 0; mt < 2; mt++)
#pragma unroll
        for (int nt = 0; nt < 8; nt++)
#pragma unroll
            for (int j = 0; j < 4; j++) acc[mt][nt][j] = 0.f;

    const int NCH = DM / 64;
    {
        uint32_t s0 = sb;
#pragma unroll
        for (int t = 0; t < 4; t++) {
            size_t xo = (size_t)(m0 + ur[t]) * DM + (uc[t] >> 1);
            size_t wo = (size_t)(n0 + ur[t]) * DM + (uc[t] >> 1);
            cp16(s0 + OFF_AH + usw[t], Xh + xo);
            cp16(s0 + OFF_AL + usw[t], Xl + xo);
            cp16(s0 + OFF_BH + usw[t], Wh + wo);
            cp16(s0 + OFF_BL + usw[t], Wl + wo);
        }
        cp_commit();
    }

    for (int c = 0; c < NCH; c++) {
        if (c + 1 < NCH) {
            uint32_t s1 = sb + ((c + 1) & 1) * STG;
            int k0 = (c + 1) * 64;
#pragma unroll
            for (int t = 0; t < 4; t++) {
                size_t xo = (size_t)(m0 + ur[t]) * DM + k0 + (uc[t] >> 1);
                size_t wo = (size_t)(n0 + ur[t]) * DM + k0 + (uc[t] >> 1);
                cp16(s1 + OFF_AH + usw[t], Xh + xo);
                cp16(s1 + OFF_AL + usw[t], Xl + xo);
                cp16(s1 + OFF_BH + usw[t], Wh + wo);
                cp16(s1 + OFF_BL + usw[t], Wl + wo);
            }
            cp_commit();
            cp_wait<1>();
        } else {
            cp_wait<0>();
        }
        __syncthreads();

        const uint32_t sc = sb + (c & 1) * STG;
#pragma unroll
        for (int kt = 0; kt < 4; kt++) {
            const uint32_t kb = kt * 32 + klane;
            uint32_t ah[2][4], al[2][4], bh[4][4], bl[4][4];
#pragma unroll
            for (int mt = 0; mt < 2; mt++) {
                uint32_t off = sw128((uint32_t)((a_row + mt * 16) * 128 + kb));
                ldsm_x4(ah[mt], sc + OFF_AH + off);
                ldsm_x4(al[mt], sc + OFF_AL + off);
            }
#pragma unroll
            for (int nt2 = 0; nt2 < 4; nt2++) {
                uint32_t off = sw128((uint32_t)((b_row + nt2 * 16) * 128 + kb));
                ldsm_x4(bh[nt2], sc + OFF_BH + off);
                ldsm_x4(bl[nt2], sc + OFF_BL + off);
            }
#pragma unroll
            for (int mt = 0; mt < 2; mt++)
#pragma unroll
                for (int nt = 0; nt < 8; nt++) {
                    int p = nt >> 1, j = nt & 1;
                    mma_bf16(acc[mt][nt], ah[mt], bh[p][j], bh[p][2 + j]);
                    mma_bf16(acc[mt][nt], ah[mt], bl[p][j], bl[p][2 + j]);
                    mma_bf16(acc[mt][nt], al[mt], bh[p][j], bh[p][2 + j]);
                }
        }
        __syncthreads();
    }

    const int g = lane >> 2;
    const int tc = (lane & 3) * 2;
#pragma unroll
    for (int mt = 0; mt < 2; mt++) {
        int row = m0 + warpRow * 32 + mt * 16 + g;
#pragma unroll
        for (int nt = 0; nt < 8; nt++) {
            int col = n0 + warpCol * 64 + nt * 8 + tc;
            if (MODE == 0) {
                *(float2*)&C[(size_t)row * N + col] =
                    make_float2(acc[mt][nt][0], acc[mt][nt][1]);
                *(float2*)&C[(size_t)(row + 8) * N + col] =
                    make_float2(acc[mt][nt][2], acc[mt][nt][3]);
            } else {
                float v0 = acc[mt][nt][0], v1 = acc[mt][nt][1];
                float v2 = acc[mt][nt][2], v3 = acc[mt][nt][3];
                __nv_bfloat16 h0 = __float2bfloat16(v0), h1 = __float2bfloat16(v1);
                __nv_bfloat16 h2 = __float2bfloat16(v2), h3 = __float2bfloat16(v3);
                __nv_bfloat16 l0 = __float2bfloat16(v0 - __bfloat162float(h0));
                __nv_bfloat16 l1 = __float2bfloat16(v1 - __bfloat162float(h1));
                __nv_bfloat16 l2 = __float2bfloat16(v2 - __bfloat162float(h2));
                __nv_bfloat16 l3 = __float2bfloat16(v3 - __bfloat162float(h3));
                *(__nv_bfloat162*)&Ch[(size_t)row * N + col] = __nv_bfloat162(h0, h1);
                *(__nv_bfloat162*)&Cl[(size_t)row * N + col] = __nv_bfloat162(l0, l1);
                *(__nv_bfloat162*)&Ch[(size_t)(row + 8) * N + col] = __nv_bfloat162(h2, h3);
                *(__nv_bfloat162*)&Cl[(size_t)(row + 8) * N + col] = __nv_bfloat162(l2, l3);
            }
        }
    }
}

// ---------------------------------------------------------------------------
// HMMA attention.
// S = Q K^T (3-pass split bf16), A = poly(s)*(2 if causal) split into Ah/Al,
// z = rowsum(A) fp32, Y += A V (3-pass: Ah Vh + Ah Vl + Al Vh).
// Outputs Y as split bf16 (Yh, Yl).
// ---------------------------------------------------------------------------
#define AQ_OFF 0                     // Qh @0, Ql @6144  (128 rows * 48B)
#define AK_OFF 12288                 // + st*6144 + split*3072 (64 rows * 48B)
#define AV_OFF 24576                 // + st*16384 + split*8192 (64 rows * 128B, SW128)
#define ASM_TOTAL 57344

__device__ __forceinline__ void attn_load_tile(
    uint32_t sb, int st, int m0, int tid,
    const __nv_bfloat16* QKh, const __nv_bfloat16* QKl,
    const __nv_bfloat16* Vh, const __nv_bfloat16* Vl,
    size_t rowbase, int h)
{
    {
        int r = (tid & 127) >> 1, half = tid & 1;
        const __nv_bfloat16* src = ((tid < 128) ? QKh : QKl)
            + (rowbase + m0 + r) * QKS + 192 + h * FEATD + half * 8;
        cp16(sb + AK_OFF + st * 6144 + ((tid < 128) ? 0 : 3072) + r * 48 + half * 16, src);
    }
#pragma unroll
    for (int i = 0; i < 4; i++) {
        int u = tid + i * 256;
        int split = u >> 9, u2 = u & 511;
        int r = u2 >> 3, ch = (u2 & 7) * 16;
        const __nv_bfloat16* src = (split ? Vl : Vh)
            + (rowbase + m0 + r) * DM + h * HD + (ch >> 1);
        cp16(sb + AV_OFF + st * 16384 + split * 8192 + sw128((uint32_t)(r * 128 + ch)), src);
    }
}

__global__ void __launch_bounds__(256, 2) attn_mma(
    const __nv_bfloat16* __restrict__ QKh, const __nv_bfloat16* __restrict__ QKl,
    const __nv_bfloat16* __restrict__ Vh,  const __nv_bfloat16* __restrict__ Vl,
    __nv_bfloat16* __restrict__ Yh, __nv_bfloat16* __restrict__ Yl)
{
    extern __shared__ char smem[];
    const uint32_t sb = smem_u32(smem);
    const int tid = threadIdx.x;
    const int wid = tid >> 5;
    const int lane = tid & 31;
    const int qb0 = blockIdx.x * 128;
    const int h = blockIdx.y;
    const int b = blockIdx.z;
    const size_t rowbase = (size_t)b * LSEQ;

    // group 0: Q (both splits)
    {
        int r = tid >> 1, half = tid & 1;
        cp16(sb + AQ_OFF + r * 48 + half * 16,
             QKh + (rowbase + qb0 + r) * QKS + h * FEATD + half * 8);
        cp16(sb + AQ_OFF + 6144 + r * 48 + half * 16,
             QKl + (rowbase + qb0 + r) * QKS + h * FEATD + half * 8);
    }
    cp_commit();
    // group 1: tile 0
    attn_load_tile(sb, 0, 0, tid, QKh, QKl, Vh, Vl, rowbase, h);
    cp_commit();
    cp_wait<1>();           // Q ready
    __syncthreads();

    uint32_t qh[4], ql[4];
    {
        uint32_t off = (uint32_t)((wid * 16 + ((lane >> 3) & 1) * 8 + (lane & 7)) * 48
                                  + ((lane >> 4) & 1) * 16);
        ldsm_x4(qh, sb + AQ_OFF + off);
        ldsm_x4(ql, sb + AQ_OFF + 6144 + off);
    }

    float accY[8][4];
#pragma unroll
    for (int nt = 0; nt < 8; nt++)
#pragma unroll
        for (int j = 0; j < 4; j++) accY[nt][j] = 0.f;
    float z0 = 0.f, z1 = 0.f;
    const int qrow0 = qb0 + wid * 16 + (lane >> 2);   // global query of c0/c1 rows

    const int NT = LSEQ / AKT;   // 32 tiles
    for (int c = 0; c < NT; c++) {
        const int m0 = c * AKT;
        if (c + 1 < NT) {
            attn_load_tile(sb, (c + 1) & 1, m0 + AKT, tid, QKh, QKl, Vh, Vl, rowbase, h);
            cp_commit();
            cp_wait<1>();
        } else {
            cp_wait<0>();
        }
        __syncthreads();

        const uint32_t kb = sb + AK_OFF + (c & 1) * 6144;
        const uint32_t vb = sb + AV_OFF + (c & 1) * 16384;
        const int relq0 = qrow0 - m0;

#pragma unroll
        for (int s = 0; s < 4; s++) {
            // ---- S for keys 16s..16s+15 (2 n-tiles) ----
            uint32_t koff = (uint32_t)((16 * s + ((lane >> 4) & 1) * 8 + (lane & 7)) * 48
                                       + ((lane >> 3) & 1) * 16);
            uint32_t bh[4], bl[4];
            ldsm_x4(bh, kb + koff);
            ldsm_x4(bl, kb + 3072 + koff);
            float s0[4] = {0.f, 0.f, 0.f, 0.f};
            float s1[4] = {0.f, 0.f, 0.f, 0.f};
            mma_bf16(s0, qh, bh[0], bh[1]);
            mma_bf16(s0, qh, bl[0], bl[1]);
            mma_bf16(s0, ql, bh[0], bh[1]);
            mma_bf16(s1, qh, bh[2], bh[3]);
            mma_bf16(s1, qh, bl[2], bl[3]);
            mma_bf16(s1, ql, bh[2], bh[3]);

            // ---- poly + causal + z + split A into hi/lo a-frags ----
            uint32_t aah[4], aal[4];
            {
                const int key0 = 16 * s + (lane & 3) * 2;
                const int key8 = key0 + 8;
                float a0 = poly(s0[0]); if (key0     <= relq0)     a0 += a0;
                float a1 = poly(s0[1]); if (key0 + 1 <= relq0)     a1 += a1;
                float a2 = poly(s0[2]); if (key0     <= relq0 + 8) a2 += a2;
                float a3 = poly(s0[3]); if (key0 + 1 <= relq0 + 8) a3 += a3;
                float b0 = poly(s1[0]); if (key8     <= relq0)     b0 += b0;
                float b1 = poly(s1[1]); if (key8 + 1 <= relq0)     b1 += b1;
                float b2 = poly(s1[2]); if (key8     <= relq0 + 8) b2 += b2;
                float b3 = poly(s1[3]); if (key8 + 1 <= relq0 + 8) b3 += b3;
                z0 += (a0 + a1) + (b0 + b1);
                z1 += (a2 + a3) + (b2 + b3);
                float h0, l0, h1, l1, h2, l2, h3, l3;
                split1(a0, h0, l0); split1(a1, h1, l1);
                split1(a2, h2, l2); split1(a3, h3, l3);
                aah[0] = cvt2(h0, h1); aal[0] = cvt2(l0, l1);
                aah[1] = cvt2(h2, h3); aal[1] = cvt2(l2, l3);
                split1(b0, h0, l0); split1(b1, h1, l1);
                split1(b2, h2, l2); split1(b3, h3, l3);
                aah[2] = cvt2(h0, h1); aal[2] = cvt2(l0, l1);
                aah[3] = cvt2(h2, h3); aal[3] = cvt2(l2, l3);
            }

            // ---- Y += A V for this k16 step (3-pass) ----
#pragma unroll
            for (int g4 = 0; g4 < 4; g4++) {
                uint32_t voff = sw128((uint32_t)((16 * s + ((lane >> 3) & 1) * 8 + (lane & 7)) * 128
                                                 + 32 * g4 + ((lane >> 4) & 1) * 16));
                uint32_t vhf[4], vlf[4];
                ldsm_x4t(vhf, vb + voff);
                ldsm_x4t(vlf, vb + 8192 + voff);
                mma_bf16(accY[2 * g4],     aah, vhf[0], vhf[1]);
                mma_bf16(accY[2 * g4],     aah, vlf[0], vlf[1]);
                mma_bf16(accY[2 * g4],     aal, vhf[0], vhf[1]);
                mma_bf16(accY[2 * g4 + 1], aah, vhf[2], vhf[3]);
                mma_bf16(accY[2 * g4 + 1], aah, vlf[2], vlf[3]);
                mma_bf16(accY[2 * g4 + 1], aal, vhf[2], vhf[3]);
            }
        }
        __syncthreads();
    }

    // z reduction across the lane quad (lanes sharing a row)
    z0 += __shfl_xor_sync(0xFFFFFFFFu, z0, 1);
    z0 += __shfl_xor_sync(0xFFFFFFFFu, z0, 2);
    z1 += __shfl_xor_sync(0xFFFFFFFFu, z1, 1);
    z1 += __shfl_xor_sync(0xFFFFFFFFu, z1, 2);
    const float inv0 = 1.f / z0, inv1 = 1.f / z1;

    const size_t r0g = rowbase + qb0 + wid * 16 + (lane >> 2);
    const int colb = h * HD + (lane & 3) * 2;
#pragma unroll
    for (int nt = 0; nt < 8; nt++) {
        float y0 = accY[nt][0] * inv0, y1 = accY[nt][1] * inv0;
        float y2 = accY[nt][2] * inv1, y3 = accY[nt][3] * inv1;
        __nv_bfloat16 h0 = __float2bfloat16(y0), h1 = __float2bfloat16(y1);
        __nv_bfloat16 h2 = __float2bfloat16(y2), h3 = __float2bfloat16(y3);
        __nv_bfloat16 l0 = __float2bfloat16(y0 - __bfloat162float(h0));
        __nv_bfloat16 l1 = __float2bfloat16(y1 - __bfloat162float(h1));
        __nv_bfloat16 l2 = __float2bfloat16(y2 - __bfloat162float(h2));
        __nv_bfloat16 l3 = __float2bfloat16(y3 - __bfloat162float(h3));
        size_t o0 = r0g * DM + colb + nt * 8;
        size_t o1 = (r0g + 8) * DM + colb + nt * 8;
        *(__nv_bfloat162*)&Yh[o0] = __nv_bfloat162(h0, h1);
        *(__nv_bfloat162*)&Yl[o0] = __nv_bfloat162(l0, l1);
        *(__nv_bfloat162*)&Yh[o1] = __nv_bfloat162(h2, h3);
        *(__nv_bfloat162*)&Yl[o1] = __nv_bfloat162(l2, l3);
    }
}

// ---------------------------------------------------------------------------
extern "C" void kernel_launch(void* const* d_in, const int* in_sizes, int n_in,
                              void* d_out, int out_size)
{
    const float* hs = (const float*)d_in[0];
    const float* Wq = (const float*)d_in[1];
    const float* Wk = (const float*)d_in[2];
    const float* Wv = (const float*)d_in[3];
    const float* Wo = (const float*)d_in[4];
    float* out = (float*)d_out;

    __nv_bfloat16 *Xh, *Xl, *Wh, *Wl, *QKh, *QKl, *Vh, *Vl;
    cudaGetSymbolAddress((void**)&Xh, g_Xh);
    cudaGetSymbolAddress((void**)&Xl, g_Xl);
    cudaGetSymbolAddress((void**)&Wh, g_Wh);
    cudaGetSymbolAddress((void**)&Wl, g_Wl);
    cudaGetSymbolAddress((void**)&QKh, g_QKh);
    cudaGetSymbolAddress((void**)&QKl, g_QKl);
    cudaGetSymbolAddress((void**)&Vh, g_Vh);
    cudaGetSymbolAddress((void**)&Vl, g_Vl);

    cudaFuncSetAttribute(mma_gemm<0>, cudaFuncAttributeMaxDynamicSharedMemorySize, 2 * STG);
    cudaFuncSetAttribute(mma_gemm<1>, cudaFuncAttributeMaxDynamicSharedMemorySize, 2 * STG);
    cudaFuncSetAttribute(attn_mma, cudaFuncAttributeMaxDynamicSharedMemorySize, ASM_TOTAL);

    // Split inputs
    convert_split<<<(ROWS * DM) / 1024, 256>>>(hs, Xh, Xl);
    convert_split<<<(192 * DM) / 1024, 256>>>(Wq, Wh, Wl);
    convert_split<<<(192 * DM) / 1024, 256>>>(Wk, Wh + 192 * DM, Wl + 192 * DM);

    // QK projection -> split bf16
    {
        dim3 g(QKS / 128, ROWS / 128);
        mma_gemm<1><<<g, 256, 2 * STG>>>(Xh, Xl, Wh, Wl, nullptr, QKh, QKl, QKS);
    }
    // V projection -> split bf16
    convert_split<<<(DM * DM) / 1024, 256>>>(Wv, Wh, Wl);
    {
        dim3 g(DM / 128, ROWS / 128);
        mma_gemm<1><<<g, 256, 2 * STG>>>(Xh, Xl, Wh, Wl, nullptr, Vh, Vl, DM);
    }

    // Attention -> Y split (reuses Xh/Xl, X no longer needed)
    {
        dim3 ga(LSEQ / 128, NH, BATCH);
        attn_mma<<<ga, 256, ASM_TOTAL>>>(QKh, QKl, Vh, Vl, Xh, Xl);
    }

    // Output projection -> fp32 out
    convert_split<<<(DM * DM) / 1024, 256>>>(Wo, Wh, Wl);
    {
        dim3 g(DM / 128, ROWS / 128);
        mma_gemm<0><<<g, 256, 2 * STG>>>(Xh, Xl, Wh, Wl, out, nullptr, nullptr, DM);
    }
}

// round 8
// speedup vs baseline: 4.0760x; 1.1181x over previous
#include <cuda_runtime.h>
#include <cuda_bf16.h>
#include <cuda_fp16.h>
#include <cstdint>

#define LSEQ 2048
#define BATCH 2
#define NH 12
#define FEATD 16
#define HD 64
#define DM 768
#define QKS 384             // combined Q|K projection width
#define ROWS (BATCH * LSEQ) // 4096
#define AKT 64              // attention key tile

// Scratch (no cudaMalloc allowed)
__device__ __nv_bfloat16 g_Xh[ROWS * DM];   // X split; later reused as Y split
__device__ __nv_bfloat16 g_Xl[ROWS * DM];
__device__ __nv_bfloat16 g_Wh[DM * DM];
__device__ __nv_bfloat16 g_Wl[DM * DM];
__device__ __nv_bfloat16 g_QKh[ROWS * QKS];
__device__ __nv_bfloat16 g_QKl[ROWS * QKS];
__device__ __half g_Vh[ROWS * DM];          // V split in fp16 (hi/lo)
__device__ __half g_Vl[ROWS * DM];

// ---- helpers ----
__device__ __forceinline__ uint32_t smem_u32(const void* p) {
    uint32_t a;
    asm("{ .reg .u64 t; cvta.to.shared.u64 t, %1; cvt.u32.u64 %0, t; }" : "=r"(a) : "l"(p));
    return a;
}
__device__ __forceinline__ uint32_t sw128(uint32_t o) { return o ^ ((o >> 3) & 0x70); }
__device__ __forceinline__ void ldsm_x4(uint32_t* r, uint32_t addr) {
    asm volatile("ldmatrix.sync.aligned.m8n8.x4.shared.b16 {%0,%1,%2,%3}, [%4];"
                 : "=r"(r[0]), "=r"(r[1]), "=r"(r[2]), "=r"(r[3]) : "r"(addr));
}
__device__ __forceinline__ void ldsm_x4t(uint32_t* r, uint32_t addr) {
    asm volatile("ldmatrix.sync.aligned.m8n8.x4.trans.shared.b16 {%0,%1,%2,%3}, [%4];"
                 : "=r"(r[0]), "=r"(r[1]), "=r"(r[2]), "=r"(r[3]) : "r"(addr));
}
__device__ __forceinline__ void mma_bf16(float* d, const uint32_t* a, uint32_t b0, uint32_t b1) {
    asm volatile(
        "mma.sync.aligned.m16n8k16.row.col.f32.bf16.bf16.f32 "
        "{%0,%1,%2,%3}, {%4,%5,%6,%7}, {%8,%9}, {%0,%1,%2,%3};"
        : "+f"(d[0]), "+f"(d[1]), "+f"(d[2]), "+f"(d[3])
        : "r"(a[0]), "r"(a[1]), "r"(a[2]), "r"(a[3]), "r"(b0), "r"(b1));
}
__device__ __forceinline__ void mma_f16(float* d, const uint32_t* a, uint32_t b0, uint32_t b1) {
    asm volatile(
        "mma.sync.aligned.m16n8k16.row.col.f32.f16.f16.f32 "
        "{%0,%1,%2,%3}, {%4,%5,%6,%7}, {%8,%9}, {%0,%1,%2,%3};"
        : "+f"(d[0]), "+f"(d[1]), "+f"(d[2]), "+f"(d[3])
        : "r"(a[0]), "r"(a[1]), "r"(a[2]), "r"(a[3]), "r"(b0), "r"(b1));
}
__device__ __forceinline__ void cp16(uint32_t dst, const void* src) {
    asm volatile("cp.async.cg.shared.global [%0], [%1], 16;" :: "r"(dst), "l"(src));
}
__device__ __forceinline__ void cp_commit() { asm volatile("cp.async.commit_group;" ::: "memory"); }
template <int N> __device__ __forceinline__ void cp_wait() {
    asm volatile("cp.async.wait_group %0;" :: "n"(N) : "memory");
}
// pack two f32 -> f16x2 (lo = first arg)
__device__ __forceinline__ uint32_t cvt2h(float lo, float hi) {
    uint32_t r; asm("cvt.rn.f16x2.f32 %0, %1, %2;" : "=r"(r) : "f"(hi), "f"(lo)); return r;
}
__device__ __forceinline__ float poly(float s) {
    return fmaf(s, fmaf(s, 0.03125f, 0.25f), 1.0f);
}

// ---------------------------------------------------------------------------
// Split fp32 -> bf16 hi/lo
// ---------------------------------------------------------------------------
__global__ void __launch_bounds__(256) convert_split(
    const float* __restrict__ x, __nv_bfloat16* __restrict__ xh,
    __nv_bfloat16* __restrict__ xl)
{
    int i = (blockIdx.x * 256 + threadIdx.x) * 4;
    float4 v = *(const float4*)&x[i];
    __nv_bfloat16 h0 = __float2bfloat16(v.x);
    __nv_bfloat16 h1 = __float2bfloat16(v.y);
    __nv_bfloat16 h2 = __float2bfloat16(v.z);
    __nv_bfloat16 h3 = __float2bfloat16(v.w);
    __nv_bfloat16 l0 = __float2bfloat16(v.x - __bfloat162float(h0));
    __nv_bfloat16 l1 = __float2bfloat16(v.y - __bfloat162float(h1));
    __nv_bfloat16 l2 = __float2bfloat16(v.z - __bfloat162float(h2));
    __nv_bfloat16 l3 = __float2bfloat16(v.w - __bfloat162float(h3));
    ((__nv_bfloat162*)(xh + i))[0] = __nv_bfloat162(h0, h1);
    ((__nv_bfloat162*)(xh + i))[1] = __nv_bfloat162(h2, h3);
    ((__nv_bfloat162*)(xl + i))[0] = __nv_bfloat162(l0, l1);
    ((__nv_bfloat162*)(xl + i))[1] = __nv_bfloat162(l2, l3);
}

// ---------------------------------------------------------------------------
// HMMA split-bf16 3-pass GEMM: C[M,N] = X[M,768] @ W[N,768]^T
// MODE 0: fp32 output C. MODE 1: split bf16 outputs. MODE 2: split fp16 outputs.
// ---------------------------------------------------------------------------
#define STG 65536
#define OFF_AH 0
#define OFF_AL 16384
#define OFF_BH 32768
#define OFF_BL 49152

template <int MODE>
__global__ void __launch_bounds__(256, 1) mma_gemm(
    const __nv_bfloat16* __restrict__ Xh, const __nv_bfloat16* __restrict__ Xl,
    const __nv_bfloat16* __restrict__ Wh, const __nv_bfloat16* __restrict__ Wl,
    float* __restrict__ C, void* __restrict__ Chv,
    void* __restrict__ Clv, int N)
{
    extern __shared__ char smem[];
    const uint32_t sb = smem_u32(smem);
    const int tid = threadIdx.x;
    const int wid = tid >> 5;
    const int lane = tid & 31;
    const int warpRow = wid >> 1;
    const int warpCol = wid & 1;
    const int m0 = blockIdx.y * 128;
    const int n0 = blockIdx.x * 128;

    int ur[4], uc[4]; uint32_t usw[4];
#pragma unroll
    for (int t = 0; t < 4; t++) {
        int u = tid + t * 256;
        ur[t] = u >> 3;
        uc[t] = (u & 7) * 16;
        usw[t] = sw128((uint32_t)(ur[t] * 128 + uc[t]));
    }

    const int lrow8 = ((lane >> 3) & 1) * 8 + (lane & 7);
    const int klane = ((lane >> 4) & 1) * 16;
    const int a_row = warpRow * 32 + lrow8;
    const int b_row = warpCol * 64 + lrow8;

    float acc[2][8][4];
#pragma unroll
    for (int mt = 0; mt < 2; mt++)
#pragma unroll
        for (int nt = 0; nt < 8; nt++)
#pragma unroll
            for (int j = 0; j < 4; j++) acc[mt][nt][j] = 0.f;

    const int NCH = DM / 64;
    {
        uint32_t s0 = sb;
#pragma unroll
        for (int t = 0; t < 4; t++) {
            size_t xo = (size_t)(m0 + ur[t]) * DM + (uc[t] >> 1);
            size_t wo = (size_t)(n0 + ur[t]) * DM + (uc[t] >> 1);
            cp16(s0 + OFF_AH + usw[t], Xh + xo);
            cp16(s0 + OFF_AL + usw[t], Xl + xo);
            cp16(s0 + OFF_BH + usw[t], Wh + wo);
            cp16(s0 + OFF_BL + usw[t], Wl + wo);
        }
        cp_commit();
    }

    for (int c = 0; c < NCH; c++) {
        if (c + 1 < NCH) {
            uint32_t s1 = sb + ((c + 1) & 1) * STG;
            int k0 = (c + 1) * 64;
#pragma unroll
            for (int t = 0; t < 4; t++) {
                size_t xo = (size_t)(m0 + ur[t]) * DM + k0 + (uc[t] >> 1);
                size_t wo = (size_t)(n0 + ur[t]) * DM + k0 + (uc[t] >> 1);
                cp16(s1 + OFF_AH + usw[t], Xh + xo);
                cp16(s1 + OFF_AL + usw[t], Xl + xo);
                cp16(s1 + OFF_BH + usw[t], Wh + wo);
                cp16(s1 + OFF_BL + usw[t], Wl + wo);
            }
            cp_commit();
            cp_wait<1>();
        } else {
            cp_wait<0>();
        }
        __syncthreads();

        const uint32_t sc = sb + (c & 1) * STG;
#pragma unroll
        for (int kt = 0; kt < 4; kt++) {
            const uint32_t kb = kt * 32 + klane;
            uint32_t ah[2][4], al[2][4], bh[4][4], bl[4][4];
#pragma unroll
            for (int mt = 0; mt < 2; mt++) {
                uint32_t off = sw128((uint32_t)((a_row + mt * 16) * 128 + kb));
                ldsm_x4(ah[mt], sc + OFF_AH + off);
                ldsm_x4(al[mt], sc + OFF_AL + off);
            }
#pragma unroll
            for (int nt2 = 0; nt2 < 4; nt2++) {
                uint32_t off = sw128((uint32_t)((b_row + nt2 * 16) * 128 + kb));
                ldsm_x4(bh[nt2], sc + OFF_BH + off);
                ldsm_x4(bl[nt2], sc + OFF_BL + off);
            }
#pragma unroll
            for (int mt = 0; mt < 2; mt++)
#pragma unroll
                for (int nt = 0; nt < 8; nt++) {
                    int p = nt >> 1, j = nt & 1;
                    mma_bf16(acc[mt][nt], ah[mt], bh[p][j], bh[p][2 + j]);
                    mma_bf16(acc[mt][nt], ah[mt], bl[p][j], bl[p][2 + j]);
                    mma_bf16(acc[mt][nt], al[mt], bh[p][j], bh[p][2 + j]);
                }
        }
        __syncthreads();
    }

    const int g = lane >> 2;
    const int tc = (lane & 3) * 2;
#pragma unroll
    for (int mt = 0; mt < 2; mt++) {
        int row = m0 + warpRow * 32 + mt * 16 + g;
#pragma unroll
        for (int nt = 0; nt < 8; nt++) {
            int col = n0 + warpCol * 64 + nt * 8 + tc;
            if (MODE == 0) {
                *(float2*)&C[(size_t)row * N + col] =
                    make_float2(acc[mt][nt][0], acc[mt][nt][1]);
                *(float2*)&C[(size_t)(row + 8) * N + col] =
                    make_float2(acc[mt][nt][2], acc[mt][nt][3]);
            } else if (MODE == 1) {
                __nv_bfloat16* Ch = (__nv_bfloat16*)Chv;
                __nv_bfloat16* Cl = (__nv_bfloat16*)Clv;
                float v0 = acc[mt][nt][0], v1 = acc[mt][nt][1];
                float v2 = acc[mt][nt][2], v3 = acc[mt][nt][3];
                __nv_bfloat16 h0 = __float2bfloat16(v0), h1 = __float2bfloat16(v1);
                __nv_bfloat16 h2 = __float2bfloat16(v2), h3 = __float2bfloat16(v3);
                __nv_bfloat16 l0 = __float2bfloat16(v0 - __bfloat162float(h0));
                __nv_bfloat16 l1 = __float2bfloat16(v1 - __bfloat162float(h1));
                __nv_bfloat16 l2 = __float2bfloat16(v2 - __bfloat162float(h2));
                __nv_bfloat16 l3 = __float2bfloat16(v3 - __bfloat162float(h3));
                *(__nv_bfloat162*)&Ch[(size_t)row * N + col] = __nv_bfloat162(h0, h1);
                *(__nv_bfloat162*)&Cl[(size_t)row * N + col] = __nv_bfloat162(l0, l1);
                *(__nv_bfloat162*)&Ch[(size_t)(row + 8) * N + col] = __nv_bfloat162(h2, h3);
                *(__nv_bfloat162*)&Cl[(size_t)(row + 8) * N + col] = __nv_bfloat162(l2, l3);
            } else {
                __half* Ch = (__half*)Chv;
                __half* Cl = (__half*)Clv;
                float v0 = acc[mt][nt][0], v1 = acc[mt][nt][1];
                float v2 = acc[mt][nt][2], v3 = acc[mt][nt][3];
                __half h0 = __float2half_rn(v0), h1 = __float2half_rn(v1);
                __half h2 = __float2half_rn(v2), h3 = __float2half_rn(v3);
                __half l0 = __float2half_rn(v0 - __half2float(h0));
                __half l1 = __float2half_rn(v1 - __half2float(h1));
                __half l2 = __float2half_rn(v2 - __half2float(h2));
                __half l3 = __float2half_rn(v3 - __half2float(h3));
                *(__half2*)&Ch[(size_t)row * N + col] = __half2(h0, h1);
                *(__half2*)&Cl[(size_t)row * N + col] = __half2(l0, l1);
                *(__half2*)&Ch[(size_t)(row + 8) * N + col] = __half2(h2, h3);
                *(__half2*)&Cl[(size_t)(row + 8) * N + col] = __half2(l2, l3);
            }
        }
    }
}

// ---------------------------------------------------------------------------
// HMMA attention.
// S = Q K^T (3-pass split bf16), A = poly(s)*(2 if causal) -> fp16,
// z = rowsum(A) fp32, Y += A V (fp16 2-pass: Af Vh + Af Vl, V fp16-split).
// Outputs Y as split bf16 (Yh, Yl).
// ---------------------------------------------------------------------------
#define AQ_OFF 0                     // Qh @0, Ql @6144  (128 rows * 48B)
#define AK_OFF 12288                 // + st*6144 + split*3072 (64 rows * 48B)
#define AV_OFF 24576                 // + st*16384 + split*8192 (64 rows * 128B, SW128)
#define ASM_TOTAL 57344

__device__ __forceinline__ void attn_load_tile(
    uint32_t sb, int st, int m0, int tid,
    const __nv_bfloat16* QKh, const __nv_bfloat16* QKl,
    const __half* Vh, const __half* Vl,
    size_t rowbase, int h)
{
    {
        int r = (tid & 127) >> 1, half = tid & 1;
        const __nv_bfloat16* src = ((tid < 128) ? QKh : QKl)
            + (rowbase + m0 + r) * QKS + 192 + h * FEATD + half * 8;
        cp16(sb + AK_OFF + st * 6144 + ((tid < 128) ? 0 : 3072) + r * 48 + half * 16, src);
    }
#pragma unroll
    for (int i = 0; i < 4; i++) {
        int u = tid + i * 256;
        int split = u >> 9, u2 = u & 511;
        int r = u2 >> 3, ch = (u2 & 7) * 16;
        const __half* src = (split ? Vl : Vh)
            + (rowbase + m0 + r) * DM + h * HD + (ch >> 1);
        cp16(sb + AV_OFF + st * 16384 + split * 8192 + sw128((uint32_t)(r * 128 + ch)), src);
    }
}

__global__ void __launch_bounds__(256, 2) attn_mma(
    const __nv_bfloat16* __restrict__ QKh, const __nv_bfloat16* __restrict__ QKl,
    const __half* __restrict__ Vh,  const __half* __restrict__ Vl,
    __nv_bfloat16* __restrict__ Yh, __nv_bfloat16* __restrict__ Yl)
{
    extern __shared__ char smem[];
    const uint32_t sb = smem_u32(smem);
    const int tid = threadIdx.x;
    const int wid = tid >> 5;
    const int lane = tid & 31;
    const int qb0 = blockIdx.x * 128;
    const int h = blockIdx.y;
    const int b = blockIdx.z;
    const size_t rowbase = (size_t)b * LSEQ;

    // group 0: Q (both splits)
    {
        int r = tid >> 1, half = tid & 1;
        cp16(sb + AQ_OFF + r * 48 + half * 16,
             QKh + (rowbase + qb0 + r) * QKS + h * FEATD + half * 8);
        cp16(sb + AQ_OFF + 6144 + r * 48 + half * 16,
             QKl + (rowbase + qb0 + r) * QKS + h * FEATD + half * 8);
    }
    cp_commit();
    // group 1: tile 0
    attn_load_tile(sb, 0, 0, tid, QKh, QKl, Vh, Vl, rowbase, h);
    cp_commit();
    cp_wait<1>();           // Q ready
    __syncthreads();

    uint32_t qh[4], ql[4];
    {
        uint32_t off = (uint32_t)((wid * 16 + ((lane >> 3) & 1) * 8 + (lane & 7)) * 48
                                  + ((lane >> 4) & 1) * 16);
        ldsm_x4(qh, sb + AQ_OFF + off);
        ldsm_x4(ql, sb + AQ_OFF + 6144 + off);
    }

    float accY[8][4];
#pragma unroll
    for (int nt = 0; nt < 8; nt++)
#pragma unroll
        for (int j = 0; j < 4; j++) accY[nt][j] = 0.f;
    float z0 = 0.f, z1 = 0.f;
    const int qrow0 = qb0 + wid * 16 + (lane >> 2);   // global query of c0/c1 rows

    const int NT = LSEQ / AKT;   // 32 tiles
    for (int c = 0; c < NT; c++) {
        const int m0 = c * AKT;
        if (c + 1 < NT) {
            attn_load_tile(sb, (c + 1) & 1, m0 + AKT, tid, QKh, QKl, Vh, Vl, rowbase, h);
            cp_commit();
            cp_wait<1>();
        } else {
            cp_wait<0>();
        }
        __syncthreads();

        const uint32_t kb = sb + AK_OFF + (c & 1) * 6144;
        const uint32_t vb = sb + AV_OFF + (c & 1) * 16384;
        const int relq0 = qrow0 - m0;

#pragma unroll
        for (int s = 0; s < 4; s++) {
            // ---- S for keys 16s..16s+15 (2 n-tiles) ----
            uint32_t koff = (uint32_t)((16 * s + ((lane >> 4) & 1) * 8 + (lane & 7)) * 48
                                       + ((lane >> 3) & 1) * 16);
            uint32_t bh[4], bl[4];
            ldsm_x4(bh, kb + koff);
            ldsm_x4(bl, kb + 3072 + koff);
            float s0[4] = {0.f, 0.f, 0.f, 0.f};
            float s1[4] = {0.f, 0.f, 0.f, 0.f};
            mma_bf16(s0, qh, bh[0], bh[1]);
            mma_bf16(s0, qh, bl[0], bl[1]);
            mma_bf16(s0, ql, bh[0], bh[1]);
            mma_bf16(s1, qh, bh[2], bh[3]);
            mma_bf16(s1, qh, bl[2], bl[3]);
            mma_bf16(s1, ql, bh[2], bh[3]);

            // ---- poly + causal + z + pack A to fp16 a-frags ----
            uint32_t af[4];
            {
                const int key0 = 16 * s + (lane & 3) * 2;
                const int key8 = key0 + 8;
                float a0 = poly(s0[0]); if (key0     <= relq0)     a0 += a0;
                float a1 = poly(s0[1]); if (key0 + 1 <= relq0)     a1 += a1;
                float a2 = poly(s0[2]); if (key0     <= relq0 + 8) a2 += a2;
                float a3 = poly(s0[3]); if (key0 + 1 <= relq0 + 8) a3 += a3;
                float b0 = poly(s1[0]); if (key8     <= relq0)     b0 += b0;
                float b1 = poly(s1[1]); if (key8 + 1 <= relq0)     b1 += b1;
                float b2 = poly(s1[2]); if (key8     <= relq0 + 8) b2 += b2;
                float b3 = poly(s1[3]); if (key8 + 1 <= relq0 + 8) b3 += b3;
                z0 += (a0 + a1) + (b0 + b1);
                z1 += (a2 + a3) + (b2 + b3);
                af[0] = cvt2h(a0, a1);
                af[1] = cvt2h(a2, a3);
                af[2] = cvt2h(b0, b1);
                af[3] = cvt2h(b2, b3);
            }

            // ---- Y += A V for this k16 step (fp16 2-pass) ----
#pragma unroll
            for (int g4 = 0; g4 < 4; g4++) {
                uint32_t voff = sw128((uint32_t)((16 * s + ((lane >> 3) & 1) * 8 + (lane & 7)) * 128
                                                 + 32 * g4 + ((lane >> 4) & 1) * 16));
                uint32_t vhf[4], vlf[4];
                ldsm_x4t(vhf, vb + voff);
                ldsm_x4t(vlf, vb + 8192 + voff);
                mma_f16(accY[2 * g4],     af, vhf[0], vhf[1]);
                mma_f16(accY[2 * g4],     af, vlf[0], vlf[1]);
                mma_f16(accY[2 * g4 + 1], af, vhf[2], vhf[3]);
                mma_f16(accY[2 * g4 + 1], af, vlf[2], vlf[3]);
            }
        }
        __syncthreads();
    }

    // z reduction across the lane quad (lanes sharing a row)
    z0 += __shfl_xor_sync(0xFFFFFFFFu, z0, 1);
    z0 += __shfl_xor_sync(0xFFFFFFFFu, z0, 2);
    z1 += __shfl_xor_sync(0xFFFFFFFFu, z1, 1);
    z1 += __shfl_xor_sync(0xFFFFFFFFu, z1, 2);
    const float inv0 = 1.f / z0, inv1 = 1.f / z1;

    const size_t r0g = rowbase + qb0 + wid * 16 + (lane >> 2);
    const int colb = h * HD + (lane & 3) * 2;
#pragma unroll
    for (int nt = 0; nt < 8; nt++) {
        float y0 = accY[nt][0] * inv0, y1 = accY[nt][1] * inv0;
        float y2 = accY[nt][2] * inv1, y3 = accY[nt][3] * inv1;
        __nv_bfloat16 h0 = __float2bfloat16(y0), h1 = __float2bfloat16(y1);
        __nv_bfloat16 h2 = __float2bfloat16(y2), h3 = __float2bfloat16(y3);
        __nv_bfloat16 l0 = __float2bfloat16(y0 - __bfloat162float(h0));
        __nv_bfloat16 l1 = __float2bfloat16(y1 - __bfloat162float(h1));
        __nv_bfloat16 l2 = __float2bfloat16(y2 - __bfloat162float(h2));
        __nv_bfloat16 l3 = __float2bfloat16(y3 - __bfloat162float(h3));
        size_t o0 = r0g * DM + colb + nt * 8;
        size_t o1 = (r0g + 8) * DM + colb + nt * 8;
        *(__nv_bfloat162*)&Yh[o0] = __nv_bfloat162(h0, h1);
        *(__nv_bfloat162*)&Yl[o0] = __nv_bfloat162(l0, l1);
        *(__nv_bfloat162*)&Yh[o1] = __nv_bfloat162(h2, h3);
        *(__nv_bfloat162*)&Yl[o1] = __nv_bfloat162(l2, l3);
    }
}

// ---------------------------------------------------------------------------
extern "C" void kernel_launch(void* const* d_in, const int* in_sizes, int n_in,
                              void* d_out, int out_size)
{
    const float* hs = (const float*)d_in[0];
    const float* Wq = (const float*)d_in[1];
    const float* Wk = (const float*)d_in[2];
    const float* Wv = (const float*)d_in[3];
    const float* Wo = (const float*)d_in[4];
    float* out = (float*)d_out;

    __nv_bfloat16 *Xh, *Xl, *Wh, *Wl, *QKh, *QKl;
    __half *Vh, *Vl;
    cudaGetSymbolAddress((void**)&Xh, g_Xh);
    cudaGetSymbolAddress((void**)&Xl, g_Xl);
    cudaGetSymbolAddress((void**)&Wh, g_Wh);
    cudaGetSymbolAddress((void**)&Wl, g_Wl);
    cudaGetSymbolAddress((void**)&QKh, g_QKh);
    cudaGetSymbolAddress((void**)&QKl, g_QKl);
    cudaGetSymbolAddress((void**)&Vh, g_Vh);
    cudaGetSymbolAddress((void**)&Vl, g_Vl);

    cudaFuncSetAttribute(mma_gemm<0>, cudaFuncAttributeMaxDynamicSharedMemorySize, 2 * STG);
    cudaFuncSetAttribute(mma_gemm<1>, cudaFuncAttributeMaxDynamicSharedMemorySize, 2 * STG);
    cudaFuncSetAttribute(mma_gemm<2>, cudaFuncAttributeMaxDynamicSharedMemorySize, 2 * STG);
    cudaFuncSetAttribute(attn_mma, cudaFuncAttributeMaxDynamicSharedMemorySize, ASM_TOTAL);

    // Split inputs
    convert_split<<<(ROWS * DM) / 1024, 256>>>(hs, Xh, Xl);
    convert_split<<<(192 * DM) / 1024, 256>>>(Wq, Wh, Wl);
    convert_split<<<(192 * DM) / 1024, 256>>>(Wk, Wh + 192 * DM, Wl + 192 * DM);

    // QK projection -> split bf16
    {
        dim3 g(QKS / 128, ROWS / 128);
        mma_gemm<1><<<g, 256, 2 * STG>>>(Xh, Xl, Wh, Wl, nullptr, QKh, QKl, QKS);
    }
    // V projection -> split fp16
    convert_split<<<(DM * DM) / 1024, 256>>>(Wv, Wh, Wl);
    {
        dim3 g(DM / 128, ROWS / 128);
        mma_gemm<2><<<g, 256, 2 * STG>>>(Xh, Xl, Wh, Wl, nullptr, Vh, Vl, DM);
    }

    // Attention -> Y split (reuses Xh/Xl, X no longer needed)
    {
        dim3 ga(LSEQ / 128, NH, BATCH);
        attn_mma<<<ga, 256, ASM_TOTAL>>>(QKh, QKl, Vh, Vl, Xh, Xl);
    }

    // Output projection -> fp32 out
    convert_split<<<(DM * DM) / 1024, 256>>>(Wo, Wh, Wl);
    {
        dim3 g(DM / 128, ROWS / 128);
        mma_gemm<0><<<g, 256, 2 * STG>>>(Xh, Xl, Wh, Wl, out, nullptr, nullptr, DM);
    }
}

// round 9
// speedup vs baseline: 5.3970x; 1.3241x over previous
#include <cuda_runtime.h>
#include <cuda_bf16.h>
#include <cuda_fp16.h>
#include <cstdint>

#define LSEQ 2048
#define BATCH 2
#define NH 12
#define FEATD 16
#define HD 64
#define DM 768
#define QKS 384             // combined Q|K width
#define NPROJ 1152          // merged Q|K|V projection width
#define ROWS (BATCH * LSEQ) // 4096
#define AKT 64              // attention key tile

// Scratch (no cudaMalloc allowed)
__device__ __nv_bfloat16 g_Xh[ROWS * DM];    // X split; later reused as Y split
__device__ __nv_bfloat16 g_Xl[ROWS * DM];
__device__ __nv_bfloat16 g_Wh[NPROJ * DM];   // merged weights (also holds Wo)
__device__ __nv_bfloat16 g_Wl[NPROJ * DM];
__device__ __half g_QKf[ROWS * QKS];         // Q|K single fp16
__device__ __half g_Vh[ROWS * DM];           // V split fp16
__device__ __half g_Vl[ROWS * DM];

// ---- helpers ----
__device__ __forceinline__ uint32_t smem_u32(const void* p) {
    uint32_t a;
    asm("{ .reg .u64 t; cvta.to.shared.u64 t, %1; cvt.u32.u64 %0, t; }" : "=r"(a) : "l"(p));
    return a;
}
__device__ __forceinline__ uint32_t sw128(uint32_t o) { return o ^ ((o >> 3) & 0x70); }
__device__ __forceinline__ void ldsm_x4(uint32_t* r, uint32_t addr) {
    asm volatile("ldmatrix.sync.aligned.m8n8.x4.shared.b16 {%0,%1,%2,%3}, [%4];"
                 : "=r"(r[0]), "=r"(r[1]), "=r"(r[2]), "=r"(r[3]) : "r"(addr));
}
__device__ __forceinline__ void ldsm_x4t(uint32_t* r, uint32_t addr) {
    asm volatile("ldmatrix.sync.aligned.m8n8.x4.trans.shared.b16 {%0,%1,%2,%3}, [%4];"
                 : "=r"(r[0]), "=r"(r[1]), "=r"(r[2]), "=r"(r[3]) : "r"(addr));
}
__device__ __forceinline__ void mma_bf16(float* d, const uint32_t* a, uint32_t b0, uint32_t b1) {
    asm volatile(
        "mma.sync.aligned.m16n8k16.row.col.f32.bf16.bf16.f32 "
        "{%0,%1,%2,%3}, {%4,%5,%6,%7}, {%8,%9}, {%0,%1,%2,%3};"
        : "+f"(d[0]), "+f"(d[1]), "+f"(d[2]), "+f"(d[3])
        : "r"(a[0]), "r"(a[1]), "r"(a[2]), "r"(a[3]), "r"(b0), "r"(b1));
}
__device__ __forceinline__ void mma_f16(float* d, const uint32_t* a, uint32_t b0, uint32_t b1) {
    asm volatile(
        "mma.sync.aligned.m16n8k16.row.col.f32.f16.f16.f32 "
        "{%0,%1,%2,%3}, {%4,%5,%6,%7}, {%8,%9}, {%0,%1,%2,%3};"
        : "+f"(d[0]), "+f"(d[1]), "+f"(d[2]), "+f"(d[3])
        : "r"(a[0]), "r"(a[1]), "r"(a[2]), "r"(a[3]), "r"(b0), "r"(b1));
}
__device__ __forceinline__ void cp16(uint32_t dst, const void* src) {
    asm volatile("cp.async.cg.shared.global [%0], [%1], 16;" :: "r"(dst), "l"(src));
}
__device__ __forceinline__ void cp_commit() { asm volatile("cp.async.commit_group;" ::: "memory"); }
template <int N> __device__ __forceinline__ void cp_wait() {
    asm volatile("cp.async.wait_group %0;" :: "n"(N) : "memory");
}
// pack two f32 -> f16x2 (lo = first arg)
__device__ __forceinline__ uint32_t cvt2h(float lo, float hi) {
    uint32_t r; asm("cvt.rn.f16x2.f32 %0, %1, %2;" : "=r"(r) : "f"(hi), "f"(lo)); return r;
}
__device__ __forceinline__ float poly(float s) {
    return fmaf(s, fmaf(s, 0.03125f, 0.25f), 1.0f);
}

// ---------------------------------------------------------------------------
// Split fp32 -> bf16 hi/lo
// ---------------------------------------------------------------------------
__global__ void __launch_bounds__(256) convert_split(
    const float* __restrict__ x, __nv_bfloat16* __restrict__ xh,
    __nv_bfloat16* __restrict__ xl)
{
    int i = (blockIdx.x * 256 + threadIdx.x) * 4;
    float4 v = *(const float4*)&x[i];
    __nv_bfloat16 h0 = __float2bfloat16(v.x);
    __nv_bfloat16 h1 = __float2bfloat16(v.y);
    __nv_bfloat16 h2 = __float2bfloat16(v.z);
    __nv_bfloat16 h3 = __float2bfloat16(v.w);
    __nv_bfloat16 l0 = __float2bfloat16(v.x - __bfloat162float(h0));
    __nv_bfloat16 l1 = __float2bfloat16(v.y - __bfloat162float(h1));
    __nv_bfloat16 l2 = __float2bfloat16(v.z - __bfloat162float(h2));
    __nv_bfloat16 l3 = __float2bfloat16(v.w - __bfloat162float(h3));
    ((__nv_bfloat162*)(xh + i))[0] = __nv_bfloat162(h0, h1);
    ((__nv_bfloat162*)(xh + i))[1] = __nv_bfloat162(h2, h3);
    ((__nv_bfloat162*)(xl + i))[0] = __nv_bfloat162(l0, l1);
    ((__nv_bfloat162*)(xl + i))[1] = __nv_bfloat162(l2, l3);
}

// ---------------------------------------------------------------------------
// HMMA split-bf16 3-pass GEMM v2: CTA tile 128x64, warp tile 32x32, BK=64.
// 8 warps (4 rows x 2 cols), 2-stage cp.async, 2 CTAs/SM.
// MODE 0: fp32 C (N=768). MODE 1: merged proj (N=1152): cols<384 -> QKf fp16;
//         cols>=384 -> Vh/Vl fp16 split.
// ---------------------------------------------------------------------------
#define STG2 49152
#define OFF_AH 0
#define OFF_AL 16384
#define OFF_BH 32768
#define OFF_BL 40960

template <int MODE>
__global__ void __launch_bounds__(256, 2) mma_gemm(
    const __nv_bfloat16* __restrict__ Xh, const __nv_bfloat16* __restrict__ Xl,
    const __nv_bfloat16* __restrict__ Wh, const __nv_bfloat16* __restrict__ Wl,
    float* __restrict__ C, __half* __restrict__ QKf,
    __half* __restrict__ Vh, __half* __restrict__ Vl)
{
    extern __shared__ char smem[];
    const uint32_t sb = smem_u32(smem);
    const int tid = threadIdx.x;
    const int wid = tid >> 5;
    const int lane = tid & 31;
    const int warpRow = wid >> 1;   // 0..3 -> m*32
    const int warpCol = wid & 1;    // 0..1 -> n*32
    const int m0 = blockIdx.y * 128;
    const int n0 = blockIdx.x * 64;

    const int lrow8 = ((lane >> 3) & 1) * 8 + (lane & 7);
    const int klane = ((lane >> 4) & 1) * 16;
    const int a_row = warpRow * 32 + lrow8;
    const int b_row = warpCol * 32 + lrow8;

    float acc[2][4][4];
#pragma unroll
    for (int mt = 0; mt < 2; mt++)
#pragma unroll
        for (int nt = 0; nt < 4; nt++)
#pragma unroll
            for (int j = 0; j < 4; j++) acc[mt][nt][j] = 0.f;

    const int NCH = DM / 64;   // 12

    // prologue loads (chunk 0)
    {
        uint32_t s0 = sb;
#pragma unroll
        for (int t = 0; t < 4; t++) {
            int u = tid + t * 256;
            int r = u >> 3, cb = (u & 7) * 16;
            uint32_t sw = sw128((uint32_t)(r * 128 + cb));
            size_t xo = (size_t)(m0 + r) * DM + (cb >> 1);
            cp16(s0 + OFF_AH + sw, Xh + xo);
            cp16(s0 + OFF_AL + sw, Xl + xo);
        }
#pragma unroll
        for (int t = 0; t < 2; t++) {
            int u = tid + t * 256;
            int r = u >> 3, cb = (u & 7) * 16;
            uint32_t sw = sw128((uint32_t)(r * 128 + cb));
            size_t wo = (size_t)(n0 + r) * DM + (cb >> 1);
            cp16(s0 + OFF_BH + sw, Wh + wo);
            cp16(s0 + OFF_BL + sw, Wl + wo);
        }
        cp_commit();
    }

    for (int c = 0; c < NCH; c++) {
        if (c + 1 < NCH) {
            uint32_t s1 = sb + ((c + 1) & 1) * STG2;
            int k0 = (c + 1) * 64;
#pragma unroll
            for (int t = 0; t < 4; t++) {
                int u = tid + t * 256;
                int r = u >> 3, cb = (u & 7) * 16;
                uint32_t sw = sw128((uint32_t)(r * 128 + cb));
                size_t xo = (size_t)(m0 + r) * DM + k0 + (cb >> 1);
                cp16(s1 + OFF_AH + sw, Xh + xo);
                cp16(s1 + OFF_AL + sw, Xl + xo);
            }
#pragma unroll
            for (int t = 0; t < 2; t++) {
                int u = tid + t * 256;
                int r = u >> 3, cb = (u & 7) * 16;
                uint32_t sw = sw128((uint32_t)(r * 128 + cb));
                size_t wo = (size_t)(n0 + r) * DM + k0 + (cb >> 1);
                cp16(s1 + OFF_BH + sw, Wh + wo);
                cp16(s1 + OFF_BL + sw, Wl + wo);
            }
            cp_commit();
            cp_wait<1>();
        } else {
            cp_wait<0>();
        }
        __syncthreads();

        const uint32_t sc = sb + (c & 1) * STG2;
#pragma unroll
        for (int kt = 0; kt < 4; kt++) {
            const uint32_t kb = kt * 32 + klane;
            uint32_t ah[2][4], al[2][4], bh[2][4], bl[2][4];
#pragma unroll
            for (int mt = 0; mt < 2; mt++) {
                uint32_t off = sw128((uint32_t)((a_row + mt * 16) * 128 + kb));
                ldsm_x4(ah[mt], sc + OFF_AH + off);
                ldsm_x4(al[mt], sc + OFF_AL + off);
            }
#pragma unroll
            for (int nt2 = 0; nt2 < 2; nt2++) {
                uint32_t off = sw128((uint32_t)((b_row + nt2 * 16) * 128 + kb));
                ldsm_x4(bh[nt2], sc + OFF_BH + off);
                ldsm_x4(bl[nt2], sc + OFF_BL + off);
            }
#pragma unroll
            for (int mt = 0; mt < 2; mt++)
#pragma unroll
                for (int nt = 0; nt < 4; nt++) {
                    int p = nt >> 1, j = nt & 1;
                    mma_bf16(acc[mt][nt], ah[mt], bh[p][j], bh[p][2 + j]);
                    mma_bf16(acc[mt][nt], ah[mt], bl[p][j], bl[p][2 + j]);
                    mma_bf16(acc[mt][nt], al[mt], bh[p][j], bh[p][2 + j]);
                }
        }
        __syncthreads();
    }

    const int g = lane >> 2;
    const int tc = (lane & 3) * 2;
#pragma unroll
    for (int mt = 0; mt < 2; mt++) {
        int row = m0 + warpRow * 32 + mt * 16 + g;
#pragma unroll
        for (int nt = 0; nt < 4; nt++) {
            int col = n0 + warpCol * 32 + nt * 8 + tc;
            float v0 = acc[mt][nt][0], v1 = acc[mt][nt][1];
            float v2 = acc[mt][nt][2], v3 = acc[mt][nt][3];
            if (MODE == 0) {
                *(float2*)&C[(size_t)row * DM + col] = make_float2(v0, v1);
                *(float2*)&C[(size_t)(row + 8) * DM + col] = make_float2(v2, v3);
            } else {
                if (n0 < QKS) {
                    // QK -> single fp16
                    *(uint32_t*)&QKf[(size_t)row * QKS + col] = cvt2h(v0, v1);
                    *(uint32_t*)&QKf[(size_t)(row + 8) * QKS + col] = cvt2h(v2, v3);
                } else {
                    int c2 = col - QKS;
                    __half h0 = __float2half_rn(v0), h1 = __float2half_rn(v1);
                    __half h2 = __float2half_rn(v2), h3 = __float2half_rn(v3);
                    __half l0 = __float2half_rn(v0 - __half2float(h0));
                    __half l1 = __float2half_rn(v1 - __half2float(h1));
                    __half l2 = __float2half_rn(v2 - __half2float(h2));
                    __half l3 = __float2half_rn(v3 - __half2float(h3));
                    *(__half2*)&Vh[(size_t)row * DM + c2] = __half2(h0, h1);
                    *(__half2*)&Vl[(size_t)row * DM + c2] = __half2(l0, l1);
                    *(__half2*)&Vh[(size_t)(row + 8) * DM + c2] = __half2(h2, h3);
                    *(__half2*)&Vl[(size_t)(row + 8) * DM + c2] = __half2(l2, l3);
                }
            }
        }
    }
}

// ---------------------------------------------------------------------------
// HMMA attention.
// S = Q K^T fp16 single-pass; A = poly(s)*(2 if causal) -> fp16;
// z = rowsum(A) fp32; Y += A V (fp16 2-pass, V split). Output Y split bf16.
// ---------------------------------------------------------------------------
#define AQ_OFF 0                       // 128 rows * 48B = 6144
#define AK_OFF 6144                    // + st*3072 (64 rows * 48B)
#define AV_OFF 12288                   // + st*16384 + split*8192
#define ASM_TOTAL 45056

__device__ __forceinline__ void attn_load_tile(
    uint32_t sb, int st, int m0, int tid,
    const __half* QKf, const __half* Vh, const __half* Vl,
    size_t rowbase, int h)
{
    if (tid < 128) {
        int r = tid >> 1, half = tid & 1;
        const __half* src = QKf + (rowbase + m0 + r) * QKS + 192 + h * FEATD + half * 8;
        cp16(sb + AK_OFF + st * 3072 + r * 48 + half * 16, src);
    }
#pragma unroll
    for (int i = 0; i < 4; i++) {
        int u = tid + i * 256;
        int split = u >> 9, u2 = u & 511;
        int r = u2 >> 3, ch = (u2 & 7) * 16;
        const __half* src = (split ? Vl : Vh)
            + (rowbase + m0 + r) * DM + h * HD + (ch >> 1);
        cp16(sb + AV_OFF + st * 16384 + split * 8192 + sw128((uint32_t)(r * 128 + ch)), src);
    }
}

__global__ void __launch_bounds__(256, 2) attn_mma(
    const __half* __restrict__ QKf,
    const __half* __restrict__ Vh, const __half* __restrict__ Vl,
    __nv_bfloat16* __restrict__ Yh, __nv_bfloat16* __restrict__ Yl)
{
    extern __shared__ char smem[];
    const uint32_t sb = smem_u32(smem);
    const int tid = threadIdx.x;
    const int wid = tid >> 5;
    const int lane = tid & 31;
    const int qb0 = blockIdx.x * 128;
    const int h = blockIdx.y;
    const int b = blockIdx.z;
    const size_t rowbase = (size_t)b * LSEQ;

    // group 0: Q (fp16 single, 128 rows x 32B)
    {
        int r = tid >> 1, half = tid & 1;
        cp16(sb + AQ_OFF + r * 48 + half * 16,
             QKf + (rowbase + qb0 + r) * QKS + h * FEATD + half * 8);
    }
    cp_commit();
    // group 1: tile 0
    attn_load_tile(sb, 0, 0, tid, QKf, Vh, Vl, rowbase, h);
    cp_commit();
    cp_wait<1>();           // Q ready
    __syncthreads();

    uint32_t qf[4];
    {
        uint32_t off = (uint32_t)((wid * 16 + ((lane >> 3) & 1) * 8 + (lane & 7)) * 48
                                  + ((lane >> 4) & 1) * 16);
        ldsm_x4(qf, sb + AQ_OFF + off);
    }

    float accY[8][4];
#pragma unroll
    for (int nt = 0; nt < 8; nt++)
#pragma unroll
        for (int j = 0; j < 4; j++) accY[nt][j] = 0.f;
    float z0 = 0.f, z1 = 0.f;
    const int qrow0 = qb0 + wid * 16 + (lane >> 2);

    const int NT = LSEQ / AKT;   // 32
    for (int c = 0; c < NT; c++) {
        const int m0 = c * AKT;
        if (c + 1 < NT) {
            attn_load_tile(sb, (c + 1) & 1, m0 + AKT, tid, QKf, Vh, Vl, rowbase, h);
            cp_commit();
            cp_wait<1>();
        } else {
            cp_wait<0>();
        }
        __syncthreads();

        const uint32_t kb = sb + AK_OFF + (c & 1) * 3072;
        const uint32_t vb = sb + AV_OFF + (c & 1) * 16384;
        const int relq0 = qrow0 - m0;

#pragma unroll
        for (int s = 0; s < 4; s++) {
            // ---- S for keys 16s..16s+15 (single-pass fp16) ----
            uint32_t koff = (uint32_t)((16 * s + ((lane >> 4) & 1) * 8 + (lane & 7)) * 48
                                       + ((lane >> 3) & 1) * 16);
            uint32_t bf[4];
            ldsm_x4(bf, kb + koff);
            float s0[4] = {0.f, 0.f, 0.f, 0.f};
            float s1[4] = {0.f, 0.f, 0.f, 0.f};
            mma_f16(s0, qf, bf[0], bf[1]);
            mma_f16(s1, qf, bf[2], bf[3]);

            // ---- poly + causal + z + pack A to fp16 a-frags ----
            uint32_t af[4];
            {
                const int key0 = 16 * s + (lane & 3) * 2;
                const int key8 = key0 + 8;
                float a0 = poly(s0[0]); if (key0     <= relq0)     a0 += a0;
                float a1 = poly(s0[1]); if (key0 + 1 <= relq0)     a1 += a1;
                float a2 = poly(s0[2]); if (key0     <= relq0 + 8) a2 += a2;
                float a3 = poly(s0[3]); if (key0 + 1 <= relq0 + 8) a3 += a3;
                float b0 = poly(s1[0]); if (key8     <= relq0)     b0 += b0;
                float b1 = poly(s1[1]); if (key8 + 1 <= relq0)     b1 += b1;
                float b2 = poly(s1[2]); if (key8     <= relq0 + 8) b2 += b2;
                float b3 = poly(s1[3]); if (key8 + 1 <= relq0 + 8) b3 += b3;
                z0 += (a0 + a1) + (b0 + b1);
                z1 += (a2 + a3) + (b2 + b3);
                af[0] = cvt2h(a0, a1);
                af[1] = cvt2h(a2, a3);
                af[2] = cvt2h(b0, b1);
                af[3] = cvt2h(b2, b3);
            }

            // ---- Y += A V (fp16 2-pass) ----
#pragma unroll
            for (int g4 = 0; g4 < 4; g4++) {
                uint32_t voff = sw128((uint32_t)((16 * s + ((lane >> 3) & 1) * 8 + (lane & 7)) * 128
                                                 + 32 * g4 + ((lane >> 4) & 1) * 16));
                uint32_t vhf[4], vlf[4];
                ldsm_x4t(vhf, vb + voff);
                ldsm_x4t(vlf, vb + 8192 + voff);
                mma_f16(accY[2 * g4],     af, vhf[0], vhf[1]);
                mma_f16(accY[2 * g4],     af, vlf[0], vlf[1]);
                mma_f16(accY[2 * g4 + 1], af, vhf[2], vhf[3]);
                mma_f16(accY[2 * g4 + 1], af, vlf[2], vlf[3]);
            }
        }
        __syncthreads();
    }

    // z reduction across the lane quad
    z0 += __shfl_xor_sync(0xFFFFFFFFu, z0, 1);
    z0 += __shfl_xor_sync(0xFFFFFFFFu, z0, 2);
    z1 += __shfl_xor_sync(0xFFFFFFFFu, z1, 1);
    z1 += __shfl_xor_sync(0xFFFFFFFFu, z1, 2);
    const float inv0 = 1.f / z0, inv1 = 1.f / z1;

    const size_t r0g = rowbase + qb0 + wid * 16 + (lane >> 2);
    const int colb = h * HD + (lane & 3) * 2;
#pragma unroll
    for (int nt = 0; nt < 8; nt++) {
        float y0 = accY[nt][0] * inv0, y1 = accY[nt][1] * inv0;
        float y2 = accY[nt][2] * inv1, y3 = accY[nt][3] * inv1;
        __nv_bfloat16 h0 = __float2bfloat16(y0), h1 = __float2bfloat16(y1);
        __nv_bfloat16 h2 = __float2bfloat16(y2), h3 = __float2bfloat16(y3);
        __nv_bfloat16 l0 = __float2bfloat16(y0 - __bfloat162float(h0));
        __nv_bfloat16 l1 = __float2bfloat16(y1 - __bfloat162float(h1));
        __nv_bfloat16 l2 = __float2bfloat16(y2 - __bfloat162float(h2));
        __nv_bfloat16 l3 = __float2bfloat16(y3 - __bfloat162float(h3));
        size_t o0 = r0g * DM + colb + nt * 8;
        size_t o1 = (r0g + 8) * DM + colb + nt * 8;
        *(__nv_bfloat162*)&Yh[o0] = __nv_bfloat162(h0, h1);
        *(__nv_bfloat162*)&Yl[o0] = __nv_bfloat162(l0, l1);
        *(__nv_bfloat162*)&Yh[o1] = __nv_bfloat162(h2, h3);
        *(__nv_bfloat162*)&Yl[o1] = __nv_bfloat162(l2, l3);
    }
}

// ---------------------------------------------------------------------------
extern "C" void kernel_launch(void* const* d_in, const int* in_sizes, int n_in,
                              void* d_out, int out_size)
{
    const float* hs = (const float*)d_in[0];
    const float* Wq = (const float*)d_in[1];
    const float* Wk = (const float*)d_in[2];
    const float* Wv = (const float*)d_in[3];
    const float* Wo = (const float*)d_in[4];
    float* out = (float*)d_out;

    __nv_bfloat16 *Xh, *Xl, *Wh, *Wl;
    __half *QKf, *Vh, *Vl;
    cudaGetSymbolAddress((void**)&Xh, g_Xh);
    cudaGetSymbolAddress((void**)&Xl, g_Xl);
    cudaGetSymbolAddress((void**)&Wh, g_Wh);
    cudaGetSymbolAddress((void**)&Wl, g_Wl);
    cudaGetSymbolAddress((void**)&QKf, g_QKf);
    cudaGetSymbolAddress((void**)&Vh, g_Vh);
    cudaGetSymbolAddress((void**)&Vl, g_Vl);

    cudaFuncSetAttribute(mma_gemm<0>, cudaFuncAttributeMaxDynamicSharedMemorySize, 2 * STG2);
    cudaFuncSetAttribute(mma_gemm<1>, cudaFuncAttributeMaxDynamicSharedMemorySize, 2 * STG2);
    cudaFuncSetAttribute(attn_mma, cudaFuncAttributeMaxDynamicSharedMemorySize, ASM_TOTAL);

    // Split inputs: X, and merged weights Wq|Wk|Wv
    convert_split<<<(ROWS * DM) / 1024, 256>>>(hs, Xh, Xl);
    convert_split<<<(192 * DM) / 1024, 256>>>(Wq, Wh, Wl);
    convert_split<<<(192 * DM) / 1024, 256>>>(Wk, Wh + 192 * DM, Wl + 192 * DM);
    convert_split<<<(DM * DM) / 1024, 256>>>(Wv, Wh + QKS * DM, Wl + QKS * DM);

    // Merged projection: QK -> fp16 single, V -> fp16 split
    {
        dim3 g(NPROJ / 64, ROWS / 128);
        mma_gemm<1><<<g, 256, 2 * STG2>>>(Xh, Xl, Wh, Wl, nullptr, QKf, Vh, Vl);
    }

    // Attention -> Y split bf16 (reuses Xh/Xl)
    {
        dim3 ga(LSEQ / 128, NH, BATCH);
        attn_mma<<<ga, 256, ASM_TOTAL>>>(QKf, Vh, Vl, Xh, Xl);
    }

    // Output projection -> fp32 out
    convert_split<<<(DM * DM) / 1024, 256>>>(Wo, Wh, Wl);
    {
        dim3 g(DM / 64, ROWS / 128);
        mma_gemm<0><<<g, 256, 2 * STG2>>>(Xh, Xl, Wh, Wl, out, nullptr, nullptr, nullptr);
    }
}

// round 10
// speedup vs baseline: 7.0866x; 1.3131x over previous
#include <cuda_runtime.h>
#include <cuda_bf16.h>
#include <cuda_fp16.h>
#include <cstdint>

#define LSEQ 2048
#define BATCH 2
#define NH 12
#define FEATD 16
#define HD 64
#define DM 768
#define QKS 384             // combined Q|K width
#define NPROJ 1152          // merged Q|K|V projection width
#define ROWS (BATCH * LSEQ) // 4096
#define AKT 64              // attention key tile

// Scratch (no cudaMalloc allowed)
__device__ __nv_bfloat16 g_Xh[ROWS * DM];    // X split bf16
__device__ __nv_bfloat16 g_Xl[ROWS * DM];
__device__ __nv_bfloat16 g_Wh[NPROJ * DM];   // merged proj weights split bf16
__device__ __nv_bfloat16 g_Wl[NPROJ * DM];
__device__ __half g_QKf[ROWS * QKS];         // Q|K single fp16
__device__ __half g_Vf[ROWS * DM];           // V single fp16
__device__ __half g_Yf[ROWS * DM];           // Y single fp16
__device__ __half g_Woh[DM * DM];            // Wo split fp16
__device__ __half g_Wol[DM * DM];

// ---- helpers ----
__device__ __forceinline__ uint32_t smem_u32(const void* p) {
    uint32_t a;
    asm("{ .reg .u64 t; cvta.to.shared.u64 t, %1; cvt.u32.u64 %0, t; }" : "=r"(a) : "l"(p));
    return a;
}
__device__ __forceinline__ uint32_t sw128(uint32_t o) { return o ^ ((o >> 3) & 0x70); }
__device__ __forceinline__ void ldsm_x4(uint32_t* r, uint32_t addr) {
    asm volatile("ldmatrix.sync.aligned.m8n8.x4.shared.b16 {%0,%1,%2,%3}, [%4];"
                 : "=r"(r[0]), "=r"(r[1]), "=r"(r[2]), "=r"(r[3]) : "r"(addr));
}
__device__ __forceinline__ void ldsm_x4t(uint32_t* r, uint32_t addr) {
    asm volatile("ldmatrix.sync.aligned.m8n8.x4.trans.shared.b16 {%0,%1,%2,%3}, [%4];"
                 : "=r"(r[0]), "=r"(r[1]), "=r"(r[2]), "=r"(r[3]) : "r"(addr));
}
__device__ __forceinline__ void mma_bf16(float* d, const uint32_t* a, uint32_t b0, uint32_t b1) {
    asm volatile(
        "mma.sync.aligned.m16n8k16.row.col.f32.bf16.bf16.f32 "
        "{%0,%1,%2,%3}, {%4,%5,%6,%7}, {%8,%9}, {%0,%1,%2,%3};"
        : "+f"(d[0]), "+f"(d[1]), "+f"(d[2]), "+f"(d[3])
        : "r"(a[0]), "r"(a[1]), "r"(a[2]), "r"(a[3]), "r"(b0), "r"(b1));
}
__device__ __forceinline__ void mma_f16(float* d, const uint32_t* a, uint32_t b0, uint32_t b1) {
    asm volatile(
        "mma.sync.aligned.m16n8k16.row.col.f32.f16.f16.f32 "
        "{%0,%1,%2,%3}, {%4,%5,%6,%7}, {%8,%9}, {%0,%1,%2,%3};"
        : "+f"(d[0]), "+f"(d[1]), "+f"(d[2]), "+f"(d[3])
        : "r"(a[0]), "r"(a[1]), "r"(a[2]), "r"(a[3]), "r"(b0), "r"(b1));
}
__device__ __forceinline__ void cp16(uint32_t dst, const void* src) {
    asm volatile("cp.async.cg.shared.global [%0], [%1], 16;" :: "r"(dst), "l"(src));
}
__device__ __forceinline__ void cp_commit() { asm volatile("cp.async.commit_group;" ::: "memory"); }
template <int N> __device__ __forceinline__ void cp_wait() {
    asm volatile("cp.async.wait_group %0;" :: "n"(N) : "memory");
}
__device__ __forceinline__ uint32_t cvt2h(float lo, float hi) {
    uint32_t r; asm("cvt.rn.f16x2.f32 %0, %1, %2;" : "=r"(r) : "f"(hi), "f"(lo)); return r;
}
__device__ __forceinline__ float poly(float s) {
    return fmaf(s, fmaf(s, 0.03125f, 0.25f), 1.0f);
}

// ---------------------------------------------------------------------------
// Split fp32 -> bf16 hi/lo
// ---------------------------------------------------------------------------
__global__ void __launch_bounds__(256) convert_split(
    const float* __restrict__ x, __nv_bfloat16* __restrict__ xh,
    __nv_bfloat16* __restrict__ xl)
{
    int i = (blockIdx.x * 256 + threadIdx.x) * 4;
    float4 v = *(const float4*)&x[i];
    __nv_bfloat16 h0 = __float2bfloat16(v.x);
    __nv_bfloat16 h1 = __float2bfloat16(v.y);
    __nv_bfloat16 h2 = __float2bfloat16(v.z);
    __nv_bfloat16 h3 = __float2bfloat16(v.w);
    __nv_bfloat16 l0 = __float2bfloat16(v.x - __bfloat162float(h0));
    __nv_bfloat16 l1 = __float2bfloat16(v.y - __bfloat162float(h1));
    __nv_bfloat16 l2 = __float2bfloat16(v.z - __bfloat162float(h2));
    __nv_bfloat16 l3 = __float2bfloat16(v.w - __bfloat162float(h3));
    ((__nv_bfloat162*)(xh + i))[0] = __nv_bfloat162(h0, h1);
    ((__nv_bfloat162*)(xh + i))[1] = __nv_bfloat162(h2, h3);
    ((__nv_bfloat162*)(xl + i))[0] = __nv_bfloat162(l0, l1);
    ((__nv_bfloat162*)(xl + i))[1] = __nv_bfloat162(l2, l3);
}

// Split fp32 -> fp16 hi/lo (for Wo; residual may be subnormal — HMMA handles it)
__global__ void __launch_bounds__(256) convert_split_h(
    const float* __restrict__ x, __half* __restrict__ xh, __half* __restrict__ xl)
{
    int i = (blockIdx.x * 256 + threadIdx.x) * 4;
    float4 v = *(const float4*)&x[i];
    __half h0 = __float2half_rn(v.x), h1 = __float2half_rn(v.y);
    __half h2 = __float2half_rn(v.z), h3 = __float2half_rn(v.w);
    __half l0 = __float2half_rn(v.x - __half2float(h0));
    __half l1 = __float2half_rn(v.y - __half2float(h1));
    __half l2 = __float2half_rn(v.z - __half2float(h2));
    __half l3 = __float2half_rn(v.w - __half2float(h3));
    ((__half2*)(xh + i))[0] = __half2(h0, h1);
    ((__half2*)(xh + i))[1] = __half2(h2, h3);
    ((__half2*)(xl + i))[0] = __half2(l0, l1);
    ((__half2*)(xl + i))[1] = __half2(l2, l3);
}

// ---------------------------------------------------------------------------
// Merged projection GEMM (split-bf16 3-pass): [QK|V] = X @ [Wq|Wk|Wv]^T
// CTA tile 128x64, warp 32x32, BK=64, 2-stage. cols<384 -> QKf; else Vf (fp16).
// ---------------------------------------------------------------------------
#define STG2 49152
#define OFF_AH 0
#define OFF_AL 16384
#define OFF_BH 32768
#define OFF_BL 40960

__global__ void __launch_bounds__(256, 2) mma_proj(
    const __nv_bfloat16* __restrict__ Xh, const __nv_bfloat16* __restrict__ Xl,
    const __nv_bfloat16* __restrict__ Wh, const __nv_bfloat16* __restrict__ Wl,
    __half* __restrict__ QKf, __half* __restrict__ Vf)
{
    extern __shared__ char smem[];
    const uint32_t sb = smem_u32(smem);
    const int tid = threadIdx.x;
    const int wid = tid >> 5;
    const int lane = tid & 31;
    const int warpRow = wid >> 1;
    const int warpCol = wid & 1;
    const int m0 = blockIdx.y * 128;
    const int n0 = blockIdx.x * 64;

    const int lrow8 = ((lane >> 3) & 1) * 8 + (lane & 7);
    const int klane = ((lane >> 4) & 1) * 16;
    const int a_row = warpRow * 32 + lrow8;
    const int b_row = warpCol * 32 + lrow8;

    float acc[2][4][4];
#pragma unroll
    for (int mt = 0; mt < 2; mt++)
#pragma unroll
        for (int nt = 0; nt < 4; nt++)
#pragma unroll
            for (int j = 0; j < 4; j++) acc[mt][nt][j] = 0.f;

    const int NCH = DM / 64;
    {
        uint32_t s0 = sb;
#pragma unroll
        for (int t = 0; t < 4; t++) {
            int u = tid + t * 256;
            int r = u >> 3, cb = (u & 7) * 16;
            uint32_t sw = sw128((uint32_t)(r * 128 + cb));
            size_t xo = (size_t)(m0 + r) * DM + (cb >> 1);
            cp16(s0 + OFF_AH + sw, Xh + xo);
            cp16(s0 + OFF_AL + sw, Xl + xo);
        }
#pragma unroll
        for (int t = 0; t < 2; t++) {
            int u = tid + t * 256;
            int r = u >> 3, cb = (u & 7) * 16;
            uint32_t sw = sw128((uint32_t)(r * 128 + cb));
            size_t wo = (size_t)(n0 + r) * DM + (cb >> 1);
            cp16(s0 + OFF_BH + sw, Wh + wo);
            cp16(s0 + OFF_BL + sw, Wl + wo);
        }
        cp_commit();
    }

    for (int c = 0; c < NCH; c++) {
        if (c + 1 < NCH) {
            uint32_t s1 = sb + ((c + 1) & 1) * STG2;
            int k0 = (c + 1) * 64;
#pragma unroll
            for (int t = 0; t < 4; t++) {
                int u = tid + t * 256;
                int r = u >> 3, cb = (u & 7) * 16;
                uint32_t sw = sw128((uint32_t)(r * 128 + cb));
                size_t xo = (size_t)(m0 + r) * DM + k0 + (cb >> 1);
                cp16(s1 + OFF_AH + sw, Xh + xo);
                cp16(s1 + OFF_AL + sw, Xl + xo);
            }
#pragma unroll
            for (int t = 0; t < 2; t++) {
                int u = tid + t * 256;
                int r = u >> 3, cb = (u & 7) * 16;
                uint32_t sw = sw128((uint32_t)(r * 128 + cb));
                size_t wo = (size_t)(n0 + r) * DM + k0 + (cb >> 1);
                cp16(s1 + OFF_BH + sw, Wh + wo);
                cp16(s1 + OFF_BL + sw, Wl + wo);
            }
            cp_commit();
            cp_wait<1>();
        } else {
            cp_wait<0>();
        }
        __syncthreads();

        const uint32_t sc = sb + (c & 1) * STG2;
#pragma unroll
        for (int kt = 0; kt < 4; kt++) {
            const uint32_t kb = kt * 32 + klane;
            uint32_t ah[2][4], al[2][4], bh[2][4], bl[2][4];
#pragma unroll
            for (int mt = 0; mt < 2; mt++) {
                uint32_t off = sw128((uint32_t)((a_row + mt * 16) * 128 + kb));
                ldsm_x4(ah[mt], sc + OFF_AH + off);
                ldsm_x4(al[mt], sc + OFF_AL + off);
            }
#pragma unroll
            for (int nt2 = 0; nt2 < 2; nt2++) {
                uint32_t off = sw128((uint32_t)((b_row + nt2 * 16) * 128 + kb));
                ldsm_x4(bh[nt2], sc + OFF_BH + off);
                ldsm_x4(bl[nt2], sc + OFF_BL + off);
            }
#pragma unroll
            for (int mt = 0; mt < 2; mt++)
#pragma unroll
                for (int nt = 0; nt < 4; nt++) {
                    int p = nt >> 1, j = nt & 1;
                    mma_bf16(acc[mt][nt], ah[mt], bh[p][j], bh[p][2 + j]);
                    mma_bf16(acc[mt][nt], ah[mt], bl[p][j], bl[p][2 + j]);
                    mma_bf16(acc[mt][nt], al[mt], bh[p][j], bh[p][2 + j]);
                }
        }
        __syncthreads();
    }

    const int g = lane >> 2;
    const int tc = (lane & 3) * 2;
#pragma unroll
    for (int mt = 0; mt < 2; mt++) {
        int row = m0 + warpRow * 32 + mt * 16 + g;
#pragma unroll
        for (int nt = 0; nt < 4; nt++) {
            int col = n0 + warpCol * 32 + nt * 8 + tc;
            float v0 = acc[mt][nt][0], v1 = acc[mt][nt][1];
            float v2 = acc[mt][nt][2], v3 = acc[mt][nt][3];
            if (n0 < QKS) {
                *(uint32_t*)&QKf[(size_t)row * QKS + col] = cvt2h(v0, v1);
                *(uint32_t*)&QKf[(size_t)(row + 8) * QKS + col] = cvt2h(v2, v3);
            } else {
                int c2 = col - QKS;
                *(uint32_t*)&Vf[(size_t)row * DM + c2] = cvt2h(v0, v1);
                *(uint32_t*)&Vf[(size_t)(row + 8) * DM + c2] = cvt2h(v2, v3);
            }
        }
    }
}

// ---------------------------------------------------------------------------
// Output projection: out[fp32] = Yf[fp16] @ (Woh + Wol)[fp16 split]^T, 2-pass.
// CTA 128x64, warp 32x32, BK=64, 2-stage.
// ---------------------------------------------------------------------------
#define OSTG 32768
#define O_A 0
#define O_BH 16384
#define O_BL 24576

__global__ void __launch_bounds__(256, 2) mma_outproj(
    const __half* __restrict__ Yf, const __half* __restrict__ Woh,
    const __half* __restrict__ Wol, float* __restrict__ C)
{
    extern __shared__ char smem[];
    const uint32_t sb = smem_u32(smem);
    const int tid = threadIdx.x;
    const int wid = tid >> 5;
    const int lane = tid & 31;
    const int warpRow = wid >> 1;
    const int warpCol = wid & 1;
    const int m0 = blockIdx.y * 128;
    const int n0 = blockIdx.x * 64;

    const int lrow8 = ((lane >> 3) & 1) * 8 + (lane & 7);
    const int klane = ((lane >> 4) & 1) * 16;
    const int a_row = warpRow * 32 + lrow8;
    const int b_row = warpCol * 32 + lrow8;

    float acc[2][4][4];
#pragma unroll
    for (int mt = 0; mt < 2; mt++)
#pragma unroll
        for (int nt = 0; nt < 4; nt++)
#pragma unroll
            for (int j = 0; j < 4; j++) acc[mt][nt][j] = 0.f;

    const int NCH = DM / 64;
    {
#pragma unroll
        for (int t = 0; t < 4; t++) {
            int u = tid + t * 256;
            int r = u >> 3, cb = (u & 7) * 16;
            cp16(sb + O_A + sw128((uint32_t)(r * 128 + cb)),
                 Yf + (size_t)(m0 + r) * DM + (cb >> 1));
        }
#pragma unroll
        for (int t = 0; t < 2; t++) {
            int u = tid + t * 256;
            int r = u >> 3, cb = (u & 7) * 16;
            uint32_t sw = sw128((uint32_t)(r * 128 + cb));
            size_t wo = (size_t)(n0 + r) * DM + (cb >> 1);
            cp16(sb + O_BH + sw, Woh + wo);
            cp16(sb + O_BL + sw, Wol + wo);
        }
        cp_commit();
    }

    for (int c = 0; c < NCH; c++) {
        if (c + 1 < NCH) {
            uint32_t s1 = sb + ((c + 1) & 1) * OSTG;
            int k0 = (c + 1) * 64;
#pragma unroll
            for (int t = 0; t < 4; t++) {
                int u = tid + t * 256;
                int r = u >> 3, cb = (u & 7) * 16;
                cp16(s1 + O_A + sw128((uint32_t)(r * 128 + cb)),
                     Yf + (size_t)(m0 + r) * DM + k0 + (cb >> 1));
            }
#pragma unroll
            for (int t = 0; t < 2; t++) {
                int u = tid + t * 256;
                int r = u >> 3, cb = (u & 7) * 16;
                uint32_t sw = sw128((uint32_t)(r * 128 + cb));
                size_t wo = (size_t)(n0 + r) * DM + k0 + (cb >> 1);
                cp16(s1 + O_BH + sw, Woh + wo);
                cp16(s1 + O_BL + sw, Wol + wo);
            }
            cp_commit();
            cp_wait<1>();
        } else {
            cp_wait<0>();
        }
        __syncthreads();

        const uint32_t sc = sb + (c & 1) * OSTG;
#pragma unroll
        for (int kt = 0; kt < 4; kt++) {
            const uint32_t kb = kt * 32 + klane;
            uint32_t a[2][4], bh[2][4], bl[2][4];
#pragma unroll
            for (int mt = 0; mt < 2; mt++)
                ldsm_x4(a[mt], sc + O_A + sw128((uint32_t)((a_row + mt * 16) * 128 + kb)));
#pragma unroll
            for (int nt2 = 0; nt2 < 2; nt2++) {
                uint32_t off = sw128((uint32_t)((b_row + nt2 * 16) * 128 + kb));
                ldsm_x4(bh[nt2], sc + O_BH + off);
                ldsm_x4(bl[nt2], sc + O_BL + off);
            }
#pragma unroll
            for (int mt = 0; mt < 2; mt++)
#pragma unroll
                for (int nt = 0; nt < 4; nt++) {
                    int p = nt >> 1, j = nt & 1;
                    mma_f16(acc[mt][nt], a[mt], bh[p][j], bh[p][2 + j]);
                    mma_f16(acc[mt][nt], a[mt], bl[p][j], bl[p][2 + j]);
                }
        }
        __syncthreads();
    }

    const int g = lane >> 2;
    const int tc = (lane & 3) * 2;
#pragma unroll
    for (int mt = 0; mt < 2; mt++) {
        int row = m0 + warpRow * 32 + mt * 16 + g;
#pragma unroll
        for (int nt = 0; nt < 4; nt++) {
            int col = n0 + warpCol * 32 + nt * 8 + tc;
            *(float2*)&C[(size_t)row * DM + col] =
                make_float2(acc[mt][nt][0], acc[mt][nt][1]);
            *(float2*)&C[(size_t)(row + 8) * DM + col] =
                make_float2(acc[mt][nt][2], acc[mt][nt][3]);
        }
    }
}

// ---------------------------------------------------------------------------
// HMMA attention: S fp16 1-pass; A fp16; AV fp16 1-pass (V single fp16);
// z fp32 exact; Y out single fp16.
// ---------------------------------------------------------------------------
#define AQ_OFF 0                       // 128 rows * 48B = 6144
#define AK_OFF 6144                    // + st*3072
#define AV_OFF 12288                   // + st*8192
#define ASM_TOTAL 28672

__device__ __forceinline__ void attn_load_tile(
    uint32_t sb, int st, int m0, int tid,
    const __half* QKf, const __half* Vf, size_t rowbase, int h)
{
    if (tid < 128) {
        int r = tid >> 1, half = tid & 1;
        const __half* src = QKf + (rowbase + m0 + r) * QKS + 192 + h * FEATD + half * 8;
        cp16(sb + AK_OFF + st * 3072 + r * 48 + half * 16, src);
    }
#pragma unroll
    for (int i = 0; i < 2; i++) {
        int u = tid + i * 256;
        int r = u >> 3, ch = (u & 7) * 16;
        const __half* src = Vf + (rowbase + m0 + r) * DM + h * HD + (ch >> 1);
        cp16(sb + AV_OFF + st * 8192 + sw128((uint32_t)(r * 128 + ch)), src);
    }
}

__global__ void __launch_bounds__(256, 2) attn_mma(
    const __half* __restrict__ QKf, const __half* __restrict__ Vf,
    __half* __restrict__ Yf)
{
    extern __shared__ char smem[];
    const uint32_t sb = smem_u32(smem);
    const int tid = threadIdx.x;
    const int wid = tid >> 5;
    const int lane = tid & 31;
    const int qb0 = blockIdx.x * 128;
    const int h = blockIdx.y;
    const int b = blockIdx.z;
    const size_t rowbase = (size_t)b * LSEQ;

    // group 0: Q
    {
        int r = tid >> 1, half = tid & 1;
        cp16(sb + AQ_OFF + r * 48 + half * 16,
             QKf + (rowbase + qb0 + r) * QKS + h * FEATD + half * 8);
    }
    cp_commit();
    attn_load_tile(sb, 0, 0, tid, QKf, Vf, rowbase, h);
    cp_commit();
    cp_wait<1>();
    __syncthreads();

    uint32_t qf[4];
    {
        uint32_t off = (uint32_t)((wid * 16 + ((lane >> 3) & 1) * 8 + (lane & 7)) * 48
                                  + ((lane >> 4) & 1) * 16);
        ldsm_x4(qf, sb + AQ_OFF + off);
    }

    float accY[8][4];
#pragma unroll
    for (int nt = 0; nt < 8; nt++)
#pragma unroll
        for (int j = 0; j < 4; j++) accY[nt][j] = 0.f;
    float z0 = 0.f, z1 = 0.f;
    const int qrow0 = qb0 + wid * 16 + (lane >> 2);

    const int NT = LSEQ / AKT;
    for (int c = 0; c < NT; c++) {
        const int m0 = c * AKT;
        if (c + 1 < NT) {
            attn_load_tile(sb, (c + 1) & 1, m0 + AKT, tid, QKf, Vf, rowbase, h);
            cp_commit();
            cp_wait<1>();
        } else {
            cp_wait<0>();
        }
        __syncthreads();

        const uint32_t kb = sb + AK_OFF + (c & 1) * 3072;
        const uint32_t vb = sb + AV_OFF + (c & 1) * 8192;
        const int relq0 = qrow0 - m0;

#pragma unroll
        for (int s = 0; s < 4; s++) {
            uint32_t koff = (uint32_t)((16 * s + ((lane >> 4) & 1) * 8 + (lane & 7)) * 48
                                       + ((lane >> 3) & 1) * 16);
            uint32_t bf[4];
            ldsm_x4(bf, kb + koff);
            float s0[4] = {0.f, 0.f, 0.f, 0.f};
            float s1[4] = {0.f, 0.f, 0.f, 0.f};
            mma_f16(s0, qf, bf[0], bf[1]);
            mma_f16(s1, qf, bf[2], bf[3]);

            uint32_t af[4];
            {
                const int key0 = 16 * s + (lane & 3) * 2;
                const int key8 = key0 + 8;
                float a0 = poly(s0[0]); if (key0     <= relq0)     a0 += a0;
                float a1 = poly(s0[1]); if (key0 + 1 <= relq0)     a1 += a1;
                float a2 = poly(s0[2]); if (key0     <= relq0 + 8) a2 += a2;
                float a3 = poly(s0[3]); if (key0 + 1 <= relq0 + 8) a3 += a3;
                float b0 = poly(s1[0]); if (key8     <= relq0)     b0 += b0;
                float b1 = poly(s1[1]); if (key8 + 1 <= relq0)     b1 += b1;
                float b2 = poly(s1[2]); if (key8     <= relq0 + 8) b2 += b2;
                float b3 = poly(s1[3]); if (key8 + 1 <= relq0 + 8) b3 += b3;
                z0 += (a0 + a1) + (b0 + b1);
                z1 += (a2 + a3) + (b2 + b3);
                af[0] = cvt2h(a0, a1);
                af[1] = cvt2h(a2, a3);
                af[2] = cvt2h(b0, b1);
                af[3] = cvt2h(b2, b3);
            }

#pragma unroll
            for (int g4 = 0; g4 < 4; g4++) {
                uint32_t voff = sw128((uint32_t)((16 * s + ((lane >> 3) & 1) * 8 + (lane & 7)) * 128
                                                 + 32 * g4 + ((lane >> 4) & 1) * 16));
                uint32_t vf[4];
                ldsm_x4t(vf, vb + voff);
                mma_f16(accY[2 * g4],     af, vf[0], vf[1]);
                mma_f16(accY[2 * g4 + 1], af, vf[2], vf[3]);
            }
        }
        __syncthreads();
    }

    z0 += __shfl_xor_sync(0xFFFFFFFFu, z0, 1);
    z0 += __shfl_xor_sync(0xFFFFFFFFu, z0, 2);
    z1 += __shfl_xor_sync(0xFFFFFFFFu, z1, 1);
    z1 += __shfl_xor_sync(0xFFFFFFFFu, z1, 2);
    const float inv0 = 1.f / z0, inv1 = 1.f / z1;

    const size_t r0g = rowbase + qb0 + wid * 16 + (lane >> 2);
    const int colb = h * HD + (lane & 3) * 2;
#pragma unroll
    for (int nt = 0; nt < 8; nt++) {
        size_t o0 = r0g * DM + colb + nt * 8;
        size_t o1 = (r0g + 8) * DM + colb + nt * 8;
        *(uint32_t*)&Yf[o0] = cvt2h(accY[nt][0] * inv0, accY[nt][1] * inv0);
        *(uint32_t*)&Yf[o1] = cvt2h(accY[nt][2] * inv1, accY[nt][3] * inv1);
    }
}

// ---------------------------------------------------------------------------
extern "C" void kernel_launch(void* const* d_in, const int* in_sizes, int n_in,
                              void* d_out, int out_size)
{
    const float* hs = (const float*)d_in[0];
    const float* Wq = (const float*)d_in[1];
    const float* Wk = (const float*)d_in[2];
    const float* Wv = (const float*)d_in[3];
    const float* Wo = (const float*)d_in[4];
    float* out = (float*)d_out;

    __nv_bfloat16 *Xh, *Xl, *Wh, *Wl;
    __half *QKf, *Vf, *Yf, *Woh, *Wol;
    cudaGetSymbolAddress((void**)&Xh, g_Xh);
    cudaGetSymbolAddress((void**)&Xl, g_Xl);
    cudaGetSymbolAddress((void**)&Wh, g_Wh);
    cudaGetSymbolAddress((void**)&Wl, g_Wl);
    cudaGetSymbolAddress((void**)&QKf, g_QKf);
    cudaGetSymbolAddress((void**)&Vf, g_Vf);
    cudaGetSymbolAddress((void**)&Yf, g_Yf);
    cudaGetSymbolAddress((void**)&Woh, g_Woh);
    cudaGetSymbolAddress((void**)&Wol, g_Wol);

    cudaFuncSetAttribute(mma_proj, cudaFuncAttributeMaxDynamicSharedMemorySize, 2 * STG2);
    cudaFuncSetAttribute(mma_outproj, cudaFuncAttributeMaxDynamicSharedMemorySize, 2 * OSTG);
    cudaFuncSetAttribute(attn_mma, cudaFuncAttributeMaxDynamicSharedMemorySize, ASM_TOTAL);

    // Split inputs
    convert_split<<<(ROWS * DM) / 1024, 256>>>(hs, Xh, Xl);
    convert_split<<<(192 * DM) / 1024, 256>>>(Wq, Wh, Wl);
    convert_split<<<(192 * DM) / 1024, 256>>>(Wk, Wh + 192 * DM, Wl + 192 * DM);
    convert_split<<<(DM * DM) / 1024, 256>>>(Wv, Wh + QKS * DM, Wl + QKS * DM);
    convert_split_h<<<(DM * DM) / 1024, 256>>>(Wo, Woh, Wol);

    // Merged projection
    {
        dim3 g(NPROJ / 64, ROWS / 128);
        mma_proj<<<g, 256, 2 * STG2>>>(Xh, Xl, Wh, Wl, QKf, Vf);
    }
    // Attention
    {
        dim3 ga(LSEQ / 128, NH, BATCH);
        attn_mma<<<ga, 256, ASM_TOTAL>>>(QKf, Vf, Yf);
    }
    // Output projection
    {
        dim3 g(DM / 64, ROWS / 128);
        mma_outproj<<<g, 256, 2 * OSTG>>>(Yf, Woh, Wol, out);
    }
}

// round 11
// speedup vs baseline: 7.8637x; 1.1097x over previous
#include <cuda_runtime.h>
#include <cuda_bf16.h>
#include <cuda_fp16.h>
#include <cstdint>

#define LSEQ 2048
#define BATCH 2
#define NH 12
#define FEATD 16
#define HD 64
#define DM 768
#define QKS 384             // combined Q|K width
#define NPROJ 1152          // merged Q|K|V projection width
#define ROWS (BATCH * LSEQ) // 4096
#define AKT 64              // attention key tile

// Scratch (no cudaMalloc allowed)
__device__ __half g_Xh[ROWS * DM];           // X split fp16 (hi)
__device__ __half g_Xl[ROWS * DM];           // X split fp16 (lo)
__device__ __half g_Wf[NPROJ * DM];          // merged proj weights single fp16
__device__ __half g_QKf[ROWS * QKS];         // Q|K single fp16
__device__ __half g_Vf[ROWS * DM];           // V single fp16
__device__ __half g_Yf[ROWS * DM];           // Y single fp16
__device__ __half g_Woh[DM * DM];            // Wo split fp16
__device__ __half g_Wol[DM * DM];

// ---- helpers ----
__device__ __forceinline__ uint32_t smem_u32(const void* p) {
    uint32_t a;
    asm("{ .reg .u64 t; cvta.to.shared.u64 t, %1; cvt.u32.u64 %0, t; }" : "=r"(a) : "l"(p));
    return a;
}
__device__ __forceinline__ uint32_t sw128(uint32_t o) { return o ^ ((o >> 3) & 0x70); }
__device__ __forceinline__ void ldsm_x4(uint32_t* r, uint32_t addr) {
    asm volatile("ldmatrix.sync.aligned.m8n8.x4.shared.b16 {%0,%1,%2,%3}, [%4];"
                 : "=r"(r[0]), "=r"(r[1]), "=r"(r[2]), "=r"(r[3]) : "r"(addr));
}
__device__ __forceinline__ void ldsm_x4t(uint32_t* r, uint32_t addr) {
    asm volatile("ldmatrix.sync.aligned.m8n8.x4.trans.shared.b16 {%0,%1,%2,%3}, [%4];"
                 : "=r"(r[0]), "=r"(r[1]), "=r"(r[2]), "=r"(r[3]) : "r"(addr));
}
__device__ __forceinline__ void mma_f16(float* d, const uint32_t* a, uint32_t b0, uint32_t b1) {
    asm volatile(
        "mma.sync.aligned.m16n8k16.row.col.f32.f16.f16.f32 "
        "{%0,%1,%2,%3}, {%4,%5,%6,%7}, {%8,%9}, {%0,%1,%2,%3};"
        : "+f"(d[0]), "+f"(d[1]), "+f"(d[2]), "+f"(d[3])
        : "r"(a[0]), "r"(a[1]), "r"(a[2]), "r"(a[3]), "r"(b0), "r"(b1));
}
__device__ __forceinline__ void cp16(uint32_t dst, const void* src) {
    asm volatile("cp.async.cg.shared.global [%0], [%1], 16;" :: "r"(dst), "l"(src));
}
__device__ __forceinline__ void cp_commit() { asm volatile("cp.async.commit_group;" ::: "memory"); }
template <int N> __device__ __forceinline__ void cp_wait() {
    asm volatile("cp.async.wait_group %0;" :: "n"(N) : "memory");
}
__device__ __forceinline__ uint32_t cvt2h(float lo, float hi) {
    uint32_t r; asm("cvt.rn.f16x2.f32 %0, %1, %2;" : "=r"(r) : "f"(hi), "f"(lo)); return r;
}
__device__ __forceinline__ float poly(float s) {
    return fmaf(s, fmaf(s, 0.03125f, 0.25f), 1.0f);
}

// ---------------------------------------------------------------------------
// Converters
// ---------------------------------------------------------------------------
// fp32 -> fp16 hi/lo split
__global__ void __launch_bounds__(256) convert_split_h(
    const float* __restrict__ x, __half* __restrict__ xh, __half* __restrict__ xl)
{
    int i = (blockIdx.x * 256 + threadIdx.x) * 4;
    float4 v = *(const float4*)&x[i];
    __half h0 = __float2half_rn(v.x), h1 = __float2half_rn(v.y);
    __half h2 = __float2half_rn(v.z), h3 = __float2half_rn(v.w);
    __half l0 = __float2half_rn(v.x - __half2float(h0));
    __half l1 = __float2half_rn(v.y - __half2float(h1));
    __half l2 = __float2half_rn(v.z - __half2float(h2));
    __half l3 = __float2half_rn(v.w - __half2float(h3));
    ((__half2*)(xh + i))[0] = __half2(h0, h1);
    ((__half2*)(xh + i))[1] = __half2(h2, h3);
    ((__half2*)(xl + i))[0] = __half2(l0, l1);
    ((__half2*)(xl + i))[1] = __half2(l2, l3);
}

// fp32 -> single fp16
__global__ void __launch_bounds__(256) convert_h(
    const float* __restrict__ x, __half* __restrict__ xf)
{
    int i = (blockIdx.x * 256 + threadIdx.x) * 4;
    float4 v = *(const float4*)&x[i];
    ((uint32_t*)(xf + i))[0] = cvt2h(v.x, v.y);
    ((uint32_t*)(xf + i))[1] = cvt2h(v.z, v.w);
}

// ---------------------------------------------------------------------------
// Merged projection GEMM (fp16 2-pass, exact X): [QK|V] = X @ Wf^T
// X fp16 hi/lo split, Wf single fp16. CTA 128x64, warp 32x32, BK=64, 2-stage.
// ---------------------------------------------------------------------------
#define PSTG 40960
#define P_AH 0
#define P_AL 16384
#define P_BF 32768

__global__ void __launch_bounds__(256, 2) mma_proj(
    const __half* __restrict__ Xh, const __half* __restrict__ Xl,
    const __half* __restrict__ Wf,
    __half* __restrict__ QKf, __half* __restrict__ Vf)
{
    extern __shared__ char smem[];
    const uint32_t sb = smem_u32(smem);
    const int tid = threadIdx.x;
    const int wid = tid >> 5;
    const int lane = tid & 31;
    const int warpRow = wid >> 1;
    const int warpCol = wid & 1;
    const int m0 = blockIdx.y * 128;
    const int n0 = blockIdx.x * 64;

    const int lrow8 = ((lane >> 3) & 1) * 8 + (lane & 7);
    const int klane = ((lane >> 4) & 1) * 16;
    const int a_row = warpRow * 32 + lrow8;
    const int b_row = warpCol * 32 + lrow8;

    float acc[2][4][4];
#pragma unroll
    for (int mt = 0; mt < 2; mt++)
#pragma unroll
        for (int nt = 0; nt < 4; nt++)
#pragma unroll
            for (int j = 0; j < 4; j++) acc[mt][nt][j] = 0.f;

    const int NCH = DM / 64;
    {
#pragma unroll
        for (int t = 0; t < 4; t++) {
            int u = tid + t * 256;
            int r = u >> 3, cb = (u & 7) * 16;
            uint32_t sw = sw128((uint32_t)(r * 128 + cb));
            size_t xo = (size_t)(m0 + r) * DM + (cb >> 1);
            cp16(sb + P_AH + sw, Xh + xo);
            cp16(sb + P_AL + sw, Xl + xo);
        }
#pragma unroll
        for (int t = 0; t < 2; t++) {
            int u = tid + t * 256;
            int r = u >> 3, cb = (u & 7) * 16;
            cp16(sb + P_BF + sw128((uint32_t)(r * 128 + cb)),
                 Wf + (size_t)(n0 + r) * DM + (cb >> 1));
        }
        cp_commit();
    }

    for (int c = 0; c < NCH; c++) {
        if (c + 1 < NCH) {
            uint32_t s1 = sb + ((c + 1) & 1) * PSTG;
            int k0 = (c + 1) * 64;
#pragma unroll
            for (int t = 0; t < 4; t++) {
                int u = tid + t * 256;
                int r = u >> 3, cb = (u & 7) * 16;
                uint32_t sw = sw128((uint32_t)(r * 128 + cb));
                size_t xo = (size_t)(m0 + r) * DM + k0 + (cb >> 1);
                cp16(s1 + P_AH + sw, Xh + xo);
                cp16(s1 + P_AL + sw, Xl + xo);
            }
#pragma unroll
            for (int t = 0; t < 2; t++) {
                int u = tid + t * 256;
                int r = u >> 3, cb = (u & 7) * 16;
                cp16(s1 + P_BF + sw128((uint32_t)(r * 128 + cb)),
                     Wf + (size_t)(n0 + r) * DM + k0 + (cb >> 1));
            }
            cp_commit();
            cp_wait<1>();
        } else {
            cp_wait<0>();
        }
        __syncthreads();

        const uint32_t sc = sb + (c & 1) * PSTG;
#pragma unroll
        for (int kt = 0; kt < 4; kt++) {
            const uint32_t kb = kt * 32 + klane;
            uint32_t ah[2][4], al[2][4], bf[2][4];
#pragma unroll
            for (int mt = 0; mt < 2; mt++) {
                uint32_t off = sw128((uint32_t)((a_row + mt * 16) * 128 + kb));
                ldsm_x4(ah[mt], sc + P_AH + off);
                ldsm_x4(al[mt], sc + P_AL + off);
            }
#pragma unroll
            for (int nt2 = 0; nt2 < 2; nt2++)
                ldsm_x4(bf[nt2], sc + P_BF + sw128((uint32_t)((b_row + nt2 * 16) * 128 + kb)));
#pragma unroll
            for (int mt = 0; mt < 2; mt++)
#pragma unroll
                for (int nt = 0; nt < 4; nt++) {
                    int p = nt >> 1, j = nt & 1;
                    mma_f16(acc[mt][nt], ah[mt], bf[p][j], bf[p][2 + j]);
                    mma_f16(acc[mt][nt], al[mt], bf[p][j], bf[p][2 + j]);
                }
        }
        __syncthreads();
    }

    const int g = lane >> 2;
    const int tc = (lane & 3) * 2;
#pragma unroll
    for (int mt = 0; mt < 2; mt++) {
        int row = m0 + warpRow * 32 + mt * 16 + g;
#pragma unroll
        for (int nt = 0; nt < 4; nt++) {
            int col = n0 + warpCol * 32 + nt * 8 + tc;
            float v0 = acc[mt][nt][0], v1 = acc[mt][nt][1];
            float v2 = acc[mt][nt][2], v3 = acc[mt][nt][3];
            if (n0 < QKS) {
                *(uint32_t*)&QKf[(size_t)row * QKS + col] = cvt2h(v0, v1);
                *(uint32_t*)&QKf[(size_t)(row + 8) * QKS + col] = cvt2h(v2, v3);
            } else {
                int c2 = col - QKS;
                *(uint32_t*)&Vf[(size_t)row * DM + c2] = cvt2h(v0, v1);
                *(uint32_t*)&Vf[(size_t)(row + 8) * DM + c2] = cvt2h(v2, v3);
            }
        }
    }
}

// ---------------------------------------------------------------------------
// Output projection: out[fp32] = Yf[fp16] @ (Woh + Wol)[fp16 split]^T, 2-pass.
// ---------------------------------------------------------------------------
#define OSTG 32768
#define O_A 0
#define O_BH 16384
#define O_BL 24576

__global__ void __launch_bounds__(256, 3) mma_outproj(
    const __half* __restrict__ Yf, const __half* __restrict__ Woh,
    const __half* __restrict__ Wol, float* __restrict__ C)
{
    extern __shared__ char smem[];
    const uint32_t sb = smem_u32(smem);
    const int tid = threadIdx.x;
    const int wid = tid >> 5;
    const int lane = tid & 31;
    const int warpRow = wid >> 1;
    const int warpCol = wid & 1;
    const int m0 = blockIdx.y * 128;
    const int n0 = blockIdx.x * 64;

    const int lrow8 = ((lane >> 3) & 1) * 8 + (lane & 7);
    const int klane = ((lane >> 4) & 1) * 16;
    const int a_row = warpRow * 32 + lrow8;
    const int b_row = warpCol * 32 + lrow8;

    float acc[2][4][4];
#pragma unroll
    for (int mt = 0; mt < 2; mt++)
#pragma unroll
        for (int nt = 0; nt < 4; nt++)
#pragma unroll
            for (int j = 0; j < 4; j++) acc[mt][nt][j] = 0.f;

    const int NCH = DM / 64;
    {
#pragma unroll
        for (int t = 0; t < 4; t++) {
            int u = tid + t * 256;
            int r = u >> 3, cb = (u & 7) * 16;
            cp16(sb + O_A + sw128((uint32_t)(r * 128 + cb)),
                 Yf + (size_t)(m0 + r) * DM + (cb >> 1));
        }
#pragma unroll
        for (int t = 0; t < 2; t++) {
            int u = tid + t * 256;
            int r = u >> 3, cb = (u & 7) * 16;
            uint32_t sw = sw128((uint32_t)(r * 128 + cb));
            size_t wo = (size_t)(n0 + r) * DM + (cb >> 1);
            cp16(sb + O_BH + sw, Woh + wo);
            cp16(sb + O_BL + sw, Wol + wo);
        }
        cp_commit();
    }

    for (int c = 0; c < NCH; c++) {
        if (c + 1 < NCH) {
            uint32_t s1 = sb + ((c + 1) & 1) * OSTG;
            int k0 = (c + 1) * 64;
#pragma unroll
            for (int t = 0; t < 4; t++) {
                int u = tid + t * 256;
                int r = u >> 3, cb = (u & 7) * 16;
                cp16(s1 + O_A + sw128((uint32_t)(r * 128 + cb)),
                     Yf + (size_t)(m0 + r) * DM + k0 + (cb >> 1));
            }
#pragma unroll
            for (int t = 0; t < 2; t++) {
                int u = tid + t * 256;
                int r = u >> 3, cb = (u & 7) * 16;
                uint32_t sw = sw128((uint32_t)(r * 128 + cb));
                size_t wo = (size_t)(n0 + r) * DM + k0 + (cb >> 1);
                cp16(s1 + O_BH + sw, Woh + wo);
                cp16(s1 + O_BL + sw, Wol + wo);
            }
            cp_commit();
            cp_wait<1>();
        } else {
            cp_wait<0>();
        }
        __syncthreads();

        const uint32_t sc = sb + (c & 1) * OSTG;
#pragma unroll
        for (int kt = 0; kt < 4; kt++) {
            const uint32_t kb = kt * 32 + klane;
            uint32_t a[2][4], bh[2][4], bl[2][4];
#pragma unroll
            for (int mt = 0; mt < 2; mt++)
                ldsm_x4(a[mt], sc + O_A + sw128((uint32_t)((a_row + mt * 16) * 128 + kb)));
#pragma unroll
            for (int nt2 = 0; nt2 < 2; nt2++) {
                uint32_t off = sw128((uint32_t)((b_row + nt2 * 16) * 128 + kb));
                ldsm_x4(bh[nt2], sc + O_BH + off);
                ldsm_x4(bl[nt2], sc + O_BL + off);
            }
#pragma unroll
            for (int mt = 0; mt < 2; mt++)
#pragma unroll
                for (int nt = 0; nt < 4; nt++) {
                    int p = nt >> 1, j = nt & 1;
                    mma_f16(acc[mt][nt], a[mt], bh[p][j], bh[p][2 + j]);
                    mma_f16(acc[mt][nt], a[mt], bl[p][j], bl[p][2 + j]);
                }
        }
        __syncthreads();
    }

    const int g = lane >> 2;
    const int tc = (lane & 3) * 2;
#pragma unroll
    for (int mt = 0; mt < 2; mt++) {
        int row = m0 + warpRow * 32 + mt * 16 + g;
#pragma unroll
        for (int nt = 0; nt < 4; nt++) {
            int col = n0 + warpCol * 32 + nt * 8 + tc;
            *(float2*)&C[(size_t)row * DM + col] =
                make_float2(acc[mt][nt][0], acc[mt][nt][1]);
            *(float2*)&C[(size_t)(row + 8) * DM + col] =
                make_float2(acc[mt][nt][2], acc[mt][nt][3]);
        }
    }
}

// ---------------------------------------------------------------------------
// HMMA attention: S fp16 1-pass; A fp16; AV fp16 1-pass; z fp32 exact.
// 3 CTAs/SM -> single wave (384 CTAs vs 444 slots).
// ---------------------------------------------------------------------------
#define AQ_OFF 0                       // 128 rows * 48B = 6144
#define AK_OFF 6144                    // + st*3072
#define AV_OFF 12288                   // + st*8192
#define ASM_TOTAL 28672

__device__ __forceinline__ void attn_load_tile(
    uint32_t sb, int st, int m0, int tid,
    const __half* QKf, const __half* Vf, size_t rowbase, int h)
{
    if (tid < 128) {
        int r = tid >> 1, half = tid & 1;
        const __half* src = QKf + (rowbase + m0 + r) * QKS + 192 + h * FEATD + half * 8;
        cp16(sb + AK_OFF + st * 3072 + r * 48 + half * 16, src);
    }
#pragma unroll
    for (int i = 0; i < 2; i++) {
        int u = tid + i * 256;
        int r = u >> 3, ch = (u & 7) * 16;
        const __half* src = Vf + (rowbase + m0 + r) * DM + h * HD + (ch >> 1);
        cp16(sb + AV_OFF + st * 8192 + sw128((uint32_t)(r * 128 + ch)), src);
    }
}

__global__ void __launch_bounds__(256, 3) attn_mma(
    const __half* __restrict__ QKf, const __half* __restrict__ Vf,
    __half* __restrict__ Yf)
{
    extern __shared__ char smem[];
    const uint32_t sb = smem_u32(smem);
    const int tid = threadIdx.x;
    const int wid = tid >> 5;
    const int lane = tid & 31;
    const int qb0 = blockIdx.x * 128;
    const int h = blockIdx.y;
    const int b = blockIdx.z;
    const size_t rowbase = (size_t)b * LSEQ;

    {
        int r = tid >> 1, half = tid & 1;
        cp16(sb + AQ_OFF + r * 48 + half * 16,
             QKf + (rowbase + qb0 + r) * QKS + h * FEATD + half * 8);
    }
    cp_commit();
    attn_load_tile(sb, 0, 0, tid, QKf, Vf, rowbase, h);
    cp_commit();
    cp_wait<1>();
    __syncthreads();

    uint32_t qf[4];
    {
        uint32_t off = (uint32_t)((wid * 16 + ((lane >> 3) & 1) * 8 + (lane & 7)) * 48
                                  + ((lane >> 4) & 1) * 16);
        ldsm_x4(qf, sb + AQ_OFF + off);
    }

    float accY[8][4];
#pragma unroll
    for (int nt = 0; nt < 8; nt++)
#pragma unroll
        for (int j = 0; j < 4; j++) accY[nt][j] = 0.f;
    float z0 = 0.f, z1 = 0.f;
    const int qrow0 = qb0 + wid * 16 + (lane >> 2);

    const int NT = LSEQ / AKT;
    for (int c = 0; c < NT; c++) {
        const int m0 = c * AKT;
        if (c + 1 < NT) {
            attn_load_tile(sb, (c + 1) & 1, m0 + AKT, tid, QKf, Vf, rowbase, h);
            cp_commit();
            cp_wait<1>();
        } else {
            cp_wait<0>();
        }
        __syncthreads();

        const uint32_t kb = sb + AK_OFF + (c & 1) * 3072;
        const uint32_t vb = sb + AV_OFF + (c & 1) * 8192;
        const int relq0 = qrow0 - m0;

#pragma unroll
        for (int s = 0; s < 4; s++) {
            uint32_t koff = (uint32_t)((16 * s + ((lane >> 4) & 1) * 8 + (lane & 7)) * 48
                                       + ((lane >> 3) & 1) * 16);
            uint32_t bf[4];
            ldsm_x4(bf, kb + koff);
            float s0[4] = {0.f, 0.f, 0.f, 0.f};
            float s1[4] = {0.f, 0.f, 0.f, 0.f};
            mma_f16(s0, qf, bf[0], bf[1]);
            mma_f16(s1, qf, bf[2], bf[3]);

            uint32_t af[4];
            {
                const int key0 = 16 * s + (lane & 3) * 2;
                const int key8 = key0 + 8;
                float a0 = poly(s0[0]); if (key0     <= relq0)     a0 += a0;
                float a1 = poly(s0[1]); if (key0 + 1 <= relq0)     a1 += a1;
                float a2 = poly(s0[2]); if (key0     <= relq0 + 8) a2 += a2;
                float a3 = poly(s0[3]); if (key0 + 1 <= relq0 + 8) a3 += a3;
                float b0 = poly(s1[0]); if (key8     <= relq0)     b0 += b0;
                float b1 = poly(s1[1]); if (key8 + 1 <= relq0)     b1 += b1;
                float b2 = poly(s1[2]); if (key8     <= relq0 + 8) b2 += b2;
                float b3 = poly(s1[3]); if (key8 + 1 <= relq0 + 8) b3 += b3;
                z0 += (a0 + a1) + (b0 + b1);
                z1 += (a2 + a3) + (b2 + b3);
                af[0] = cvt2h(a0, a1);
                af[1] = cvt2h(a2, a3);
                af[2] = cvt2h(b0, b1);
                af[3] = cvt2h(b2, b3);
            }

#pragma unroll
            for (int g4 = 0; g4 < 4; g4++) {
                uint32_t voff = sw128((uint32_t)((16 * s + ((lane >> 3) & 1) * 8 + (lane & 7)) * 128
                                                 + 32 * g4 + ((lane >> 4) & 1) * 16));
                uint32_t vf[4];
                ldsm_x4t(vf, vb + voff);
                mma_f16(accY[2 * g4],     af, vf[0], vf[1]);
                mma_f16(accY[2 * g4 + 1], af, vf[2], vf[3]);
            }
        }
        __syncthreads();
    }

    z0 += __shfl_xor_sync(0xFFFFFFFFu, z0, 1);
    z0 += __shfl_xor_sync(0xFFFFFFFFu, z0, 2);
    z1 += __shfl_xor_sync(0xFFFFFFFFu, z1, 1);
    z1 += __shfl_xor_sync(0xFFFFFFFFu, z1, 2);
    const float inv0 = 1.f / z0, inv1 = 1.f / z1;

    const size_t r0g = rowbase + qb0 + wid * 16 + (lane >> 2);
    const int colb = h * HD + (lane & 3) * 2;
#pragma unroll
    for (int nt = 0; nt < 8; nt++) {
        size_t o0 = r0g * DM + colb + nt * 8;
        size_t o1 = (r0g + 8) * DM + colb + nt * 8;
        *(uint32_t*)&Yf[o0] = cvt2h(accY[nt][0] * inv0, accY[nt][1] * inv0);
        *(uint32_t*)&Yf[o1] = cvt2h(accY[nt][2] * inv1, accY[nt][3] * inv1);
    }
}

// ---------------------------------------------------------------------------
extern "C" void kernel_launch(void* const* d_in, const int* in_sizes, int n_in,
                              void* d_out, int out_size)
{
    const float* hs = (const float*)d_in[0];
    const float* Wq = (const float*)d_in[1];
    const float* Wk = (const float*)d_in[2];
    const float* Wv = (const float*)d_in[3];
    const float* Wo = (const float*)d_in[4];
    float* out = (float*)d_out;

    __half *Xh, *Xl, *Wf, *QKf, *Vf, *Yf, *Woh, *Wol;
    cudaGetSymbolAddress((void**)&Xh, g_Xh);
    cudaGetSymbolAddress((void**)&Xl, g_Xl);
    cudaGetSymbolAddress((void**)&Wf, g_Wf);
    cudaGetSymbolAddress((void**)&QKf, g_QKf);
    cudaGetSymbolAddress((void**)&Vf, g_Vf);
    cudaGetSymbolAddress((void**)&Yf, g_Yf);
    cudaGetSymbolAddress((void**)&Woh, g_Woh);
    cudaGetSymbolAddress((void**)&Wol, g_Wol);

    cudaFuncSetAttribute(mma_proj, cudaFuncAttributeMaxDynamicSharedMemorySize, 2 * PSTG);
    cudaFuncSetAttribute(mma_outproj, cudaFuncAttributeMaxDynamicSharedMemorySize, 2 * OSTG);
    cudaFuncSetAttribute(attn_mma, cudaFuncAttributeMaxDynamicSharedMemorySize, ASM_TOTAL);

    // Converts
    convert_split_h<<<(ROWS * DM) / 1024, 256>>>(hs, Xh, Xl);
    convert_h<<<(192 * DM) / 1024, 256>>>(Wq, Wf);
    convert_h<<<(192 * DM) / 1024, 256>>>(Wk, Wf + 192 * DM);
    convert_h<<<(DM * DM) / 1024, 256>>>(Wv, Wf + QKS * DM);
    convert_split_h<<<(DM * DM) / 1024, 256>>>(Wo, Woh, Wol);

    // Merged projection
    {
        dim3 g(NPROJ / 64, ROWS / 128);
        mma_proj<<<g, 256, 2 * PSTG>>>(Xh, Xl, Wf, QKf, Vf);
    }
    // Attention
    {
        dim3 ga(LSEQ / 128, NH, BATCH);
        attn_mma<<<ga, 256, ASM_TOTAL>>>(QKf, Vf, Yf);
    }
    // Output projection
    {
        dim3 g(DM / 64, ROWS / 128);
        mma_outproj<<<g, 256, 2 * OSTG>>>(Yf, Woh, Wol, out);
    }
}

// round 12
// speedup vs baseline: 9.2574x; 1.1772x over previous
#include <cuda_runtime.h>
#include <cuda_fp16.h>
#include <cstdint>

#define LSEQ 2048
#define BATCH 2
#define NH 12
#define FEATD 16
#define HD 64
#define DM 768
#define QKS 384             // combined Q|K width
#define NPROJ 1152          // merged Q|K|V projection width
#define ROWS (BATCH * LSEQ) // 4096
#define AKT 64              // attention key tile

// Scratch (no cudaMalloc allowed)
__device__ __half g_Xf[ROWS * DM];           // X single fp16
__device__ __half g_Wf[NPROJ * DM];          // merged proj weights single fp16
__device__ __half g_QKf[ROWS * QKS];         // Q|K single fp16
__device__ __half g_Vf[ROWS * DM];           // V single fp16
__device__ __half g_Yf[ROWS * DM];           // Y single fp16
__device__ __half g_Wof[DM * DM];            // Wo single fp16

// ---- helpers ----
__device__ __forceinline__ uint32_t smem_u32(const void* p) {
    uint32_t a;
    asm("{ .reg .u64 t; cvta.to.shared.u64 t, %1; cvt.u32.u64 %0, t; }" : "=r"(a) : "l"(p));
    return a;
}
__device__ __forceinline__ uint32_t sw128(uint32_t o) { return o ^ ((o >> 3) & 0x70); }
__device__ __forceinline__ void ldsm_x4(uint32_t* r, uint32_t addr) {
    asm volatile("ldmatrix.sync.aligned.m8n8.x4.shared.b16 {%0,%1,%2,%3}, [%4];"
                 : "=r"(r[0]), "=r"(r[1]), "=r"(r[2]), "=r"(r[3]) : "r"(addr));
}
__device__ __forceinline__ void ldsm_x4t(uint32_t* r, uint32_t addr) {
    asm volatile("ldmatrix.sync.aligned.m8n8.x4.trans.shared.b16 {%0,%1,%2,%3}, [%4];"
                 : "=r"(r[0]), "=r"(r[1]), "=r"(r[2]), "=r"(r[3]) : "r"(addr));
}
__device__ __forceinline__ void mma_f16(float* d, const uint32_t* a, uint32_t b0, uint32_t b1) {
    asm volatile(
        "mma.sync.aligned.m16n8k16.row.col.f32.f16.f16.f32 "
        "{%0,%1,%2,%3}, {%4,%5,%6,%7}, {%8,%9}, {%0,%1,%2,%3};"
        : "+f"(d[0]), "+f"(d[1]), "+f"(d[2]), "+f"(d[3])
        : "r"(a[0]), "r"(a[1]), "r"(a[2]), "r"(a[3]), "r"(b0), "r"(b1));
}
__device__ __forceinline__ void cp16(uint32_t dst, const void* src) {
    asm volatile("cp.async.cg.shared.global [%0], [%1], 16;" :: "r"(dst), "l"(src));
}
__device__ __forceinline__ void cp_commit() { asm volatile("cp.async.commit_group;" ::: "memory"); }
template <int N> __device__ __forceinline__ void cp_wait() {
    asm volatile("cp.async.wait_group %0;" :: "n"(N) : "memory");
}
__device__ __forceinline__ uint32_t cvt2h(float lo, float hi) {
    uint32_t r; asm("cvt.rn.f16x2.f32 %0, %1, %2;" : "=r"(r) : "f"(hi), "f"(lo)); return r;
}
__device__ __forceinline__ float poly(float s) {
    return fmaf(s, fmaf(s, 0.03125f, 0.25f), 1.0f);
}

// ---------------------------------------------------------------------------
// fp32 -> single fp16
// ---------------------------------------------------------------------------
__global__ void __launch_bounds__(256) convert_h(
    const float* __restrict__ x, __half* __restrict__ xf)
{
    int i = (blockIdx.x * 256 + threadIdx.x) * 4;
    float4 v = *(const float4*)&x[i];
    ((uint32_t*)(xf + i))[0] = cvt2h(v.x, v.y);
    ((uint32_t*)(xf + i))[1] = cvt2h(v.z, v.w);
}

// ---------------------------------------------------------------------------
// Single-pass fp16 GEMM: C[M,N] = A[M,768] @ B[N,768]^T
// CTA 128x64, 8 warps (4x2), warp 32x32, BK=64, 2-stage cp.async, occ 4.
// MODE 0: fp32 out (outproj, N=768). MODE 1: proj epilogue (N=1152).
// ---------------------------------------------------------------------------
#define GSTG 24576
#define G_A 0
#define G_B 16384

template <int MODE>
__global__ void __launch_bounds__(256, 4) mma_gemm(
    const __half* __restrict__ A, const __half* __restrict__ B,
    float* __restrict__ C, __half* __restrict__ QKf, __half* __restrict__ Vf,
    int N)
{
    extern __shared__ char smem[];
    const uint32_t sb = smem_u32(smem);
    const int tid = threadIdx.x;
    const int wid = tid >> 5;
    const int lane = tid & 31;
    const int warpRow = wid >> 1;
    const int warpCol = wid & 1;
    const int m0 = blockIdx.y * 128;
    const int n0 = blockIdx.x * 64;

    const int lrow8 = ((lane >> 3) & 1) * 8 + (lane & 7);
    const int klane = ((lane >> 4) & 1) * 16;
    const int a_row = warpRow * 32 + lrow8;
    const int b_row = warpCol * 32 + lrow8;

    float acc[2][4][4];
#pragma unroll
    for (int mt = 0; mt < 2; mt++)
#pragma unroll
        for (int nt = 0; nt < 4; nt++)
#pragma unroll
            for (int j = 0; j < 4; j++) acc[mt][nt][j] = 0.f;

    const int NCH = DM / 64;
    {
#pragma unroll
        for (int t = 0; t < 4; t++) {
            int u = tid + t * 256;
            int r = u >> 3, cb = (u & 7) * 16;
            cp16(sb + G_A + sw128((uint32_t)(r * 128 + cb)),
                 A + (size_t)(m0 + r) * DM + (cb >> 1));
        }
#pragma unroll
        for (int t = 0; t < 2; t++) {
            int u = tid + t * 256;
            int r = u >> 3, cb = (u & 7) * 16;
            cp16(sb + G_B + sw128((uint32_t)(r * 128 + cb)),
                 B + (size_t)(n0 + r) * DM + (cb >> 1));
        }
        cp_commit();
    }

    for (int c = 0; c < NCH; c++) {
        if (c + 1 < NCH) {
            uint32_t s1 = sb + ((c + 1) & 1) * GSTG;
            int k0 = (c + 1) * 64;
#pragma unroll
            for (int t = 0; t < 4; t++) {
                int u = tid + t * 256;
                int r = u >> 3, cb = (u & 7) * 16;
                cp16(s1 + G_A + sw128((uint32_t)(r * 128 + cb)),
                     A + (size_t)(m0 + r) * DM + k0 + (cb >> 1));
            }
#pragma unroll
            for (int t = 0; t < 2; t++) {
                int u = tid + t * 256;
                int r = u >> 3, cb = (u & 7) * 16;
                cp16(s1 + G_B + sw128((uint32_t)(r * 128 + cb)),
                     B + (size_t)(n0 + r) * DM + k0 + (cb >> 1));
            }
            cp_commit();
            cp_wait<1>();
        } else {
            cp_wait<0>();
        }
        __syncthreads();

        const uint32_t sc = sb + (c & 1) * GSTG;
#pragma unroll
        for (int kt = 0; kt < 4; kt++) {
            const uint32_t kb = kt * 32 + klane;
            uint32_t a[2][4], b[2][4];
#pragma unroll
            for (int mt = 0; mt < 2; mt++)
                ldsm_x4(a[mt], sc + G_A + sw128((uint32_t)((a_row + mt * 16) * 128 + kb)));
#pragma unroll
            for (int nt2 = 0; nt2 < 2; nt2++)
                ldsm_x4(b[nt2], sc + G_B + sw128((uint32_t)((b_row + nt2 * 16) * 128 + kb)));
#pragma unroll
            for (int mt = 0; mt < 2; mt++)
#pragma unroll
                for (int nt = 0; nt < 4; nt++) {
                    int p = nt >> 1, j = nt & 1;
                    mma_f16(acc[mt][nt], a[mt], b[p][j], b[p][2 + j]);
                }
        }
        __syncthreads();
    }

    const int g = lane >> 2;
    const int tc = (lane & 3) * 2;
#pragma unroll
    for (int mt = 0; mt < 2; mt++) {
        int row = m0 + warpRow * 32 + mt * 16 + g;
#pragma unroll
        for (int nt = 0; nt < 4; nt++) {
            int col = n0 + warpCol * 32 + nt * 8 + tc;
            float v0 = acc[mt][nt][0], v1 = acc[mt][nt][1];
            float v2 = acc[mt][nt][2], v3 = acc[mt][nt][3];
            if (MODE == 0) {
                *(float2*)&C[(size_t)row * DM + col] = make_float2(v0, v1);
                *(float2*)&C[(size_t)(row + 8) * DM + col] = make_float2(v2, v3);
            } else {
                if (n0 < QKS) {
                    *(uint32_t*)&QKf[(size_t)row * QKS + col] = cvt2h(v0, v1);
                    *(uint32_t*)&QKf[(size_t)(row + 8) * QKS + col] = cvt2h(v2, v3);
                } else {
                    int c2 = col - QKS;
                    *(uint32_t*)&Vf[(size_t)row * DM + c2] = cvt2h(v0, v1);
                    *(uint32_t*)&Vf[(size_t)(row + 8) * DM + c2] = cvt2h(v2, v3);
                }
            }
        }
    }
}

// ---------------------------------------------------------------------------
// HMMA attention: S fp16 1-pass; A fp16; AV fp16 1-pass; z fp32 exact.
// 3 CTAs/SM -> single wave (384 CTAs vs 444 slots).
// ---------------------------------------------------------------------------
#define AQ_OFF 0                       // 128 rows * 48B = 6144
#define AK_OFF 6144                    // + st*3072
#define AV_OFF 12288                   // + st*8192
#define ASM_TOTAL 28672

__device__ __forceinline__ void attn_load_tile(
    uint32_t sb, int st, int m0, int tid,
    const __half* QKf, const __half* Vf, size_t rowbase, int h)
{
    if (tid < 128) {
        int r = tid >> 1, half = tid & 1;
        const __half* src = QKf + (rowbase + m0 + r) * QKS + 192 + h * FEATD + half * 8;
        cp16(sb + AK_OFF + st * 3072 + r * 48 + half * 16, src);
    }
#pragma unroll
    for (int i = 0; i < 2; i++) {
        int u = tid + i * 256;
        int r = u >> 3, ch = (u & 7) * 16;
        const __half* src = Vf + (rowbase + m0 + r) * DM + h * HD + (ch >> 1);
        cp16(sb + AV_OFF + st * 8192 + sw128((uint32_t)(r * 128 + ch)), src);
    }
}

__global__ void __launch_bounds__(256, 3) attn_mma(
    const __half* __restrict__ QKf, const __half* __restrict__ Vf,
    __half* __restrict__ Yf)
{
    extern __shared__ char smem[];
    const uint32_t sb = smem_u32(smem);
    const int tid = threadIdx.x;
    const int wid = tid >> 5;
    const int lane = tid & 31;
    const int qb0 = blockIdx.x * 128;
    const int h = blockIdx.y;
    const int b = blockIdx.z;
    const size_t rowbase = (size_t)b * LSEQ;

    {
        int r = tid >> 1, half = tid & 1;
        cp16(sb + AQ_OFF + r * 48 + half * 16,
             QKf + (rowbase + qb0 + r) * QKS + h * FEATD + half * 8);
    }
    cp_commit();
    attn_load_tile(sb, 0, 0, tid, QKf, Vf, rowbase, h);
    cp_commit();
    cp_wait<1>();
    __syncthreads();

    uint32_t qf[4];
    {
        uint32_t off = (uint32_t)((wid * 16 + ((lane >> 3) & 1) * 8 + (lane & 7)) * 48
                                  + ((lane >> 4) & 1) * 16);
        ldsm_x4(qf, sb + AQ_OFF + off);
    }

    float accY[8][4];
#pragma unroll
    for (int nt = 0; nt < 8; nt++)
#pragma unroll
        for (int j = 0; j < 4; j++) accY[nt][j] = 0.f;
    float z0 = 0.f, z1 = 0.f;
    const int qrow0 = qb0 + wid * 16 + (lane >> 2);

    const int NT = LSEQ / AKT;
    for (int c = 0; c < NT; c++) {
        const int m0 = c * AKT;
        if (c + 1 < NT) {
            attn_load_tile(sb, (c + 1) & 1, m0 + AKT, tid, QKf, Vf, rowbase, h);
            cp_commit();
            cp_wait<1>();
        } else {
            cp_wait<0>();
        }
        __syncthreads();

        const uint32_t kb = sb + AK_OFF + (c & 1) * 3072;
        const uint32_t vb = sb + AV_OFF + (c & 1) * 8192;
        const int relq0 = qrow0 - m0;

#pragma unroll
        for (int s = 0; s < 4; s++) {
            uint32_t koff = (uint32_t)((16 * s + ((lane >> 4) & 1) * 8 + (lane & 7)) * 48
                                       + ((lane >> 3) & 1) * 16);
            uint32_t bf[4];
            ldsm_x4(bf, kb + koff);
            float s0[4] = {0.f, 0.f, 0.f, 0.f};
            float s1[4] = {0.f, 0.f, 0.f, 0.f};
            mma_f16(s0, qf, bf[0], bf[1]);
            mma_f16(s1, qf, bf[2], bf[3]);

            uint32_t af[4];
            {
                const int key0 = 16 * s + (lane & 3) * 2;
                const int key8 = key0 + 8;
                float a0 = poly(s0[0]); if (key0     <= relq0)     a0 += a0;
                float a1 = poly(s0[1]); if (key0 + 1 <= relq0)     a1 += a1;
                float a2 = poly(s0[2]); if (key0     <= relq0 + 8) a2 += a2;
                float a3 = poly(s0[3]); if (key0 + 1 <= relq0 + 8) a3 += a3;
                float b0 = poly(s1[0]); if (key8     <= relq0)     b0 += b0;
                float b1 = poly(s1[1]); if (key8 + 1 <= relq0)     b1 += b1;
                float b2 = poly(s1[2]); if (key8     <= relq0 + 8) b2 += b2;
                float b3 = poly(s1[3]); if (key8 + 1 <= relq0 + 8) b3 += b3;
                z0 += (a0 + a1) + (b0 + b1);
                z1 += (a2 + a3) + (b2 + b3);
                af[0] = cvt2h(a0, a1);
                af[1] = cvt2h(a2, a3);
                af[2] = cvt2h(b0, b1);
                af[3] = cvt2h(b2, b3);
            }

#pragma unroll
            for (int g4 = 0; g4 < 4; g4++) {
                uint32_t voff = sw128((uint32_t)((16 * s + ((lane >> 3) & 1) * 8 + (lane & 7)) * 128
                                                 + 32 * g4 + ((lane >> 4) & 1) * 16));
                uint32_t vf[4];
                ldsm_x4t(vf, vb + voff);
                mma_f16(accY[2 * g4],     af, vf[0], vf[1]);
                mma_f16(accY[2 * g4 + 1], af, vf[2], vf[3]);
            }
        }
        __syncthreads();
    }

    z0 += __shfl_xor_sync(0xFFFFFFFFu, z0, 1);
    z0 += __shfl_xor_sync(0xFFFFFFFFu, z0, 2);
    z1 += __shfl_xor_sync(0xFFFFFFFFu, z1, 1);
    z1 += __shfl_xor_sync(0xFFFFFFFFu, z1, 2);
    const float inv0 = 1.f / z0, inv1 = 1.f / z1;

    const size_t r0g = rowbase + qb0 + wid * 16 + (lane >> 2);
    const int colb = h * HD + (lane & 3) * 2;
#pragma unroll
    for (int nt = 0; nt < 8; nt++) {
        size_t o0 = r0g * DM + colb + nt * 8;
        size_t o1 = (r0g + 8) * DM + colb + nt * 8;
        *(uint32_t*)&Yf[o0] = cvt2h(accY[nt][0] * inv0, accY[nt][1] * inv0);
        *(uint32_t*)&Yf[o1] = cvt2h(accY[nt][2] * inv1, accY[nt][3] * inv1);
    }
}

// ---------------------------------------------------------------------------
extern "C" void kernel_launch(void* const* d_in, const int* in_sizes, int n_in,
                              void* d_out, int out_size)
{
    const float* hs = (const float*)d_in[0];
    const float* Wq = (const float*)d_in[1];
    const float* Wk = (const float*)d_in[2];
    const float* Wv = (const float*)d_in[3];
    const float* Wo = (const float*)d_in[4];
    float* out = (float*)d_out;

    __half *Xf, *Wf, *QKf, *Vf, *Yf, *Wof;
    cudaGetSymbolAddress((void**)&Xf, g_Xf);
    cudaGetSymbolAddress((void**)&Wf, g_Wf);
    cudaGetSymbolAddress((void**)&QKf, g_QKf);
    cudaGetSymbolAddress((void**)&Vf, g_Vf);
    cudaGetSymbolAddress((void**)&Yf, g_Yf);
    cudaGetSymbolAddress((void**)&Wof, g_Wof);

    cudaFuncSetAttribute(mma_gemm<0>, cudaFuncAttributeMaxDynamicSharedMemorySize, 2 * GSTG);
    cudaFuncSetAttribute(mma_gemm<1>, cudaFuncAttributeMaxDynamicSharedMemorySize, 2 * GSTG);
    cudaFuncSetAttribute(attn_mma, cudaFuncAttributeMaxDynamicSharedMemorySize, ASM_TOTAL);

    // Converts (all single fp16)
    convert_h<<<(ROWS * DM) / 1024, 256>>>(hs, Xf);
    convert_h<<<(192 * DM) / 1024, 256>>>(Wq, Wf);
    convert_h<<<(192 * DM) / 1024, 256>>>(Wk, Wf + 192 * DM);
    convert_h<<<(DM * DM) / 1024, 256>>>(Wv, Wf + QKS * DM);
    convert_h<<<(DM * DM) / 1024, 256>>>(Wo, Wof);

    // Merged projection (single-pass fp16)
    {
        dim3 g(NPROJ / 64, ROWS / 128);
        mma_gemm<1><<<g, 256, 2 * GSTG>>>(Xf, Wf, nullptr, QKf, Vf, NPROJ);
    }
    // Attention
    {
        dim3 ga(LSEQ / 128, NH, BATCH);
        attn_mma<<<ga, 256, ASM_TOTAL>>>(QKf, Vf, Yf);
    }
    // Output projection (single-pass fp16)
    {
        dim3 g(DM / 64, ROWS / 128);
        mma_gemm<0><<<g, 256, 2 * GSTG>>>(Yf, Wof, out, nullptr, nullptr, DM);
    }
}

// round 13
// speedup vs baseline: 10.4706x; 1.1310x over previous
#include <cuda_runtime.h>
#include <cuda_fp16.h>
#include <cstdint>

#define LSEQ 2048
#define BATCH 2
#define NH 12
#define FEATD 16
#define HD 64
#define DM 768
#define QKS 384             // combined Q|K width
#define NPROJ 1152          // merged Q|K|V projection width
#define ROWS (BATCH * LSEQ) // 4096
#define AKT 64              // attention key tile

// Scratch (no cudaMalloc allowed)
__device__ __half g_Xf[ROWS * DM];           // X single fp16
__device__ __half g_Wf[NPROJ * DM];          // merged proj weights single fp16
__device__ __half g_QKf[ROWS * QKS];         // Q|K single fp16
__device__ __half g_Vf[ROWS * DM];           // V single fp16
__device__ __half g_Yf[ROWS * DM];           // Y single fp16
__device__ __half g_Wof[DM * DM];            // Wo single fp16

// ---- helpers ----
__device__ __forceinline__ uint32_t smem_u32(const void* p) {
    uint32_t a;
    asm("{ .reg .u64 t; cvta.to.shared.u64 t, %1; cvt.u32.u64 %0, t; }" : "=r"(a) : "l"(p));
    return a;
}
__device__ __forceinline__ uint32_t sw128(uint32_t o) { return o ^ ((o >> 3) & 0x70); }
__device__ __forceinline__ void ldsm_x4(uint32_t* r, uint32_t addr) {
    asm volatile("ldmatrix.sync.aligned.m8n8.x4.shared.b16 {%0,%1,%2,%3}, [%4];"
                 : "=r"(r[0]), "=r"(r[1]), "=r"(r[2]), "=r"(r[3]) : "r"(addr));
}
__device__ __forceinline__ void ldsm_x4t(uint32_t* r, uint32_t addr) {
    asm volatile("ldmatrix.sync.aligned.m8n8.x4.trans.shared.b16 {%0,%1,%2,%3}, [%4];"
                 : "=r"(r[0]), "=r"(r[1]), "=r"(r[2]), "=r"(r[3]) : "r"(addr));
}
__device__ __forceinline__ void mma_f16(float* d, const uint32_t* a, uint32_t b0, uint32_t b1) {
    asm volatile(
        "mma.sync.aligned.m16n8k16.row.col.f32.f16.f16.f32 "
        "{%0,%1,%2,%3}, {%4,%5,%6,%7}, {%8,%9}, {%0,%1,%2,%3};"
        : "+f"(d[0]), "+f"(d[1]), "+f"(d[2]), "+f"(d[3])
        : "r"(a[0]), "r"(a[1]), "r"(a[2]), "r"(a[3]), "r"(b0), "r"(b1));
}
__device__ __forceinline__ void cp16(uint32_t dst, const void* src) {
    asm volatile("cp.async.cg.shared.global [%0], [%1], 16;" :: "r"(dst), "l"(src));
}
__device__ __forceinline__ void cp_commit() { asm volatile("cp.async.commit_group;" ::: "memory"); }
template <int N> __device__ __forceinline__ void cp_wait() {
    asm volatile("cp.async.wait_group %0;" :: "n"(N) : "memory");
}
__device__ __forceinline__ uint32_t cvt2h(float lo, float hi) {
    uint32_t r; asm("cvt.rn.f16x2.f32 %0, %1, %2;" : "=r"(r) : "f"(hi), "f"(lo)); return r;
}
__device__ __forceinline__ float poly(float s) {      // weight-1 score
    return fmaf(s, fmaf(s, 0.03125f, 0.25f), 1.0f);
}
__device__ __forceinline__ float poly2(float s) {     // weight-2 folded in
    return fmaf(s, fmaf(s, 0.0625f, 0.5f), 2.0f);
}

// ---------------------------------------------------------------------------
// Converters
// ---------------------------------------------------------------------------
__global__ void __launch_bounds__(256) convert_h(
    const float* __restrict__ x, __half* __restrict__ xf)
{
    int i = (blockIdx.x * 256 + threadIdx.x) * 4;
    float4 v = *(const float4*)&x[i];
    ((uint32_t*)(xf + i))[0] = cvt2h(v.x, v.y);
    ((uint32_t*)(xf + i))[1] = cvt2h(v.z, v.w);
}

// All four weight matrices in one launch: Wf = [Wq|Wk|Wv], Wof = Wo
#define WQN (192 * DM)
#define WVN (DM * DM)
__global__ void __launch_bounds__(256) convert_weights(
    const float* __restrict__ Wq, const float* __restrict__ Wk,
    const float* __restrict__ Wv, const float* __restrict__ Wo,
    __half* __restrict__ Wf, __half* __restrict__ Wof)
{
    int i = (blockIdx.x * 256 + threadIdx.x) * 4;
    const float* src;
    __half* dst;
    if (i < WQN)                   { src = Wq + i;                 dst = Wf + i; }
    else if (i < 2 * WQN)          { src = Wk + (i - WQN);         dst = Wf + i; }
    else if (i < 2 * WQN + WVN)    { src = Wv + (i - 2 * WQN);     dst = Wf + i; }
    else                           { src = Wo + (i - 2 * WQN - WVN); dst = Wof + (i - 2 * WQN - WVN); }
    float4 v = *(const float4*)src;
    ((uint32_t*)dst)[0] = cvt2h(v.x, v.y);
    ((uint32_t*)dst)[1] = cvt2h(v.z, v.w);
}

// ---------------------------------------------------------------------------
// Single-pass fp16 GEMM: C[M,N] = A[M,768] @ B[N,768]^T
// CTA 128x128, 8 warps (4x2), warp 32x64, BK=64, 2-stage cp.async, occ 2.
// MODE 0: fp32 out (outproj). MODE 1: proj epilogue (QKf / Vf split by col).
// ---------------------------------------------------------------------------
#define GSTG 32768
#define G_A 0
#define G_B 16384

template <int MODE>
__global__ void __launch_bounds__(256, 2) mma_gemm(
    const __half* __restrict__ A, const __half* __restrict__ B,
    float* __restrict__ C, __half* __restrict__ QKf, __half* __restrict__ Vf)
{
    extern __shared__ char smem[];
    const uint32_t sb = smem_u32(smem);
    const int tid = threadIdx.x;
    const int wid = tid >> 5;
    const int lane = tid & 31;
    const int warpRow = wid >> 1;     // 0..3 -> m*32
    const int warpCol = wid & 1;      // 0..1 -> n*64
    const int m0 = blockIdx.y * 128;
    const int n0 = blockIdx.x * 128;

    const int lrow8 = ((lane >> 3) & 1) * 8 + (lane & 7);
    const int klane = ((lane >> 4) & 1) * 16;
    const int a_row = warpRow * 32 + lrow8;
    const int b_row = warpCol * 64 + lrow8;

    float acc[2][8][4];
#pragma unroll
    for (int mt = 0; mt < 2; mt++)
#pragma unroll
        for (int nt = 0; nt < 8; nt++)
#pragma unroll
            for (int j = 0; j < 4; j++) acc[mt][nt][j] = 0.f;

    const int NCH = DM / 64;
    {
#pragma unroll
        for (int t = 0; t < 4; t++) {
            int u = tid + t * 256;
            int r = u >> 3, cb = (u & 7) * 16;
            uint32_t sw = sw128((uint32_t)(r * 128 + cb));
            cp16(sb + G_A + sw, A + (size_t)(m0 + r) * DM + (cb >> 1));
            cp16(sb + G_B + sw, B + (size_t)(n0 + r) * DM + (cb >> 1));
        }
        cp_commit();
    }

    for (int c = 0; c < NCH; c++) {
        if (c + 1 < NCH) {
            uint32_t s1 = sb + ((c + 1) & 1) * GSTG;
            int k0 = (c + 1) * 64;
#pragma unroll
            for (int t = 0; t < 4; t++) {
                int u = tid + t * 256;
                int r = u >> 3, cb = (u & 7) * 16;
                uint32_t sw = sw128((uint32_t)(r * 128 + cb));
                cp16(s1 + G_A + sw, A + (size_t)(m0 + r) * DM + k0 + (cb >> 1));
                cp16(s1 + G_B + sw, B + (size_t)(n0 + r) * DM + k0 + (cb >> 1));
            }
            cp_commit();
            cp_wait<1>();
        } else {
            cp_wait<0>();
        }
        __syncthreads();

        const uint32_t sc = sb + (c & 1) * GSTG;
#pragma unroll
        for (int kt = 0; kt < 4; kt++) {
            const uint32_t kb = kt * 32 + klane;
            uint32_t a[2][4], b[4][4];
#pragma unroll
            for (int mt = 0; mt < 2; mt++)
                ldsm_x4(a[mt], sc + G_A + sw128((uint32_t)((a_row + mt * 16) * 128 + kb)));
#pragma unroll
            for (int nt2 = 0; nt2 < 4; nt2++)
                ldsm_x4(b[nt2], sc + G_B + sw128((uint32_t)((b_row + nt2 * 16) * 128 + kb)));
#pragma unroll
            for (int mt = 0; mt < 2; mt++)
#pragma unroll
                for (int nt = 0; nt < 8; nt++) {
                    int p = nt >> 1, j = nt & 1;
                    mma_f16(acc[mt][nt], a[mt], b[p][j], b[p][2 + j]);
                }
        }
        __syncthreads();
    }

    const int g = lane >> 2;
    const int tc = (lane & 3) * 2;
#pragma unroll
    for (int mt = 0; mt < 2; mt++) {
        int row = m0 + warpRow * 32 + mt * 16 + g;
#pragma unroll
        for (int nt = 0; nt < 8; nt++) {
            int col = n0 + warpCol * 64 + nt * 8 + tc;
            float v0 = acc[mt][nt][0], v1 = acc[mt][nt][1];
            float v2 = acc[mt][nt][2], v3 = acc[mt][nt][3];
            if (MODE == 0) {
                *(float2*)&C[(size_t)row * DM + col] = make_float2(v0, v1);
                *(float2*)&C[(size_t)(row + 8) * DM + col] = make_float2(v2, v3);
            } else {
                if (col < QKS) {
                    *(uint32_t*)&QKf[(size_t)row * QKS + col] = cvt2h(v0, v1);
                    *(uint32_t*)&QKf[(size_t)(row + 8) * QKS + col] = cvt2h(v2, v3);
                } else {
                    int c2 = col - QKS;
                    *(uint32_t*)&Vf[(size_t)row * DM + c2] = cvt2h(v0, v1);
                    *(uint32_t*)&Vf[(size_t)(row + 8) * DM + c2] = cvt2h(v2, v3);
                }
            }
        }
    }
}

// ---------------------------------------------------------------------------
// HMMA attention: S fp16 1-pass; A fp16; AV fp16 1-pass; z fp32 exact.
// Causal-mode specialization: CMODE 2 = all keys causal (weight 2, poly2),
// CMODE 1 = none causal (poly), CMODE 0 = mixed (per-element compare).
// ---------------------------------------------------------------------------
#define AQ_OFF 0                       // 128 rows * 48B = 6144
#define AK_OFF 6144                    // + st*3072
#define AV_OFF 12288                   // + st*8192
#define ASM_TOTAL 28672

__device__ __forceinline__ void attn_load_tile(
    uint32_t sb, int st, int m0, int tid,
    const __half* QKf, const __half* Vf, size_t rowbase, int h)
{
    if (tid < 128) {
        int r = tid >> 1, half = tid & 1;
        const __half* src = QKf + (rowbase + m0 + r) * QKS + 192 + h * FEATD + half * 8;
        cp16(sb + AK_OFF + st * 3072 + r * 48 + half * 16, src);
    }
#pragma unroll
    for (int i = 0; i < 2; i++) {
        int u = tid + i * 256;
        int r = u >> 3, ch = (u & 7) * 16;
        const __half* src = Vf + (rowbase + m0 + r) * DM + h * HD + (ch >> 1);
        cp16(sb + AV_OFF + st * 8192 + sw128((uint32_t)(r * 128 + ch)), src);
    }
}

template <int CMODE>
__device__ __forceinline__ void attn_tile_body(
    uint32_t kb, uint32_t vb, const uint32_t* qf,
    float accY[8][4], float& z0, float& z1, int relq0, int lane)
{
#pragma unroll
    for (int s = 0; s < 4; s++) {
        uint32_t koff = (uint32_t)((16 * s + ((lane >> 4) & 1) * 8 + (lane & 7)) * 48
                                   + ((lane >> 3) & 1) * 16);
        uint32_t bf[4];
        ldsm_x4(bf, kb + koff);
        float s0[4] = {0.f, 0.f, 0.f, 0.f};
        float s1[4] = {0.f, 0.f, 0.f, 0.f};
        mma_f16(s0, qf, bf[0], bf[1]);
        mma_f16(s1, qf, bf[2], bf[3]);

        float a0, a1, a2, a3, b0, b1, b2, b3;
        if (CMODE == 2) {
            a0 = poly2(s0[0]); a1 = poly2(s0[1]); a2 = poly2(s0[2]); a3 = poly2(s0[3]);
            b0 = poly2(s1[0]); b1 = poly2(s1[1]); b2 = poly2(s1[2]); b3 = poly2(s1[3]);
        } else if (CMODE == 1) {
            a0 = poly(s0[0]); a1 = poly(s0[1]); a2 = poly(s0[2]); a3 = poly(s0[3]);
            b0 = poly(s1[0]); b1 = poly(s1[1]); b2 = poly(s1[2]); b3 = poly(s1[3]);
        } else {
            const int key0 = 16 * s + (lane & 3) * 2;
            const int key8 = key0 + 8;
            a0 = poly(s0[0]); if (key0     <= relq0)     a0 += a0;
            a1 = poly(s0[1]); if (key0 + 1 <= relq0)     a1 += a1;
            a2 = poly(s0[2]); if (key0     <= relq0 + 8) a2 += a2;
            a3 = poly(s0[3]); if (key0 + 1 <= relq0 + 8) a3 += a3;
            b0 = poly(s1[0]); if (key8     <= relq0)     b0 += b0;
            b1 = poly(s1[1]); if (key8 + 1 <= relq0)     b1 += b1;
            b2 = poly(s1[2]); if (key8     <= relq0 + 8) b2 += b2;
            b3 = poly(s1[3]); if (key8 + 1 <= relq0 + 8) b3 += b3;
        }
        z0 += (a0 + a1) + (b0 + b1);
        z1 += (a2 + a3) + (b2 + b3);
        uint32_t af[4];
        af[0] = cvt2h(a0, a1);
        af[1] = cvt2h(a2, a3);
        af[2] = cvt2h(b0, b1);
        af[3] = cvt2h(b2, b3);

#pragma unroll
        for (int g4 = 0; g4 < 4; g4++) {
            uint32_t voff = sw128((uint32_t)((16 * s + ((lane >> 3) & 1) * 8 + (lane & 7)) * 128
                                             + 32 * g4 + ((lane >> 4) & 1) * 16));
            uint32_t vf[4];
            ldsm_x4t(vf, vb + voff);
            mma_f16(accY[2 * g4],     af, vf[0], vf[1]);
            mma_f16(accY[2 * g4 + 1], af, vf[2], vf[3]);
        }
    }
}

__global__ void __launch_bounds__(256, 3) attn_mma(
    const __half* __restrict__ QKf, const __half* __restrict__ Vf,
    __half* __restrict__ Yf)
{
    extern __shared__ char smem[];
    const uint32_t sb = smem_u32(smem);
    const int tid = threadIdx.x;
    const int wid = tid >> 5;
    const int lane = tid & 31;
    const int qb0 = blockIdx.x * 128;
    const int h = blockIdx.y;
    const int b = blockIdx.z;
    const size_t rowbase = (size_t)b * LSEQ;

    {
        int r = tid >> 1, half = tid & 1;
        cp16(sb + AQ_OFF + r * 48 + half * 16,
             QKf + (rowbase + qb0 + r) * QKS + h * FEATD + half * 8);
    }
    cp_commit();
    attn_load_tile(sb, 0, 0, tid, QKf, Vf, rowbase, h);
    cp_commit();
    cp_wait<1>();
    __syncthreads();

    uint32_t qf[4];
    {
        uint32_t off = (uint32_t)((wid * 16 + ((lane >> 3) & 1) * 8 + (lane & 7)) * 48
                                  + ((lane >> 4) & 1) * 16);
        ldsm_x4(qf, sb + AQ_OFF + off);
    }

    float accY[8][4];
#pragma unroll
    for (int nt = 0; nt < 8; nt++)
#pragma unroll
        for (int j = 0; j < 4; j++) accY[nt][j] = 0.f;
    float z0 = 0.f, z1 = 0.f;
    const int qrow0 = qb0 + wid * 16 + (lane >> 2);

    const int NT = LSEQ / AKT;
    for (int c = 0; c < NT; c++) {
        const int m0 = c * AKT;
        if (c + 1 < NT) {
            attn_load_tile(sb, (c + 1) & 1, m0 + AKT, tid, QKf, Vf, rowbase, h);
            cp_commit();
            cp_wait<1>();
        } else {
            cp_wait<0>();
        }
        __syncthreads();

        const uint32_t kb = sb + AK_OFF + (c & 1) * 3072;
        const uint32_t vb = sb + AV_OFF + (c & 1) * 8192;
        const int relq0 = qrow0 - m0;

        if (m0 + AKT <= qb0) {
            attn_tile_body<2>(kb, vb, qf, accY, z0, z1, relq0, lane);
        } else if (m0 >= qb0 + 128) {
            attn_tile_body<1>(kb, vb, qf, accY, z0, z1, relq0, lane);
        } else {
            attn_tile_body<0>(kb, vb, qf, accY, z0, z1, relq0, lane);
        }
        __syncthreads();
    }

    z0 += __shfl_xor_sync(0xFFFFFFFFu, z0, 1);
    z0 += __shfl_xor_sync(0xFFFFFFFFu, z0, 2);
    z1 += __shfl_xor_sync(0xFFFFFFFFu, z1, 1);
    z1 += __shfl_xor_sync(0xFFFFFFFFu, z1, 2);
    const float inv0 = 1.f / z0, inv1 = 1.f / z1;

    const size_t r0g = rowbase + qb0 + wid * 16 + (lane >> 2);
    const int colb = h * HD + (lane & 3) * 2;
#pragma unroll
    for (int nt = 0; nt < 8; nt++) {
        size_t o0 = r0g * DM + colb + nt * 8;
        size_t o1 = (r0g + 8) * DM + colb + nt * 8;
        *(uint32_t*)&Yf[o0] = cvt2h(accY[nt][0] * inv0, accY[nt][1] * inv0);
        *(uint32_t*)&Yf[o1] = cvt2h(accY[nt][2] * inv1, accY[nt][3] * inv1);
    }
}

// ---------------------------------------------------------------------------
extern "C" void kernel_launch(void* const* d_in, const int* in_sizes, int n_in,
                              void* d_out, int out_size)
{
    const float* hs = (const float*)d_in[0];
    const float* Wq = (const float*)d_in[1];
    const float* Wk = (const float*)d_in[2];
    const float* Wv = (const float*)d_in[3];
    const float* Wo = (const float*)d_in[4];
    float* out = (float*)d_out;

    __half *Xf, *Wf, *QKf, *Vf, *Yf, *Wof;
    cudaGetSymbolAddress((void**)&Xf, g_Xf);
    cudaGetSymbolAddress((void**)&Wf, g_Wf);
    cudaGetSymbolAddress((void**)&QKf, g_QKf);
    cudaGetSymbolAddress((void**)&Vf, g_Vf);
    cudaGetSymbolAddress((void**)&Yf, g_Yf);
    cudaGetSymbolAddress((void**)&Wof, g_Wof);

    cudaFuncSetAttribute(mma_gemm<0>, cudaFuncAttributeMaxDynamicSharedMemorySize, 2 * GSTG);
    cudaFuncSetAttribute(mma_gemm<1>, cudaFuncAttributeMaxDynamicSharedMemorySize, 2 * GSTG);
    cudaFuncSetAttribute(attn_mma, cudaFuncAttributeMaxDynamicSharedMemorySize, ASM_TOTAL);

    // Converts (2 launches)
    convert_h<<<(ROWS * DM) / 1024, 256>>>(hs, Xf);
    convert_weights<<<(NPROJ * DM + DM * DM) / 1024, 256>>>(Wq, Wk, Wv, Wo, Wf, Wof);

    // Merged projection (single-pass fp16, CTA 128x128)
    {
        dim3 g(NPROJ / 128, ROWS / 128);
        mma_gemm<1><<<g, 256, 2 * GSTG>>>(Xf, Wf, nullptr, QKf, Vf);
    }
    // Attention
    {
        dim3 ga(LSEQ / 128, NH, BATCH);
        attn_mma<<<ga, 256, ASM_TOTAL>>>(QKf, Vf, Yf);
    }
    // Output projection
    {
        dim3 g(DM / 128, ROWS / 128);
        mma_gemm<0><<<g, 256, 2 * GSTG>>>(Yf, Wof, out, nullptr, nullptr);
    }
}